// round 9
// baseline (speedup 1.0000x reference)
#include <cuda_runtime.h>
#include <cuda_fp16.h>
#include <cstdint>

#define HS 1024
#define NH 16
#define DH 64
#define B 4
#define SC 512
#define SE 2048

// -------------------- scratch (device globals; no allocation) --------------------
__device__ float g_QKVc[(size_t)3 * B * SC * HS];   // Qc | Kc | Vc
__device__ float g_QKVe[(size_t)3 * B * SE * HS];   // Qe | Ke | Ve
__device__ float g_Ac[(size_t)B * SC * HS];
__device__ float g_Ae[(size_t)B * SE * HS];
// fp16 preconverted GEMM operands
__device__ __align__(256) __half g_xch[(size_t)B * SC * HS];
__device__ __align__(256) __half g_xeh[(size_t)B * SE * HS];
__device__ __align__(256) __half g_Wch[(size_t)3 * HS * HS];   // W_cq|W_ck|W_cv
__device__ __align__(256) __half g_Weh[(size_t)3 * HS * HS];   // W_eq|W_ek|W_ev
// fp16 K (d-permuted) / V-transposed (seq-permuted) per head
__device__ __align__(256) __half g_Ke16[(size_t)B * NH * SE * DH];
__device__ __align__(256) __half g_Vte16[(size_t)B * NH * SE * DH];
__device__ __align__(256) __half g_Kc16[(size_t)B * NH * SC * DH];
__device__ __align__(256) __half g_Vtc16[(size_t)B * NH * SC * DH];

// ==================== helpers ====================
__device__ __forceinline__ void mma_f16(float* d, const uint32_t* a, const uint32_t* b) {
    asm volatile(
        "mma.sync.aligned.m16n8k16.row.col.f32.f16.f16.f32 "
        "{%0,%1,%2,%3}, {%4,%5,%6,%7}, {%8,%9}, {%0,%1,%2,%3};"
        : "+f"(d[0]), "+f"(d[1]), "+f"(d[2]), "+f"(d[3])
        : "r"(a[0]), "r"(a[1]), "r"(a[2]), "r"(a[3]), "r"(b[0]), "r"(b[1]));
}

__device__ __forceinline__ uint32_t packh2(float a, float b) {
    __half2 h = __floats2half2_rn(a, b);
    return *(uint32_t*)&h;
}

__device__ __forceinline__ uint32_t smem_u32(const void* p) {
    uint32_t a;
    asm("{ .reg .u64 t; cvta.to.shared.u64 t, %1; cvt.u32.u64 %0, t; }" : "=r"(a) : "l"(p));
    return a;
}

__device__ __forceinline__ void cp16(uint32_t dst, const void* src) {
    asm volatile("cp.async.cg.shared.global [%0], [%1], 16;" :: "r"(dst), "l"(src));
}

// hardware exp2 (MUFU.EX2)
__device__ __forceinline__ float ex2(float x) {
    float r;
    asm("ex2.approx.f32 %0, %1;" : "=f"(r) : "f"(x));
    return r;
}

// k-dim pair permutation: within each 16-element group, element c (even) moves to
// np(c) = grp*16 + ((c&7)>>1)*4 + ((c>>3)&1)*2  -> lane t reads {2t,2t+1,2t+8,2t+9}
// as one contiguous 8-byte LDS.64.
__device__ __forceinline__ int kperm(int c) {
    return (c >> 4) * 16 + (((c & 7) >> 1) << 2) + (((c >> 3) & 1) << 1);
}

#define CSC 0.1803368801111694f   // log2(e)/8
#define MASKADD (-24000.0f)

// ==================== merged convert: 6 weights + 2 activations ====================
__global__ __launch_bounds__(256) void cvt_all(
    const float* __restrict__ Wcq, const float* __restrict__ Wck,
    const float* __restrict__ Wcv, const float* __restrict__ Weq,
    const float* __restrict__ Wek, const float* __restrict__ Wev,
    const float* __restrict__ xc, const float* __restrict__ xe,
    __half* __restrict__ dWc, __half* __restrict__ dWe,
    __half* __restrict__ dxc, __half* __restrict__ dxe)
{
    int bid = blockIdx.x;
    const float* s;
    __half* d;
    int i;
    if (bid < 6144) {
        int z = bid >> 10;
        const float* Ws[6] = {Wcq, Wck, Wcv, Weq, Wek, Wev};
        s = Ws[z];
        d = (z < 3) ? (dWc + ((size_t)z << 20)) : (dWe + ((size_t)(z - 3) << 20));
        i = (bid & 1023) * 256 + threadIdx.x;
    } else if (bid < 8192) {
        s = xc; d = dxc;
        i = (bid - 6144) * 256 + threadIdx.x;
    } else {
        s = xe; d = dxe;
        i = (bid - 8192) * 256 + threadIdx.x;
    }
    float4 v = ((const float4*)s)[i];
    ((uint2*)d)[i] = make_uint2(packh2(v.x, v.y), packh2(v.z, v.w));
}

// ==================== GEMM: 128x256 CTA tile, 256 threads, 3-stage ==============
#define G_RS    80
#define G_A     0
#define G_B     (128 * G_RS)          // 10240
#define G_STAGE (384 * G_RS)          // 30720
#define G_SMEM  (3 * G_STAGE)         // 92160

__global__ __launch_bounds__(256, 1) void gemm_f16(
    const __half* __restrict__ xeh, const __half* __restrict__ Weh,
    const __half* __restrict__ xch, const __half* __restrict__ Wch,
    const float* __restrict__ beq, const float* __restrict__ bek,
    const float* __restrict__ bev,
    const float* __restrict__ bcq, const float* __restrict__ bck,
    const float* __restrict__ bcv,
    float* __restrict__ Ce, float* __restrict__ Cc)
{
    const int z = blockIdx.z;
    const __half *Ah, *Wz;
    float* C;
    const float* bias;
    if (z < 3) {
        Ah = xeh;
        Wz = Weh + ((size_t)z << 20);
        C = Ce + (size_t)z * (B * SE) * HS;
        bias = (z == 0) ? beq : ((z == 1) ? bek : bev);
    } else {
        if (blockIdx.y >= (B * SC) / 128) return;
        int zz = z - 3;
        Ah = xch;
        Wz = Wch + ((size_t)zz << 20);
        C = Cc + (size_t)zz * (B * SC) * HS;
        bias = (zz == 0) ? bcq : ((zz == 1) ? bck : bcv);
    }

    extern __shared__ char smem[];
    const uint32_t sb = smem_u32(smem);
    const int tid = threadIdx.x;
    const int wid = tid >> 5;
    const int lane = tid & 31;
    const int g = lane >> 2;
    const int t = lane & 3;
    const int wm = wid >> 2;      // 0..1 -> 64 rows each
    const int wn = wid & 3;       // 0..3 -> 64 cols each
    const int bm = blockIdx.y * 128;
    const int bn = blockIdx.x * 256;

    // cp.async: 6 chunks of 16B per thread per stage (A 512 + B 1024 chunks)
    const char* csrc[6];
    uint32_t cdst[6];
#pragma unroll
    for (int q = 0; q < 6; q++) {
        int f = q * 256 + tid;
        if (f < 512) {
            int r = f >> 2, c = f & 3;
            cdst[q] = (uint32_t)(G_A + r * G_RS + c * 16);
            csrc[q] = (const char*)(Ah + (size_t)(bm + r) * HS + c * 8);
        } else {
            int idx = f - 512;
            int r = idx >> 2, c = idx & 3;
            cdst[q] = (uint32_t)(G_B + r * G_RS + c * 16);
            csrc[q] = (const char*)(Wz + (size_t)(bn + r) * HS + c * 8);
        }
    }

    const int NC = HS / 32;

#pragma unroll
    for (int st = 0; st < 3; st++) {
        uint32_t db = sb + st * G_STAGE;
#pragma unroll
        for (int q = 0; q < 6; q++)
            cp16(db + cdst[q], csrc[q] + st * 64);
        asm volatile("cp.async.commit_group;");
    }

    float acc[4][8][4];
#pragma unroll
    for (int i = 0; i < 4; i++)
#pragma unroll
        for (int j = 0; j < 8; j++)
#pragma unroll
            for (int k = 0; k < 4; k++) acc[i][j][k] = 0.f;

    for (int c = 0; c < NC; c++) {
        asm volatile("cp.async.wait_group 2;");
        __syncthreads();

        const char* buf = smem + (c % 3) * G_STAGE;
#pragma unroll
        for (int s = 0; s < 2; s++) {
            const int kb = s * 32 + 4 * t;
            uint32_t ah[4][4];
#pragma unroll
            for (int i = 0; i < 4; i++) {
                int r = wm * 64 + 16 * i + g;
                const char* pa = buf + G_A + r * G_RS + kb;
                ah[i][0] = *(const uint32_t*)(pa);
                ah[i][1] = *(const uint32_t*)(pa + 8 * G_RS);
                ah[i][2] = *(const uint32_t*)(pa + 16);
                ah[i][3] = *(const uint32_t*)(pa + 8 * G_RS + 16);
            }
#pragma unroll
            for (int j = 0; j < 8; j++) {
                int nr = wn * 64 + 8 * j + g;
                const char* pb = buf + G_B + nr * G_RS + kb;
                uint32_t bh[2];
                bh[0] = *(const uint32_t*)(pb);
                bh[1] = *(const uint32_t*)(pb + 16);
#pragma unroll
                for (int i = 0; i < 4; i++)
                    mma_f16(acc[i][j], ah[i], bh);
            }
        }
        __syncthreads();

        if (c + 3 < NC) {
            uint32_t db = sb + ((c + 3) % 3) * G_STAGE;
            int koff = (c + 3) * 64;
#pragma unroll
            for (int q = 0; q < 6; q++)
                cp16(db + cdst[q], csrc[q] + koff);
        }
        asm volatile("cp.async.commit_group;");
    }

#pragma unroll
    for (int i = 0; i < 4; i++) {
        int row0 = bm + wm * 64 + 16 * i + g;
#pragma unroll
        for (int j = 0; j < 8; j++) {
            int col = bn + wn * 64 + 8 * j + 2 * t;
            float2 bv2 = *(const float2*)(bias + col);
            *(float2*)(C + (size_t)row0 * HS + col) =
                make_float2(acc[i][j][0] + bv2.x, acc[i][j][1] + bv2.y);
            *(float2*)(C + (size_t)(row0 + 8) * HS + col) =
                make_float2(acc[i][j][2] + bv2.x, acc[i][j][3] + bv2.y);
        }
    }
}

// ==================== K/V prep: fp32 -> fp16, k-dim permuted ====================
__global__ __launch_bounds__(256) void prep_all(
    const float* __restrict__ Kc, const float* __restrict__ Vc,
    __half* __restrict__ Kc16, __half* __restrict__ Vtc16,
    const float* __restrict__ Ke, const float* __restrict__ Ve,
    __half* __restrict__ Ke16, __half* __restrict__ Vte16)
{
    __shared__ float vs[64][65];
    const int tid = threadIdx.x;
    const int b = blockIdx.z, h = blockIdx.y;
    const int bh = b * NH + h;

    const float *K, *V;
    __half *Kh, *Vth;
    int Sk, s0;
    if (blockIdx.x < SC / 64) {
        K = Kc; V = Vc; Kh = Kc16; Vth = Vtc16; Sk = SC;
        s0 = blockIdx.x * 64;
    } else {
        K = Ke; V = Ve; Kh = Ke16; Vth = Vte16; Sk = SE;
        s0 = (blockIdx.x - SC / 64) * 64;
    }

    // K: permute d within 16-groups
#pragma unroll
    for (int i = 0; i < 4; i++) {
        int f = tid + 256 * i;
        int r = f >> 4, c4 = f & 15;
        float4 v = *(const float4*)(K + (size_t)(b * Sk + s0 + r) * HS + h * DH + c4 * 4);
        int c = c4 * 4;
        int n0 = kperm(c);
        size_t o = ((size_t)(bh * Sk + s0 + r)) * DH;
        *(uint32_t*)(Kh + o + n0) = packh2(v.x, v.y);
        *(uint32_t*)(Kh + o + n0 + 4) = packh2(v.z, v.w);
    }
    // V: stage rows, write transposed with seq permuted within 16-groups
#pragma unroll
    for (int i = 0; i < 4; i++) {
        int f = tid + 256 * i;
        int r = f >> 4, c4 = f & 15;
        float4 v = *(const float4*)(V + (size_t)(b * Sk + s0 + r) * HS + h * DH + c4 * 4);
        vs[r][c4 * 4 + 0] = v.x;
        vs[r][c4 * 4 + 1] = v.y;
        vs[r][c4 * 4 + 2] = v.z;
        vs[r][c4 * 4 + 3] = v.w;
    }
    __syncthreads();
#pragma unroll
    for (int i = 0; i < 8; i++) {
        int f = tid + 256 * i;
        int d = f >> 5, sp = f & 31;
        float v0 = vs[2 * sp][d], v1 = vs[2 * sp + 1][d];
        int np = kperm(2 * sp);
        size_t o = ((size_t)(bh * DH + d)) * Sk + s0 + np;
        *(uint32_t*)(Vth + o) = packh2(v0, v1);
    }
}

// ==================== attention: 4 warps x (32 q-rows x 64 keys), LDS.64 frags ====
#define AK    0
#define AV    10240
#define AMS   20480
#define ABUF  20736
#define ASMEM (2 * ABUF)   // 41472
#define ARS   160          // smem row stride (conflict-free LDS.64)

__global__ __launch_bounds__(128, 2) void attn_all(
    const float* __restrict__ Qc, const __half* __restrict__ Ke,
    const __half* __restrict__ Vte, const int* __restrict__ me,
    float* __restrict__ Ac,
    const float* __restrict__ Qe, const __half* __restrict__ Kc,
    const __half* __restrict__ Vtc, const int* __restrict__ mc,
    float* __restrict__ Ae)
{
    extern __shared__ char sm[];
    const uint32_t sb = smem_u32(sm);
    const int tid = threadIdx.x;
    const int wid = tid >> 5;
    const int lane = tid & 31;
    const int g = lane >> 2;
    const int t = lane & 3;
    const int b = blockIdx.z, h = blockIdx.y;
    const int bx = blockIdx.x;
    const int bh = b * NH + h;

    const float* Q;
    const __half* K;
    const __half* Vt;
    const int* mask;
    float* O;
    int Sq, Sk, q0;
    if (bx < SC / 128) {
        Q = Qc; K = Ke; Vt = Vte; mask = me; O = Ac;
        Sq = SC; Sk = SE; q0 = bx * 128;
    } else {
        Q = Qe; K = Kc; Vt = Vtc; mask = mc; O = Ae;
        Sq = SE; Sk = SC; q0 = (bx - SC / 128) * 128;
    }
    const int nt = Sk / 64;

    // cp.async: 8 chunks of 16B per thread per tile (K 512 + V 512 chunks)
    const char* csrc[8];
    uint32_t cdst[8];
#pragma unroll
    for (int q = 0; q < 8; q++) {
        int f = q * 128 + tid;
        int tile = f >> 9;
        int idx = f & 511;
        int r = idx >> 3, c = idx & 7;
        if (tile == 0) {
            csrc[q] = (const char*)(K + (size_t)(bh * (size_t)Sk + r) * DH + c * 8);
            cdst[q] = AK + (uint32_t)(r * ARS + c * 16);
        } else {
            csrc[q] = (const char*)(Vt + (size_t)(bh * DH + r) * (size_t)Sk + c * 8);
            cdst[q] = AV + (uint32_t)(r * ARS + c * 16);
        }
    }
    const char* msrc = (const char*)(mask + (size_t)b * Sk) + tid * 16;

    {
#pragma unroll
        for (int q = 0; q < 8; q++)
            cp16(sb + cdst[q], csrc[q]);
        if (tid < 16) cp16(sb + AMS + tid * 16, msrc);
        asm volatile("cp.async.commit_group;");
    }
    if (nt > 1) {
#pragma unroll
        for (int q = 0; q < 8; q++)
            cp16(sb + ABUF + cdst[q], csrc[q] + ((q < 4) ? 8192 : 128));
        if (tid < 16) cp16(sb + ABUF + AMS + tid * 16, msrc + 256);
    }
    asm volatile("cp.async.commit_group;");

    // Q fragments (2 m16 tiles per warp), pre-scaled by CSC
    uint32_t qh[2][4][4];
#pragma unroll
    for (int i = 0; i < 2; i++) {
        const float* qp0 = Q + (size_t)(b * Sq + q0 + wid * 32 + 16 * i + g) * HS + h * DH;
        const float* qp8 = qp0 + 8 * HS;
#pragma unroll
        for (int kk = 0; kk < 4; kk++) {
            int c0 = 16 * kk + 2 * t;
            float2 x0 = *(const float2*)(qp0 + c0);
            float2 x1 = *(const float2*)(qp8 + c0);
            float2 x2 = *(const float2*)(qp0 + c0 + 8);
            float2 x3 = *(const float2*)(qp8 + c0 + 8);
            qh[i][kk][0] = packh2(x0.x * CSC, x0.y * CSC);
            qh[i][kk][1] = packh2(x1.x * CSC, x1.y * CSC);
            qh[i][kk][2] = packh2(x2.x * CSC, x2.y * CSC);
            qh[i][kk][3] = packh2(x3.x * CSC, x3.y * CSC);
        }
    }

    float oacc[2][8][4];
#pragma unroll
    for (int i = 0; i < 2; i++)
#pragma unroll
        for (int j = 0; j < 8; j++)
#pragma unroll
            for (int k = 0; k < 4; k++) oacc[i][j][k] = 0.f;
    float l[2][2] = {{0.f, 0.f}, {0.f, 0.f}};

    for (int it = 0; it < nt; it++) {
        if (it + 1 < nt) { asm volatile("cp.async.wait_group 1;"); }
        else             { asm volatile("cp.async.wait_group 0;"); }
        __syncthreads();

        char* buf = sm + (it & 1) * ABUF;
        const int* ms = (const int*)(buf + AMS);

        // ---- S = Q @ K^T : one LDS.64 per K fragment, shared by both m-tiles ----
        float sacc[2][8][4];
#pragma unroll
        for (int i = 0; i < 2; i++)
#pragma unroll
            for (int j = 0; j < 8; j++)
#pragma unroll
                for (int k = 0; k < 4; k++) sacc[i][j][k] = 0.f;

#pragma unroll
        for (int kk = 0; kk < 4; kk++) {
#pragma unroll
            for (int j = 0; j < 8; j++) {
                uint2 kv = *(const uint2*)(buf + AK + (8 * j + g) * ARS + kk * 32 + t * 8);
                mma_f16(sacc[0][j], qh[0][kk], (const uint32_t*)&kv);
                mma_f16(sacc[1][j], qh[1][kk], (const uint32_t*)&kv);
            }
        }

        // ---- max-free softmax with MUFU exp2 ----
#pragma unroll
        for (int j = 0; j < 8; j++) {
            int2 mv = *(const int2*)(ms + 8 * j + 2 * t);
            float a0 = mv.x ? 0.f : MASKADD;
            float a1 = mv.y ? 0.f : MASKADD;
#pragma unroll
            for (int i = 0; i < 2; i++) {
                sacc[i][j][0] = ex2(sacc[i][j][0] + a0);
                sacc[i][j][1] = ex2(sacc[i][j][1] + a1);
                sacc[i][j][2] = ex2(sacc[i][j][2] + a0);
                sacc[i][j][3] = ex2(sacc[i][j][3] + a1);
                l[i][0] += sacc[i][j][0] + sacc[i][j][1];
                l[i][1] += sacc[i][j][2] + sacc[i][j][3];
            }
        }

        // ---- pack P into fp16 A-fragments ----
        uint32_t ph[2][4][4];
#pragma unroll
        for (int i = 0; i < 2; i++)
#pragma unroll
            for (int s = 0; s < 4; s++) {
                const float* pa = sacc[i][2 * s];
                const float* pb = sacc[i][2 * s + 1];
                ph[i][s][0] = packh2(pa[0], pa[1]);
                ph[i][s][1] = packh2(pa[2], pa[3]);
                ph[i][s][2] = packh2(pb[0], pb[1]);
                ph[i][s][3] = packh2(pb[2], pb[3]);
            }

        // ---- O += P @ V : one LDS.64 per V fragment, shared by both m-tiles ----
#pragma unroll
        for (int s = 0; s < 4; s++) {
#pragma unroll
            for (int j = 0; j < 8; j++) {
                uint2 vv = *(const uint2*)(buf + AV + (8 * j + g) * ARS + s * 32 + t * 8);
                mma_f16(oacc[0][j], ph[0][s], (const uint32_t*)&vv);
                mma_f16(oacc[1][j], ph[1][s], (const uint32_t*)&vv);
            }
        }

        __syncthreads();
        if (it + 2 < nt) {
            size_t kaK = (size_t)(it + 2) * 8192;
            size_t kaV = (size_t)(it + 2) * 128;
            uint32_t db = sb + (it & 1) * ABUF;
#pragma unroll
            for (int q = 0; q < 8; q++)
                cp16(db + cdst[q], csrc[q] + ((q < 4) ? kaK : kaV));
            if (tid < 16) cp16(db + AMS + tid * 16, msrc + (size_t)(it + 2) * 256);
        }
        asm volatile("cp.async.commit_group;");
    }

    // quad-reduce row sums, normalize, write
#pragma unroll
    for (int i = 0; i < 2; i++) {
        l[i][0] += __shfl_xor_sync(0xffffffffu, l[i][0], 1);
        l[i][0] += __shfl_xor_sync(0xffffffffu, l[i][0], 2);
        l[i][1] += __shfl_xor_sync(0xffffffffu, l[i][1], 1);
        l[i][1] += __shfl_xor_sync(0xffffffffu, l[i][1], 2);
        float inv0 = 1.f / l[i][0];
        float inv1 = 1.f / l[i][1];
        int row0 = q0 + wid * 32 + 16 * i + g;
#pragma unroll
        for (int j = 0; j < 8; j++) {
            int col = h * DH + 8 * j + 2 * t;
            *(float2*)(O + (size_t)(b * Sq + row0) * HS + col) =
                make_float2(oacc[i][j][0] * inv0, oacc[i][j][1] * inv0);
            *(float2*)(O + (size_t)(b * Sq + row0 + 8) * HS + col) =
                make_float2(oacc[i][j][2] * inv1, oacc[i][j][3] * inv1);
        }
    }
}

// ==================== fused residual add + LayerNorm (merged) ====================
__global__ __launch_bounds__(256) void add_ln_all(
    const float* __restrict__ xc, const float* __restrict__ Ac,
    const float* __restrict__ xe, const float* __restrict__ Ae,
    const float* __restrict__ g, const float* __restrict__ bb,
    float* __restrict__ out)
{
    int row = blockIdx.x;
    const float *x, *att;
    if (row < B * SC) { x = xc + (size_t)row * HS; att = Ac + (size_t)row * HS; }
    else {
        int r = row - B * SC;
        x = xe + (size_t)r * HS; att = Ae + (size_t)r * HS;
    }
    int tid = threadIdx.x;
    float4 xv = ((const float4*)x)[tid];
    float4 av = ((const float4*)att)[tid];
    float v0 = xv.x + av.x, v1 = xv.y + av.y, v2 = xv.z + av.z, v3 = xv.w + av.w;

    float s = v0 + v1 + v2 + v3;
    float sq = v0 * v0 + v1 * v1 + v2 * v2 + v3 * v3;
#pragma unroll
    for (int off = 16; off > 0; off >>= 1) {
        s  += __shfl_xor_sync(0xffffffffu, s, off);
        sq += __shfl_xor_sync(0xffffffffu, sq, off);
    }
    __shared__ float ss[8], ssq[8];
    int wid = tid >> 5, lane = tid & 31;
    if (lane == 0) { ss[wid] = s; ssq[wid] = sq; }
    __syncthreads();
    s = 0.f; sq = 0.f;
#pragma unroll
    for (int w = 0; w < 8; w++) { s += ss[w]; sq += ssq[w]; }

    float mu = s * (1.f / HS);
    float var = sq * (1.f / HS) - mu * mu;
    float r = rsqrtf(var + 1e-5f);

    float4 gv = ((const float4*)g)[tid];
    float4 bv = ((const float4*)bb)[tid];
    float4 ov = make_float4((v0 - mu) * r * gv.x + bv.x,
                            (v1 - mu) * r * gv.y + bv.y,
                            (v2 - mu) * r * gv.z + bv.z,
                            (v3 - mu) * r * gv.w + bv.w);
    ((float4*)(out + (size_t)row * HS))[tid] = ov;
}

// ==================== launcher ====================
extern "C" void kernel_launch(void* const* d_in, const int* in_sizes, int n_in,
                              void* d_out, int out_size)
{
    (void)in_sizes; (void)n_in; (void)out_size;
    const float* x_c   = (const float*)d_in[0];
    const float* x_e   = (const float*)d_in[1];
    const int*   msk_c = (const int*)d_in[2];
    const int*   msk_e = (const int*)d_in[3];
    const float* W_cq = (const float*)d_in[4];  const float* b_cq = (const float*)d_in[5];
    const float* W_ek = (const float*)d_in[6];  const float* b_ek = (const float*)d_in[7];
    const float* W_ev = (const float*)d_in[8];  const float* b_ev = (const float*)d_in[9];
    const float* W_eq = (const float*)d_in[10]; const float* b_eq = (const float*)d_in[11];
    const float* W_ck = (const float*)d_in[12]; const float* b_ck = (const float*)d_in[13];
    const float* W_cv = (const float*)d_in[14]; const float* b_cv = (const float*)d_in[15];
    const float* ln_g = (const float*)d_in[16]; const float* ln_b = (const float*)d_in[17];
    float* out = (float*)d_out;

    float *QKVc, *QKVe, *Ac, *Ae;
    cudaGetSymbolAddress((void**)&QKVc, g_QKVc);
    cudaGetSymbolAddress((void**)&QKVe, g_QKVe);
    cudaGetSymbolAddress((void**)&Ac, g_Ac);
    cudaGetSymbolAddress((void**)&Ae, g_Ae);
    __half *xch, *xeh, *Wch, *Weh;
    cudaGetSymbolAddress((void**)&xch, g_xch);
    cudaGetSymbolAddress((void**)&xeh, g_xeh);
    cudaGetSymbolAddress((void**)&Wch, g_Wch);
    cudaGetSymbolAddress((void**)&Weh, g_Weh);
    __half *Ke16, *Vte16, *Kc16, *Vtc16;
    cudaGetSymbolAddress((void**)&Ke16, g_Ke16);
    cudaGetSymbolAddress((void**)&Vte16, g_Vte16);
    cudaGetSymbolAddress((void**)&Kc16, g_Kc16);
    cudaGetSymbolAddress((void**)&Vtc16, g_Vtc16);

    cudaFuncSetAttribute(gemm_f16, cudaFuncAttributeMaxDynamicSharedMemorySize, G_SMEM);
    cudaFuncSetAttribute(attn_all, cudaFuncAttributeMaxDynamicSharedMemorySize, ASMEM);

    const int Mc = B * SC;   // 2048
    const int Me = B * SE;   // 8192

    cvt_all<<<16384, 256>>>(W_cq, W_ck, W_cv, W_eq, W_ek, W_ev, x_c, x_e,
                            Wch, Weh, xch, xeh);

    gemm_f16<<<dim3(4, Me / 128, 6), 256, G_SMEM>>>(
        xeh, Weh, xch, Wch,
        b_eq, b_ek, b_ev, b_cq, b_ck, b_cv,
        QKVe, QKVc);

    float* Qc = QKVc;
    float* Kc = QKVc + (size_t)Mc * HS;
    float* Vc = QKVc + (size_t)2 * Mc * HS;
    float* Qe = QKVe;
    float* Ke = QKVe + (size_t)Me * HS;
    float* Ve = QKVe + (size_t)2 * Me * HS;

    prep_all<<<dim3(SC / 64 + SE / 64, NH, B), 256>>>(
        Kc, Vc, Kc16, Vtc16, Ke, Ve, Ke16, Vte16);

    attn_all<<<dim3(SC / 128 + SE / 128, NH, B), 128, ASMEM>>>(
        Qc, Ke16, Vte16, msk_e, Ac,
        Qe, Kc16, Vtc16, msk_c, Ae);

    add_ln_all<<<Mc + Me, 256>>>(x_c, Ac, x_e, Ae, ln_g, ln_b, out);
}

// round 10
// speedup vs baseline: 1.0602x; 1.0602x over previous
#include <cuda_runtime.h>
#include <cuda_fp16.h>
#include <cstdint>

#define HS 1024
#define NH 16
#define DH 64
#define B 4
#define SC 512
#define SE 2048

// -------------------- scratch (device globals; no allocation) --------------------
__device__ float g_QKVc[(size_t)3 * B * SC * HS];   // Qc | Kc | Vc
__device__ float g_QKVe[(size_t)3 * B * SE * HS];   // Qe | Ke | Ve
__device__ float g_Ac[(size_t)B * SC * HS];
__device__ float g_Ae[(size_t)B * SE * HS];
// fp16 preconverted GEMM operands (k-dim permuted within 16-groups)
__device__ __align__(256) __half g_xch[(size_t)B * SC * HS];
__device__ __align__(256) __half g_xeh[(size_t)B * SE * HS];
__device__ __align__(256) __half g_Wch[(size_t)3 * HS * HS];   // W_cq|W_ck|W_cv
__device__ __align__(256) __half g_Weh[(size_t)3 * HS * HS];   // W_eq|W_ek|W_ev
// fp16 K (d-permuted) / V-transposed (seq-permuted) per head
__device__ __align__(256) __half g_Ke16[(size_t)B * NH * SE * DH];
__device__ __align__(256) __half g_Vte16[(size_t)B * NH * SE * DH];
__device__ __align__(256) __half g_Kc16[(size_t)B * NH * SC * DH];
__device__ __align__(256) __half g_Vtc16[(size_t)B * NH * SC * DH];

// ==================== helpers ====================
__device__ __forceinline__ void mma_f16(float* d, const uint32_t* a, const uint32_t* b) {
    asm volatile(
        "mma.sync.aligned.m16n8k16.row.col.f32.f16.f16.f32 "
        "{%0,%1,%2,%3}, {%4,%5,%6,%7}, {%8,%9}, {%0,%1,%2,%3};"
        : "+f"(d[0]), "+f"(d[1]), "+f"(d[2]), "+f"(d[3])
        : "r"(a[0]), "r"(a[1]), "r"(a[2]), "r"(a[3]), "r"(b[0]), "r"(b[1]));
}

__device__ __forceinline__ uint32_t packh2(float a, float b) {
    __half2 h = __floats2half2_rn(a, b);
    return *(uint32_t*)&h;
}

__device__ __forceinline__ uint32_t smem_u32(const void* p) {
    uint32_t a;
    asm("{ .reg .u64 t; cvta.to.shared.u64 t, %1; cvt.u32.u64 %0, t; }" : "=r"(a) : "l"(p));
    return a;
}

__device__ __forceinline__ void cp16(uint32_t dst, const void* src) {
    asm volatile("cp.async.cg.shared.global [%0], [%1], 16;" :: "r"(dst), "l"(src));
}

// hardware exp2 (MUFU.EX2)
__device__ __forceinline__ float ex2(float x) {
    float r;
    asm("ex2.approx.f32 %0, %1;" : "=f"(r) : "f"(x));
    return r;
}

// k-dim pair permutation: within each 16-element group, lane t's fragment
// elements {2t,2t+1,2t+8,2t+9} become contiguous -> one LDS.64 per fragment row.
__device__ __forceinline__ int kperm(int c) {
    return (c >> 4) * 16 + (((c & 7) >> 1) << 2) + (((c >> 3) & 1) << 1);
}

#define CSC 0.1803368801111694f   // log2(e)/8
#define MASKADD (-24000.0f)

// ==================== merged convert: 6 weights + 2 activations (k-permuted) =====
__global__ __launch_bounds__(256) void cvt_all(
    const float* __restrict__ Wcq, const float* __restrict__ Wck,
    const float* __restrict__ Wcv, const float* __restrict__ Weq,
    const float* __restrict__ Wek, const float* __restrict__ Wev,
    const float* __restrict__ xc, const float* __restrict__ xe,
    __half* __restrict__ dWc, __half* __restrict__ dWe,
    __half* __restrict__ dxc, __half* __restrict__ dxe)
{
    int bid = blockIdx.x;
    const float* s;
    __half* d;
    int i;
    if (bid < 6144) {
        int z = bid >> 10;
        const float* Ws[6] = {Wcq, Wck, Wcv, Weq, Wek, Wev};
        s = Ws[z];
        d = (z < 3) ? (dWc + ((size_t)z << 20)) : (dWe + ((size_t)(z - 3) << 20));
        i = (bid & 1023) * 256 + threadIdx.x;
    } else if (bid < 8192) {
        s = xc; d = dxc;
        i = (bid - 6144) * 256 + threadIdx.x;
    } else {
        s = xe; d = dxe;
        i = (bid - 8192) * 256 + threadIdx.x;
    }
    float4 v = ((const float4*)s)[i];
    int e = i * 4;
    int row = e >> 10;            // HS = 1024 elements per row
    int cr = e & 1023;
    int n0 = kperm(cr);           // pair (cr,cr+1) -> n0 ; pair (cr+2,cr+3) -> n0+4
    __half* dr = d + ((size_t)row << 10);
    *(uint32_t*)(dr + n0) = packh2(v.x, v.y);
    *(uint32_t*)(dr + n0 + 4) = packh2(v.z, v.w);
}

// ==================== GEMM: 128x128 tile, 128 thr, 2 CTA/SM, LDS.64 frags ========
#define G_RS    96
#define G_A     0
#define G_B     (128 * G_RS)          // 12288
#define G_STAGE (256 * G_RS)          // 24576
#define G_SMEM  (3 * G_STAGE)         // 73728

__global__ __launch_bounds__(128, 2) void gemm_f16(
    const __half* __restrict__ xeh, const __half* __restrict__ Weh,
    const __half* __restrict__ xch, const __half* __restrict__ Wch,
    const float* __restrict__ beq, const float* __restrict__ bek,
    const float* __restrict__ bev,
    const float* __restrict__ bcq, const float* __restrict__ bck,
    const float* __restrict__ bcv,
    float* __restrict__ Ce, float* __restrict__ Cc)
{
    const int z = blockIdx.z;
    const __half *Ah, *Wz;
    float* C;
    const float* bias;
    if (z < 3) {
        Ah = xeh;
        Wz = Weh + ((size_t)z << 20);
        C = Ce + (size_t)z * (B * SE) * HS;
        bias = (z == 0) ? beq : ((z == 1) ? bek : bev);
    } else {
        if (blockIdx.y >= (B * SC) / 128) return;
        int zz = z - 3;
        Ah = xch;
        Wz = Wch + ((size_t)zz << 20);
        C = Cc + (size_t)zz * (B * SC) * HS;
        bias = (zz == 0) ? bcq : ((zz == 1) ? bck : bcv);
    }

    extern __shared__ char smem[];
    const uint32_t sb = smem_u32(smem);
    const int tid = threadIdx.x;
    const int wid = tid >> 5;
    const int lane = tid & 31;
    const int g = lane >> 2;
    const int t = lane & 3;
    const int wm = wid >> 1;      // 0..1 -> 64 rows each
    const int wn = wid & 1;       // 0..1 -> 64 cols each
    const int bm = blockIdx.y * 128;
    const int bn = blockIdx.x * 128;

    // cp.async: 8 chunks of 16B per thread per stage (A 512 + B 512 chunks)
    const char* csrc[8];
    uint32_t cdst[8];
#pragma unroll
    for (int q = 0; q < 8; q++) {
        int f = q * 128 + tid;
        int tile = f >> 9;
        int idx = f & 511;
        int r = idx >> 2, c = idx & 3;
        cdst[q] = (uint32_t)(tile * G_B + r * G_RS + c * 16);
        if (tile == 0) csrc[q] = (const char*)(Ah + (size_t)(bm + r) * HS + c * 8);
        else           csrc[q] = (const char*)(Wz + (size_t)(bn + r) * HS + c * 8);
    }

    const int NC = HS / 32;

#pragma unroll
    for (int st = 0; st < 3; st++) {
        uint32_t db = sb + st * G_STAGE;
#pragma unroll
        for (int q = 0; q < 8; q++)
            cp16(db + cdst[q], csrc[q] + st * 64);
        asm volatile("cp.async.commit_group;");
    }

    float acc[4][8][4];
#pragma unroll
    for (int i = 0; i < 4; i++)
#pragma unroll
        for (int j = 0; j < 8; j++)
#pragma unroll
            for (int k = 0; k < 4; k++) acc[i][j][k] = 0.f;

    for (int c = 0; c < NC; c++) {
        asm volatile("cp.async.wait_group 2;");
        __syncthreads();

        const char* buf = smem + (c % 3) * G_STAGE;
#pragma unroll
        for (int s = 0; s < 2; s++) {
            const int kb = s * 32 + t * 8;   // 32B per k16 group, LDS.64 per frag
            uint32_t ah[4][4];
#pragma unroll
            for (int i = 0; i < 4; i++) {
                const char* pa = buf + G_A + (wm * 64 + 16 * i + g) * G_RS + kb;
                uint2 alo = *(const uint2*)(pa);
                uint2 ahi = *(const uint2*)(pa + 8 * G_RS);
                ah[i][0] = alo.x;   // row g,   k 2t,2t+1
                ah[i][1] = ahi.x;   // row g+8, k 2t,2t+1
                ah[i][2] = alo.y;   // row g,   k 2t+8,2t+9
                ah[i][3] = ahi.y;   // row g+8, k 2t+8,2t+9
            }
#pragma unroll
            for (int j = 0; j < 8; j++) {
                uint2 bv = *(const uint2*)(buf + G_B + (wn * 64 + 8 * j + g) * G_RS + kb);
#pragma unroll
                for (int i = 0; i < 4; i++)
                    mma_f16(acc[i][j], ah[i], (const uint32_t*)&bv);
            }
        }
        __syncthreads();

        if (c + 3 < NC) {
            uint32_t db = sb + ((c + 3) % 3) * G_STAGE;
            int koff = (c + 3) * 64;
#pragma unroll
            for (int q = 0; q < 8; q++)
                cp16(db + cdst[q], csrc[q] + koff);
        }
        asm volatile("cp.async.commit_group;");
    }

#pragma unroll
    for (int i = 0; i < 4; i++) {
        int row0 = bm + wm * 64 + 16 * i + g;
#pragma unroll
        for (int j = 0; j < 8; j++) {
            int col = bn + wn * 64 + 8 * j + 2 * t;
            float2 bv2 = *(const float2*)(bias + col);
            *(float2*)(C + (size_t)row0 * HS + col) =
                make_float2(acc[i][j][0] + bv2.x, acc[i][j][1] + bv2.y);
            *(float2*)(C + (size_t)(row0 + 8) * HS + col) =
                make_float2(acc[i][j][2] + bv2.x, acc[i][j][3] + bv2.y);
        }
    }
}

// ==================== K/V prep: fp32 -> fp16, k-dim permuted ====================
__global__ __launch_bounds__(256) void prep_all(
    const float* __restrict__ Kc, const float* __restrict__ Vc,
    __half* __restrict__ Kc16, __half* __restrict__ Vtc16,
    const float* __restrict__ Ke, const float* __restrict__ Ve,
    __half* __restrict__ Ke16, __half* __restrict__ Vte16)
{
    __shared__ float vs[64][65];
    const int tid = threadIdx.x;
    const int b = blockIdx.z, h = blockIdx.y;
    const int bh = b * NH + h;

    const float *K, *V;
    __half *Kh, *Vth;
    int Sk, s0;
    if (blockIdx.x < SC / 64) {
        K = Kc; V = Vc; Kh = Kc16; Vth = Vtc16; Sk = SC;
        s0 = blockIdx.x * 64;
    } else {
        K = Ke; V = Ve; Kh = Ke16; Vth = Vte16; Sk = SE;
        s0 = (blockIdx.x - SC / 64) * 64;
    }

#pragma unroll
    for (int i = 0; i < 4; i++) {
        int f = tid + 256 * i;
        int r = f >> 4, c4 = f & 15;
        float4 v = *(const float4*)(K + (size_t)(b * Sk + s0 + r) * HS + h * DH + c4 * 4);
        int c = c4 * 4;
        int n0 = kperm(c);
        size_t o = ((size_t)(bh * Sk + s0 + r)) * DH;
        *(uint32_t*)(Kh + o + n0) = packh2(v.x, v.y);
        *(uint32_t*)(Kh + o + n0 + 4) = packh2(v.z, v.w);
    }
#pragma unroll
    for (int i = 0; i < 4; i++) {
        int f = tid + 256 * i;
        int r = f >> 4, c4 = f & 15;
        float4 v = *(const float4*)(V + (size_t)(b * Sk + s0 + r) * HS + h * DH + c4 * 4);
        vs[r][c4 * 4 + 0] = v.x;
        vs[r][c4 * 4 + 1] = v.y;
        vs[r][c4 * 4 + 2] = v.z;
        vs[r][c4 * 4 + 3] = v.w;
    }
    __syncthreads();
#pragma unroll
    for (int i = 0; i < 8; i++) {
        int f = tid + 256 * i;
        int d = f >> 5, sp = f & 31;
        float v0 = vs[2 * sp][d], v1 = vs[2 * sp + 1][d];
        int np = kperm(2 * sp);
        size_t o = ((size_t)(bh * DH + d)) * Sk + s0 + np;
        *(uint32_t*)(Vth + o) = packh2(v0, v1);
    }
}

// ==================== attention: 4 warps x (32 q-rows x 64 keys), LDS.64 frags ====
#define AK    0
#define AV    10240
#define AMS   20480
#define ABUF  20736
#define ASMEM (2 * ABUF)   // 41472
#define ARS   160          // smem row stride (conflict-free LDS.64)

__global__ __launch_bounds__(128, 2) void attn_all(
    const float* __restrict__ Qc, const __half* __restrict__ Ke,
    const __half* __restrict__ Vte, const int* __restrict__ me,
    float* __restrict__ Ac,
    const float* __restrict__ Qe, const __half* __restrict__ Kc,
    const __half* __restrict__ Vtc, const int* __restrict__ mc,
    float* __restrict__ Ae)
{
    extern __shared__ char sm[];
    const uint32_t sb = smem_u32(sm);
    const int tid = threadIdx.x;
    const int wid = tid >> 5;
    const int lane = tid & 31;
    const int g = lane >> 2;
    const int t = lane & 3;
    const int b = blockIdx.z, h = blockIdx.y;
    const int bx = blockIdx.x;
    const int bh = b * NH + h;

    const float* Q;
    const __half* K;
    const __half* Vt;
    const int* mask;
    float* O;
    int Sq, Sk, q0;
    if (bx < SC / 128) {
        Q = Qc; K = Ke; Vt = Vte; mask = me; O = Ac;
        Sq = SC; Sk = SE; q0 = bx * 128;
    } else {
        Q = Qe; K = Kc; Vt = Vtc; mask = mc; O = Ae;
        Sq = SE; Sk = SC; q0 = (bx - SC / 128) * 128;
    }
    const int nt = Sk / 64;

    const char* csrc[8];
    uint32_t cdst[8];
#pragma unroll
    for (int q = 0; q < 8; q++) {
        int f = q * 128 + tid;
        int tile = f >> 9;
        int idx = f & 511;
        int r = idx >> 3, c = idx & 7;
        if (tile == 0) {
            csrc[q] = (const char*)(K + (size_t)(bh * (size_t)Sk + r) * DH + c * 8);
            cdst[q] = AK + (uint32_t)(r * ARS + c * 16);
        } else {
            csrc[q] = (const char*)(Vt + (size_t)(bh * DH + r) * (size_t)Sk + c * 8);
            cdst[q] = AV + (uint32_t)(r * ARS + c * 16);
        }
    }
    const char* msrc = (const char*)(mask + (size_t)b * Sk) + tid * 16;

    {
#pragma unroll
        for (int q = 0; q < 8; q++)
            cp16(sb + cdst[q], csrc[q]);
        if (tid < 16) cp16(sb + AMS + tid * 16, msrc);
        asm volatile("cp.async.commit_group;");
    }
    if (nt > 1) {
#pragma unroll
        for (int q = 0; q < 8; q++)
            cp16(sb + ABUF + cdst[q], csrc[q] + ((q < 4) ? 8192 : 128));
        if (tid < 16) cp16(sb + ABUF + AMS + tid * 16, msrc + 256);
    }
    asm volatile("cp.async.commit_group;");

    // Q fragments (2 m16 tiles per warp), pre-scaled by CSC
    uint32_t qh[2][4][4];
#pragma unroll
    for (int i = 0; i < 2; i++) {
        const float* qp0 = Q + (size_t)(b * Sq + q0 + wid * 32 + 16 * i + g) * HS + h * DH;
        const float* qp8 = qp0 + 8 * HS;
#pragma unroll
        for (int kk = 0; kk < 4; kk++) {
            int c0 = 16 * kk + 2 * t;
            float2 x0 = *(const float2*)(qp0 + c0);
            float2 x1 = *(const float2*)(qp8 + c0);
            float2 x2 = *(const float2*)(qp0 + c0 + 8);
            float2 x3 = *(const float2*)(qp8 + c0 + 8);
            qh[i][kk][0] = packh2(x0.x * CSC, x0.y * CSC);
            qh[i][kk][1] = packh2(x1.x * CSC, x1.y * CSC);
            qh[i][kk][2] = packh2(x2.x * CSC, x2.y * CSC);
            qh[i][kk][3] = packh2(x3.x * CSC, x3.y * CSC);
        }
    }

    float oacc[2][8][4];
#pragma unroll
    for (int i = 0; i < 2; i++)
#pragma unroll
        for (int j = 0; j < 8; j++)
#pragma unroll
            for (int k = 0; k < 4; k++) oacc[i][j][k] = 0.f;
    float l[2][2] = {{0.f, 0.f}, {0.f, 0.f}};

    for (int it = 0; it < nt; it++) {
        if (it + 1 < nt) { asm volatile("cp.async.wait_group 1;"); }
        else             { asm volatile("cp.async.wait_group 0;"); }
        __syncthreads();

        char* buf = sm + (it & 1) * ABUF;
        const int* ms = (const int*)(buf + AMS);

        float sacc[2][8][4];
#pragma unroll
        for (int i = 0; i < 2; i++)
#pragma unroll
            for (int j = 0; j < 8; j++)
#pragma unroll
                for (int k = 0; k < 4; k++) sacc[i][j][k] = 0.f;

#pragma unroll
        for (int kk = 0; kk < 4; kk++) {
#pragma unroll
            for (int j = 0; j < 8; j++) {
                uint2 kv = *(const uint2*)(buf + AK + (8 * j + g) * ARS + kk * 32 + t * 8);
                mma_f16(sacc[0][j], qh[0][kk], (const uint32_t*)&kv);
                mma_f16(sacc[1][j], qh[1][kk], (const uint32_t*)&kv);
            }
        }

#pragma unroll
        for (int j = 0; j < 8; j++) {
            int2 mv = *(const int2*)(ms + 8 * j + 2 * t);
            float a0 = mv.x ? 0.f : MASKADD;
            float a1 = mv.y ? 0.f : MASKADD;
#pragma unroll
            for (int i = 0; i < 2; i++) {
                sacc[i][j][0] = ex2(sacc[i][j][0] + a0);
                sacc[i][j][1] = ex2(sacc[i][j][1] + a1);
                sacc[i][j][2] = ex2(sacc[i][j][2] + a0);
                sacc[i][j][3] = ex2(sacc[i][j][3] + a1);
                l[i][0] += sacc[i][j][0] + sacc[i][j][1];
                l[i][1] += sacc[i][j][2] + sacc[i][j][3];
            }
        }

        uint32_t ph[2][4][4];
#pragma unroll
        for (int i = 0; i < 2; i++)
#pragma unroll
            for (int s = 0; s < 4; s++) {
                const float* pa = sacc[i][2 * s];
                const float* pb = sacc[i][2 * s + 1];
                ph[i][s][0] = packh2(pa[0], pa[1]);
                ph[i][s][1] = packh2(pa[2], pa[3]);
                ph[i][s][2] = packh2(pb[0], pb[1]);
                ph[i][s][3] = packh2(pb[2], pb[3]);
            }

#pragma unroll
        for (int s = 0; s < 4; s++) {
#pragma unroll
            for (int j = 0; j < 8; j++) {
                uint2 vv = *(const uint2*)(buf + AV + (8 * j + g) * ARS + s * 32 + t * 8);
                mma_f16(oacc[0][j], ph[0][s], (const uint32_t*)&vv);
                mma_f16(oacc[1][j], ph[1][s], (const uint32_t*)&vv);
            }
        }

        __syncthreads();
        if (it + 2 < nt) {
            size_t kaK = (size_t)(it + 2) * 8192;
            size_t kaV = (size_t)(it + 2) * 128;
            uint32_t db = sb + (it & 1) * ABUF;
#pragma unroll
            for (int q = 0; q < 8; q++)
                cp16(db + cdst[q], csrc[q] + ((q < 4) ? kaK : kaV));
            if (tid < 16) cp16(db + AMS + tid * 16, msrc + (size_t)(it + 2) * 256);
        }
        asm volatile("cp.async.commit_group;");
    }

#pragma unroll
    for (int i = 0; i < 2; i++) {
        l[i][0] += __shfl_xor_sync(0xffffffffu, l[i][0], 1);
        l[i][0] += __shfl_xor_sync(0xffffffffu, l[i][0], 2);
        l[i][1] += __shfl_xor_sync(0xffffffffu, l[i][1], 1);
        l[i][1] += __shfl_xor_sync(0xffffffffu, l[i][1], 2);
        float inv0 = 1.f / l[i][0];
        float inv1 = 1.f / l[i][1];
        int row0 = q0 + wid * 32 + 16 * i + g;
#pragma unroll
        for (int j = 0; j < 8; j++) {
            int col = h * DH + 8 * j + 2 * t;
            *(float2*)(O + (size_t)(b * Sq + row0) * HS + col) =
                make_float2(oacc[i][j][0] * inv0, oacc[i][j][1] * inv0);
            *(float2*)(O + (size_t)(b * Sq + row0 + 8) * HS + col) =
                make_float2(oacc[i][j][2] * inv1, oacc[i][j][3] * inv1);
        }
    }
}

// ==================== fused residual add + LayerNorm (merged) ====================
__global__ __launch_bounds__(256) void add_ln_all(
    const float* __restrict__ xc, const float* __restrict__ Ac,
    const float* __restrict__ xe, const float* __restrict__ Ae,
    const float* __restrict__ g, const float* __restrict__ bb,
    float* __restrict__ out)
{
    int row = blockIdx.x;
    const float *x, *att;
    if (row < B * SC) { x = xc + (size_t)row * HS; att = Ac + (size_t)row * HS; }
    else {
        int r = row - B * SC;
        x = xe + (size_t)r * HS; att = Ae + (size_t)r * HS;
    }
    int tid = threadIdx.x;
    float4 xv = ((const float4*)x)[tid];
    float4 av = ((const float4*)att)[tid];
    float v0 = xv.x + av.x, v1 = xv.y + av.y, v2 = xv.z + av.z, v3 = xv.w + av.w;

    float s = v0 + v1 + v2 + v3;
    float sq = v0 * v0 + v1 * v1 + v2 * v2 + v3 * v3;
#pragma unroll
    for (int off = 16; off > 0; off >>= 1) {
        s  += __shfl_xor_sync(0xffffffffu, s, off);
        sq += __shfl_xor_sync(0xffffffffu, sq, off);
    }
    __shared__ float ss[8], ssq[8];
    int wid = tid >> 5, lane = tid & 31;
    if (lane == 0) { ss[wid] = s; ssq[wid] = sq; }
    __syncthreads();
    s = 0.f; sq = 0.f;
#pragma unroll
    for (int w = 0; w < 8; w++) { s += ss[w]; sq += ssq[w]; }

    float mu = s * (1.f / HS);
    float var = sq * (1.f / HS) - mu * mu;
    float r = rsqrtf(var + 1e-5f);

    float4 gv = ((const float4*)g)[tid];
    float4 bv = ((const float4*)bb)[tid];
    float4 ov = make_float4((v0 - mu) * r * gv.x + bv.x,
                            (v1 - mu) * r * gv.y + bv.y,
                            (v2 - mu) * r * gv.z + bv.z,
                            (v3 - mu) * r * gv.w + bv.w);
    ((float4*)(out + (size_t)row * HS))[tid] = ov;
}

// ==================== launcher ====================
extern "C" void kernel_launch(void* const* d_in, const int* in_sizes, int n_in,
                              void* d_out, int out_size)
{
    (void)in_sizes; (void)n_in; (void)out_size;
    const float* x_c   = (const float*)d_in[0];
    const float* x_e   = (const float*)d_in[1];
    const int*   msk_c = (const int*)d_in[2];
    const int*   msk_e = (const int*)d_in[3];
    const float* W_cq = (const float*)d_in[4];  const float* b_cq = (const float*)d_in[5];
    const float* W_ek = (const float*)d_in[6];  const float* b_ek = (const float*)d_in[7];
    const float* W_ev = (const float*)d_in[8];  const float* b_ev = (const float*)d_in[9];
    const float* W_eq = (const float*)d_in[10]; const float* b_eq = (const float*)d_in[11];
    const float* W_ck = (const float*)d_in[12]; const float* b_ck = (const float*)d_in[13];
    const float* W_cv = (const float*)d_in[14]; const float* b_cv = (const float*)d_in[15];
    const float* ln_g = (const float*)d_in[16]; const float* ln_b = (const float*)d_in[17];
    float* out = (float*)d_out;

    float *QKVc, *QKVe, *Ac, *Ae;
    cudaGetSymbolAddress((void**)&QKVc, g_QKVc);
    cudaGetSymbolAddress((void**)&QKVe, g_QKVe);
    cudaGetSymbolAddress((void**)&Ac, g_Ac);
    cudaGetSymbolAddress((void**)&Ae, g_Ae);
    __half *xch, *xeh, *Wch, *Weh;
    cudaGetSymbolAddress((void**)&xch, g_xch);
    cudaGetSymbolAddress((void**)&xeh, g_xeh);
    cudaGetSymbolAddress((void**)&Wch, g_Wch);
    cudaGetSymbolAddress((void**)&Weh, g_Weh);
    __half *Ke16, *Vte16, *Kc16, *Vtc16;
    cudaGetSymbolAddress((void**)&Ke16, g_Ke16);
    cudaGetSymbolAddress((void**)&Vte16, g_Vte16);
    cudaGetSymbolAddress((void**)&Kc16, g_Kc16);
    cudaGetSymbolAddress((void**)&Vtc16, g_Vtc16);

    cudaFuncSetAttribute(gemm_f16, cudaFuncAttributeMaxDynamicSharedMemorySize, G_SMEM);
    cudaFuncSetAttribute(attn_all, cudaFuncAttributeMaxDynamicSharedMemorySize, ASMEM);

    const int Mc = B * SC;   // 2048
    const int Me = B * SE;   // 8192

    cvt_all<<<16384, 256>>>(W_cq, W_ck, W_cv, W_eq, W_ek, W_ev, x_c, x_e,
                            Wch, Weh, xch, xeh);

    gemm_f16<<<dim3(8, Me / 128, 6), 128, G_SMEM>>>(
        xeh, Weh, xch, Wch,
        b_eq, b_ek, b_ev, b_cq, b_ck, b_cv,
        QKVe, QKVc);

    float* Qc = QKVc;
    float* Kc = QKVc + (size_t)Mc * HS;
    float* Vc = QKVc + (size_t)2 * Mc * HS;
    float* Qe = QKVe;
    float* Ke = QKVe + (size_t)Me * HS;
    float* Ve = QKVe + (size_t)2 * Me * HS;

    prep_all<<<dim3(SC / 64 + SE / 64, NH, B), 256>>>(
        Kc, Vc, Kc16, Vtc16, Ke, Ve, Ke16, Vte16);

    attn_all<<<dim3(SC / 128 + SE / 128, NH, B), 128, ASMEM>>>(
        Qc, Ke16, Vte16, msk_e, Ac,
        Qe, Kc16, Vtc16, msk_c, Ae);

    add_ln_all<<<Mc + Me, 256>>>(x_c, Ac, x_e, Ae, ln_g, ln_b, out);
}

// round 12
// speedup vs baseline: 1.1021x; 1.0395x over previous
#include <cuda_runtime.h>
#include <cuda_fp16.h>
#include <cstdint>

#define HS 1024
#define NH 16
#define DH 64
#define B 4
#define SC 512
#define SE 2048

// -------------------- scratch (device globals; no allocation) --------------------
__device__ float g_QKVc[(size_t)3 * B * SC * HS];   // Qc | Kc | Vc
__device__ float g_QKVe[(size_t)3 * B * SE * HS];   // Qe | Ke | Ve
__device__ float g_Ac[(size_t)B * SC * HS];
__device__ float g_Ae[(size_t)B * SE * HS];
// fp16 preconverted GEMM operands (k-dim permuted within 16-groups)
__device__ __align__(256) __half g_xch[(size_t)B * SC * HS];
__device__ __align__(256) __half g_xeh[(size_t)B * SE * HS];
__device__ __align__(256) __half g_Wch[(size_t)3 * HS * HS];   // W_cq|W_ck|W_cv
__device__ __align__(256) __half g_Weh[(size_t)3 * HS * HS];   // W_eq|W_ek|W_ev
// fp16 K (d-permuted) / V-transposed (seq-permuted) per head
__device__ __align__(256) __half g_Ke16[(size_t)B * NH * SE * DH];
__device__ __align__(256) __half g_Vte16[(size_t)B * NH * SE * DH];
__device__ __align__(256) __half g_Kc16[(size_t)B * NH * SC * DH];
__device__ __align__(256) __half g_Vtc16[(size_t)B * NH * SC * DH];
// fp16 masks (0.0 / 1.0)
__device__ __align__(256) __half g_mhc[(size_t)B * SC];
__device__ __align__(256) __half g_mhe[(size_t)B * SE];

// ==================== helpers ====================
__device__ __forceinline__ void mma_f16(float* d, const uint32_t* a, const uint32_t* b) {
    asm volatile(
        "mma.sync.aligned.m16n8k16.row.col.f32.f16.f16.f32 "
        "{%0,%1,%2,%3}, {%4,%5,%6,%7}, {%8,%9}, {%0,%1,%2,%3};"
        : "+f"(d[0]), "+f"(d[1]), "+f"(d[2]), "+f"(d[3])
        : "r"(a[0]), "r"(a[1]), "r"(a[2]), "r"(a[3]), "r"(b[0]), "r"(b[1]));
}

__device__ __forceinline__ uint32_t packh2(float a, float b) {
    __half2 h = __floats2half2_rn(a, b);
    return *(uint32_t*)&h;
}

__device__ __forceinline__ uint32_t hmul2u(uint32_t a, uint32_t b) {
    __half2 r = __hmul2(*(__half2*)&a, *(__half2*)&b);
    return *(uint32_t*)&r;
}

__device__ __forceinline__ uint32_t smem_u32(const void* p) {
    uint32_t a;
    asm("{ .reg .u64 t; cvta.to.shared.u64 t, %1; cvt.u32.u64 %0, t; }" : "=r"(a) : "l"(p));
    return a;
}

__device__ __forceinline__ void cp16(uint32_t dst, const void* src) {
    asm volatile("cp.async.cg.shared.global [%0], [%1], 16;" :: "r"(dst), "l"(src));
}

// hardware exp2 (MUFU.EX2)
__device__ __forceinline__ float ex2(float x) {
    float r;
    asm("ex2.approx.f32 %0, %1;" : "=f"(r) : "f"(x));
    return r;
}

// k-dim pair permutation (within 16-element groups) used by prep_all (K,V paths)
__device__ __forceinline__ int kperm(int c) {
    return (c >> 4) * 16 + (((c & 7) >> 1) << 2) + (((c >> 3) & 1) << 1);
}

#define CSC 0.1803368801111694f   // log2(e)/8

// ==================== merged convert: weights + activations + masks ==============
// Each thread emits ONE 16B store = 8 elements (half of a 16-element k-group),
// applying the inverse k-permutation on the read side (reads stay in one L2 line).
// Output pair j within a 16-elt group <- input pair p = 4*(j&1) + (j>>1).
// Grid: [0,3072) weights (512 blocks each of 6), [3072,4096) x_c,
//       [4096,8192) x_e, [8192,8202) masks.
__global__ __launch_bounds__(256) void cvt_all(
    const float* __restrict__ Wcq, const float* __restrict__ Wck,
    const float* __restrict__ Wcv, const float* __restrict__ Weq,
    const float* __restrict__ Wek, const float* __restrict__ Wev,
    const float* __restrict__ xc, const float* __restrict__ xe,
    const int* __restrict__ mc, const int* __restrict__ me,
    __half* __restrict__ dWc, __half* __restrict__ dWe,
    __half* __restrict__ dxc, __half* __restrict__ dxe,
    __half* __restrict__ dmc, __half* __restrict__ dme)
{
    int bid = blockIdx.x;
    if (bid >= 8192) {   // mask conversion: 10240 ints total, 4 per thread
        int idx = (bid - 8192) * 256 + threadIdx.x;
        int base = idx * 4;
        const int* src;
        __half* dst;
        if (base < B * SC) { src = mc + base; dst = dmc + base; }
        else { base -= B * SC; src = me + base; dst = dme + base; }
        int4 v = *(const int4*)src;
        uint2 o;
        o.x = packh2(v.x ? 1.f : 0.f, v.y ? 1.f : 0.f);
        o.y = packh2(v.z ? 1.f : 0.f, v.w ? 1.f : 0.f);
        *(uint2*)dst = o;
        return;
    }

    const float* s;
    __half* d;
    int i;
    if (bid < 3072) {
        int z = bid >> 9;                      // 512 blocks per weight
        const float* Ws[6] = {Wcq, Wck, Wcv, Weq, Wek, Wev};
        s = Ws[z];
        d = (z < 3) ? (dWc + ((size_t)z << 20)) : (dWe + ((size_t)(z - 3) << 20));
        i = (bid & 511) * 256 + threadIdx.x;   // [0, 131072)
    } else if (bid < 4096) {
        s = xc; d = dxc;
        i = (bid - 3072) * 256 + threadIdx.x;  // [0, 262144)
    } else {
        s = xe; d = dxe;
        i = (bid - 4096) * 256 + threadIdx.x;  // [0, 1048576)
    }
    // thread i produces output pairs 4i..4i+3 (one 16B store)
    int op = 4 * i;
    int grp = op >> 3;            // 16-element group
    int j0 = op & 7;              // 0 or 4
    const float2* sp = (const float2*)s + (size_t)grp * 8;
    uint4 o;
    {
        int p0 = 4 * ((j0 + 0) & 1) + ((j0 + 0) >> 1);
        int p1 = 4 * ((j0 + 1) & 1) + ((j0 + 1) >> 1);
        int p2 = 4 * ((j0 + 2) & 1) + ((j0 + 2) >> 1);
        int p3 = 4 * ((j0 + 3) & 1) + ((j0 + 3) >> 1);
        float2 v0 = sp[p0], v1 = sp[p1], v2 = sp[p2], v3 = sp[p3];
        o.x = packh2(v0.x, v0.y);
        o.y = packh2(v1.x, v1.y);
        o.z = packh2(v2.x, v2.y);
        o.w = packh2(v3.x, v3.y);
    }
    ((uint4*)d)[i] = o;
}

// ==================== GEMM: 128x128 tile, 128 thr, 2 CTA/SM, LDS.64 frags ========
#define G_RS    96
#define G_A     0
#define G_B     (128 * G_RS)          // 12288
#define G_STAGE (256 * G_RS)          // 24576
#define G_SMEM  (3 * G_STAGE)         // 73728

__global__ __launch_bounds__(128, 2) void gemm_f16(
    const __half* __restrict__ xeh, const __half* __restrict__ Weh,
    const __half* __restrict__ xch, const __half* __restrict__ Wch,
    const float* __restrict__ beq, const float* __restrict__ bek,
    const float* __restrict__ bev,
    const float* __restrict__ bcq, const float* __restrict__ bck,
    const float* __restrict__ bcv,
    float* __restrict__ Ce, float* __restrict__ Cc)
{
    const int z = blockIdx.z;
    const __half *Ah, *Wz;
    float* C;
    const float* bias;
    if (z < 3) {
        Ah = xeh;
        Wz = Weh + ((size_t)z << 20);
        C = Ce + (size_t)z * (B * SE) * HS;
        bias = (z == 0) ? beq : ((z == 1) ? bek : bev);
    } else {
        if (blockIdx.y >= (B * SC) / 128) return;
        int zz = z - 3;
        Ah = xch;
        Wz = Wch + ((size_t)zz << 20);
        C = Cc + (size_t)zz * (B * SC) * HS;
        bias = (zz == 0) ? bcq : ((zz == 1) ? bck : bcv);
    }

    extern __shared__ char smem[];
    const uint32_t sb = smem_u32(smem);
    const int tid = threadIdx.x;
    const int wid = tid >> 5;
    const int lane = tid & 31;
    const int g = lane >> 2;
    const int t = lane & 3;
    const int wm = wid >> 1;
    const int wn = wid & 1;
    const int bm = blockIdx.y * 128;
    const int bn = blockIdx.x * 128;

    const char* csrc[8];
    uint32_t cdst[8];
#pragma unroll
    for (int q = 0; q < 8; q++) {
        int f = q * 128 + tid;
        int tile = f >> 9;
        int idx = f & 511;
        int r = idx >> 2, c = idx & 3;
        cdst[q] = (uint32_t)(tile * G_B + r * G_RS + c * 16);
        if (tile == 0) csrc[q] = (const char*)(Ah + (size_t)(bm + r) * HS + c * 8);
        else           csrc[q] = (const char*)(Wz + (size_t)(bn + r) * HS + c * 8);
    }

    const int NC = HS / 32;

#pragma unroll
    for (int st = 0; st < 3; st++) {
        uint32_t db = sb + st * G_STAGE;
#pragma unroll
        for (int q = 0; q < 8; q++)
            cp16(db + cdst[q], csrc[q] + st * 64);
        asm volatile("cp.async.commit_group;");
    }

    float acc[4][8][4];
#pragma unroll
    for (int i = 0; i < 4; i++)
#pragma unroll
        for (int j = 0; j < 8; j++)
#pragma unroll
            for (int k = 0; k < 4; k++) acc[i][j][k] = 0.f;

    for (int c = 0; c < NC; c++) {
        asm volatile("cp.async.wait_group 2;");
        __syncthreads();

        const char* buf = smem + (c % 3) * G_STAGE;
#pragma unroll
        for (int s = 0; s < 2; s++) {
            const int kb = s * 32 + t * 8;
            uint32_t ah[4][4];
#pragma unroll
            for (int i = 0; i < 4; i++) {
                const char* pa = buf + G_A + (wm * 64 + 16 * i + g) * G_RS + kb;
                uint2 alo = *(const uint2*)(pa);
                uint2 ahi = *(const uint2*)(pa + 8 * G_RS);
                ah[i][0] = alo.x;
                ah[i][1] = ahi.x;
                ah[i][2] = alo.y;
                ah[i][3] = ahi.y;
            }
#pragma unroll
            for (int j = 0; j < 8; j++) {
                uint2 bv = *(const uint2*)(buf + G_B + (wn * 64 + 8 * j + g) * G_RS + kb);
#pragma unroll
                for (int i = 0; i < 4; i++)
                    mma_f16(acc[i][j], ah[i], (const uint32_t*)&bv);
            }
        }
        __syncthreads();

        if (c + 3 < NC) {
            uint32_t db = sb + ((c + 3) % 3) * G_STAGE;
            int koff = (c + 3) * 64;
#pragma unroll
            for (int q = 0; q < 8; q++)
                cp16(db + cdst[q], csrc[q] + koff);
        }
        asm volatile("cp.async.commit_group;");
    }

#pragma unroll
    for (int i = 0; i < 4; i++) {
        int row0 = bm + wm * 64 + 16 * i + g;
#pragma unroll
        for (int j = 0; j < 8; j++) {
            int col = bn + wn * 64 + 8 * j + 2 * t;
            float2 bv2 = *(const float2*)(bias + col);
            *(float2*)(C + (size_t)row0 * HS + col) =
                make_float2(acc[i][j][0] + bv2.x, acc[i][j][1] + bv2.y);
            *(float2*)(C + (size_t)(row0 + 8) * HS + col) =
                make_float2(acc[i][j][2] + bv2.x, acc[i][j][3] + bv2.y);
        }
    }
}

// ==================== K/V prep: fp32 -> fp16, k-dim permuted ====================
__global__ __launch_bounds__(256) void prep_all(
    const float* __restrict__ Kc, const float* __restrict__ Vc,
    __half* __restrict__ Kc16, __half* __restrict__ Vtc16,
    const float* __restrict__ Ke, const float* __restrict__ Ve,
    __half* __restrict__ Ke16, __half* __restrict__ Vte16)
{
    __shared__ float vs[64][65];
    const int tid = threadIdx.x;
    const int b = blockIdx.z, h = blockIdx.y;
    const int bh = b * NH + h;

    const float *K, *V;
    __half *Kh, *Vth;
    int Sk, s0;
    if (blockIdx.x < SC / 64) {
        K = Kc; V = Vc; Kh = Kc16; Vth = Vtc16; Sk = SC;
        s0 = blockIdx.x * 64;
    } else {
        K = Ke; V = Ve; Kh = Ke16; Vth = Vte16; Sk = SE;
        s0 = (blockIdx.x - SC / 64) * 64;
    }

#pragma unroll
    for (int i = 0; i < 4; i++) {
        int f = tid + 256 * i;
        int r = f >> 4, c4 = f & 15;
        float4 v = *(const float4*)(K + (size_t)(b * Sk + s0 + r) * HS + h * DH + c4 * 4);
        int c = c4 * 4;
        int n0 = kperm(c);
        size_t o = ((size_t)(bh * Sk + s0 + r)) * DH;
        *(uint32_t*)(Kh + o + n0) = packh2(v.x, v.y);
        *(uint32_t*)(Kh + o + n0 + 4) = packh2(v.z, v.w);
    }
#pragma unroll
    for (int i = 0; i < 4; i++) {
        int f = tid + 256 * i;
        int r = f >> 4, c4 = f & 15;
        float4 v = *(const float4*)(V + (size_t)(b * Sk + s0 + r) * HS + h * DH + c4 * 4);
        vs[r][c4 * 4 + 0] = v.x;
        vs[r][c4 * 4 + 1] = v.y;
        vs[r][c4 * 4 + 2] = v.z;
        vs[r][c4 * 4 + 3] = v.w;
    }
    __syncthreads();
#pragma unroll
    for (int i = 0; i < 8; i++) {
        int f = tid + 256 * i;
        int d = f >> 5, sp = f & 31;
        float v0 = vs[2 * sp][d], v1 = vs[2 * sp + 1][d];
        int np = kperm(2 * sp);
        size_t o = ((size_t)(bh * DH + d)) * Sk + s0 + np;
        *(uint32_t*)(Vth + o) = packh2(v0, v1);
    }
}

// ==================== attention: ones-column l-sum + fp16 mask multiply ==========
#define AK    0
#define AV    10240               // 72 rows x 160 (rows 64..71 = ones/zero pad)
#define AMS   21760               // 64 fp16 mask values (128B)
#define ABUF  22016
#define ASMEM (2 * ABUF)          // 44032
#define ARS   160

__global__ __launch_bounds__(128, 2) void attn_all(
    const float* __restrict__ Qc, const __half* __restrict__ Ke,
    const __half* __restrict__ Vte, const __half* __restrict__ me,
    float* __restrict__ Ac,
    const float* __restrict__ Qe, const __half* __restrict__ Kc,
    const __half* __restrict__ Vtc, const __half* __restrict__ mc,
    float* __restrict__ Ae)
{
    extern __shared__ char sm[];
    const uint32_t sb = smem_u32(sm);
    const int tid = threadIdx.x;
    const int wid = tid >> 5;
    const int lane = tid & 31;
    const int g = lane >> 2;
    const int t = lane & 3;
    const int b = blockIdx.z, h = blockIdx.y;
    const int bx = blockIdx.x;
    const int bh = b * NH + h;

    const float* Q;
    const __half* K;
    const __half* Vt;
    const __half* mask;
    float* O;
    int Sq, Sk, q0;
    if (bx < SC / 128) {
        Q = Qc; K = Ke; Vt = Vte; mask = me; O = Ac;
        Sq = SC; Sk = SE; q0 = bx * 128;
    } else {
        Q = Qe; K = Kc; Vt = Vtc; mask = mc; O = Ae;
        Sq = SE; Sk = SC; q0 = (bx - SC / 128) * 128;
    }
    const int nt = Sk / 64;

    const char* csrc[8];
    uint32_t cdst[8];
#pragma unroll
    for (int q = 0; q < 8; q++) {
        int f = q * 128 + tid;
        int tile = f >> 9;
        int idx = f & 511;
        int r = idx >> 3, c = idx & 7;
        if (tile == 0) {
            csrc[q] = (const char*)(K + (size_t)(bh * (size_t)Sk + r) * DH + c * 8);
            cdst[q] = AK + (uint32_t)(r * ARS + c * 16);
        } else {
            csrc[q] = (const char*)(Vt + (size_t)(bh * DH + r) * (size_t)Sk + c * 8);
            cdst[q] = AV + (uint32_t)(r * ARS + c * 16);
        }
    }
    const char* msrc = (const char*)(mask + (size_t)b * Sk) + tid * 16;

    {
#pragma unroll
        for (int q = 0; q < 8; q++)
            cp16(sb + cdst[q], csrc[q]);
        if (tid < 8) cp16(sb + AMS + tid * 16, msrc);
        asm volatile("cp.async.commit_group;");
    }

    // init ones/zero pad rows 64..71 of both V buffers (128B per row used)
    {
        int row = 64 + (tid >> 4);
        int off = (tid & 15) * 8;
        uint2 val = (row == 64) ? make_uint2(0x3C003C00u, 0x3C003C00u)
                                : make_uint2(0u, 0u);
        *(uint2*)(sm + AV + row * ARS + off) = val;
        *(uint2*)(sm + ABUF + AV + row * ARS + off) = val;
    }

    if (nt > 1) {
#pragma unroll
        for (int q = 0; q < 8; q++)
            cp16(sb + ABUF + cdst[q], csrc[q] + ((q < 4) ? 8192 : 128));
        if (tid < 8) cp16(sb + ABUF + AMS + tid * 16, msrc + 128);
    }
    asm volatile("cp.async.commit_group;");

    // Q fragments (2 m16 tiles per warp), pre-scaled by CSC
    uint32_t qh[2][4][4];
#pragma unroll
    for (int i = 0; i < 2; i++) {
        const float* qp0 = Q + (size_t)(b * Sq + q0 + wid * 32 + 16 * i + g) * HS + h * DH;
        const float* qp8 = qp0 + 8 * HS;
#pragma unroll
        for (int kk = 0; kk < 4; kk++) {
            int c0 = 16 * kk + 2 * t;
            float2 x0 = *(const float2*)(qp0 + c0);
            float2 x1 = *(const float2*)(qp8 + c0);
            float2 x2 = *(const float2*)(qp0 + c0 + 8);
            float2 x3 = *(const float2*)(qp8 + c0 + 8);
            qh[i][kk][0] = packh2(x0.x * CSC, x0.y * CSC);
            qh[i][kk][1] = packh2(x1.x * CSC, x1.y * CSC);
            qh[i][kk][2] = packh2(x2.x * CSC, x2.y * CSC);
            qh[i][kk][3] = packh2(x3.x * CSC, x3.y * CSC);
        }
    }

    // oacc has 9 n-tiles: j=8 is the ones column (l accumulator)
    float oacc[2][9][4];
#pragma unroll
    for (int i = 0; i < 2; i++)
#pragma unroll
        for (int j = 0; j < 9; j++)
#pragma unroll
            for (int k = 0; k < 4; k++) oacc[i][j][k] = 0.f;

    for (int it = 0; it < nt; it++) {
        if (it + 1 < nt) { asm volatile("cp.async.wait_group 1;"); }
        else             { asm volatile("cp.async.wait_group 0;"); }
        __syncthreads();

        char* buf = sm + (it & 1) * ABUF;

        // ---- S = Q @ K^T ----
        float sacc[2][8][4];
#pragma unroll
        for (int i = 0; i < 2; i++)
#pragma unroll
            for (int j = 0; j < 8; j++)
#pragma unroll
                for (int k = 0; k < 4; k++) sacc[i][j][k] = 0.f;

#pragma unroll
        for (int kk = 0; kk < 4; kk++) {
#pragma unroll
            for (int j = 0; j < 8; j++) {
                uint2 kv = *(const uint2*)(buf + AK + (8 * j + g) * ARS + kk * 32 + t * 8);
                mma_f16(sacc[0][j], qh[0][kk], (const uint32_t*)&kv);
                mma_f16(sacc[1][j], qh[1][kk], (const uint32_t*)&kv);
            }
        }

        // ---- p = ex2(s) ----
#pragma unroll
        for (int i = 0; i < 2; i++)
#pragma unroll
            for (int j = 0; j < 8; j++) {
                sacc[i][j][0] = ex2(sacc[i][j][0]);
                sacc[i][j][1] = ex2(sacc[i][j][1]);
                sacc[i][j][2] = ex2(sacc[i][j][2]);
                sacc[i][j][3] = ex2(sacc[i][j][3]);
            }

        // ---- pack P, apply fp16 mask multiply ----
        uint32_t ph[2][4][4];
#pragma unroll
        for (int s = 0; s < 4; s++) {
            uint32_t m0 = *(const uint32_t*)(buf + AMS + s * 32 + t * 4);
            uint32_t m1 = *(const uint32_t*)(buf + AMS + s * 32 + t * 4 + 16);
#pragma unroll
            for (int i = 0; i < 2; i++) {
                const float* pa = sacc[i][2 * s];
                const float* pb = sacc[i][2 * s + 1];
                ph[i][s][0] = hmul2u(packh2(pa[0], pa[1]), m0);
                ph[i][s][1] = hmul2u(packh2(pa[2], pa[3]), m0);
                ph[i][s][2] = hmul2u(packh2(pb[0], pb[1]), m1);
                ph[i][s][3] = hmul2u(packh2(pb[2], pb[3]), m1);
            }
        }

        // ---- O += P @ V  (9th n-tile = ones column -> l) ----
#pragma unroll
        for (int s = 0; s < 4; s++) {
#pragma unroll
            for (int j = 0; j < 9; j++) {
                uint2 vv = *(const uint2*)(buf + AV + (8 * j + g) * ARS + s * 32 + t * 8);
                mma_f16(oacc[0][j], ph[0][s], (const uint32_t*)&vv);
                mma_f16(oacc[1][j], ph[1][s], (const uint32_t*)&vv);
            }
        }

        __syncthreads();
        if (it + 2 < nt) {
            size_t kaK = (size_t)(it + 2) * 8192;
            size_t kaV = (size_t)(it + 2) * 128;
            uint32_t db = sb + (it & 1) * ABUF;
#pragma unroll
            for (int q = 0; q < 8; q++)
                cp16(db + cdst[q], csrc[q] + ((q < 4) ? kaK : kaV));
            if (tid < 8) cp16(db + AMS + tid * 16, msrc + (size_t)(it + 2) * 128);
        }
        asm volatile("cp.async.commit_group;");
    }

    // l lives in oacc[i][8][0]/[2] of the t=0 lane of each quad; broadcast + write
#pragma unroll
    for (int i = 0; i < 2; i++) {
        float l0 = __shfl_sync(0xffffffffu, oacc[i][8][0], lane & ~3);
        float l1 = __shfl_sync(0xffffffffu, oacc[i][8][2], lane & ~3);
        float inv0 = 1.f / l0;
        float inv1 = 1.f / l1;
        int row0 = q0 + wid * 32 + 16 * i + g;
#pragma unroll
        for (int j = 0; j < 8; j++) {
            int col = h * DH + 8 * j + 2 * t;
            *(float2*)(O + (size_t)(b * Sq + row0) * HS + col) =
                make_float2(oacc[i][j][0] * inv0, oacc[i][j][1] * inv0);
            *(float2*)(O + (size_t)(b * Sq + row0 + 8) * HS + col) =
                make_float2(oacc[i][j][2] * inv1, oacc[i][j][3] * inv1);
        }
    }
}

// ==================== fused residual add + LayerNorm (merged) ====================
__global__ __launch_bounds__(256) void add_ln_all(
    const float* __restrict__ xc, const float* __restrict__ Ac,
    const float* __restrict__ xe, const float* __restrict__ Ae,
    const float* __restrict__ g, const float* __restrict__ bb,
    float* __restrict__ out)
{
    int row = blockIdx.x;
    const float *x, *att;
    if (row < B * SC) { x = xc + (size_t)row * HS; att = Ac + (size_t)row * HS; }
    else {
        int r = row - B * SC;
        x = xe + (size_t)r * HS; att = Ae + (size_t)r * HS;
    }
    int tid = threadIdx.x;
    float4 xv = ((const float4*)x)[tid];
    float4 av = ((const float4*)att)[tid];
    float v0 = xv.x + av.x, v1 = xv.y + av.y, v2 = xv.z + av.z, v3 = xv.w + av.w;

    float s = v0 + v1 + v2 + v3;
    float sq = v0 * v0 + v1 * v1 + v2 * v2 + v3 * v3;
#pragma unroll
    for (int off = 16; off > 0; off >>= 1) {
        s  += __shfl_xor_sync(0xffffffffu, s, off);
        sq += __shfl_xor_sync(0xffffffffu, sq, off);
    }
    __shared__ float ss[8], ssq[8];
    int wid = tid >> 5, lane = tid & 31;
    if (lane == 0) { ss[wid] = s; ssq[wid] = sq; }
    __syncthreads();
    s = 0.f; sq = 0.f;
#pragma unroll
    for (int w = 0; w < 8; w++) { s += ss[w]; sq += ssq[w]; }

    float mu = s * (1.f / HS);
    float var = sq * (1.f / HS) - mu * mu;
    float r = rsqrtf(var + 1e-5f);

    float4 gv = ((const float4*)g)[tid];
    float4 bv = ((const float4*)bb)[tid];
    float4 ov = make_float4((v0 - mu) * r * gv.x + bv.x,
                            (v1 - mu) * r * gv.y + bv.y,
                            (v2 - mu) * r * gv.z + bv.z,
                            (v3 - mu) * r * gv.w + bv.w);
    ((float4*)(out + (size_t)row * HS))[tid] = ov;
}

// ==================== launcher ====================
extern "C" void kernel_launch(void* const* d_in, const int* in_sizes, int n_in,
                              void* d_out, int out_size)
{
    (void)in_sizes; (void)n_in; (void)out_size;
    const float* x_c   = (const float*)d_in[0];
    const float* x_e   = (const float*)d_in[1];
    const int*   msk_c = (const int*)d_in[2];
    const int*   msk_e = (const int*)d_in[3];
    const float* W_cq = (const float*)d_in[4];  const float* b_cq = (const float*)d_in[5];
    const float* W_ek = (const float*)d_in[6];  const float* b_ek = (const float*)d_in[7];
    const float* W_ev = (const float*)d_in[8];  const float* b_ev = (const float*)d_in[9];
    const float* W_eq = (const float*)d_in[10]; const float* b_eq = (const float*)d_in[11];
    const float* W_ck = (const float*)d_in[12]; const float* b_ck = (const float*)d_in[13];
    const float* W_cv = (const float*)d_in[14]; const float* b_cv = (const float*)d_in[15];
    const float* ln_g = (const float*)d_in[16]; const float* ln_b = (const float*)d_in[17];
    float* out = (float*)d_out;

    float *QKVc, *QKVe, *Ac, *Ae;
    cudaGetSymbolAddress((void**)&QKVc, g_QKVc);
    cudaGetSymbolAddress((void**)&QKVe, g_QKVe);
    cudaGetSymbolAddress((void**)&Ac, g_Ac);
    cudaGetSymbolAddress((void**)&Ae, g_Ae);
    __half *xch, *xeh, *Wch, *Weh, *mhc, *mhe;
    cudaGetSymbolAddress((void**)&xch, g_xch);
    cudaGetSymbolAddress((void**)&xeh, g_xeh);
    cudaGetSymbolAddress((void**)&Wch, g_Wch);
    cudaGetSymbolAddress((void**)&Weh, g_Weh);
    cudaGetSymbolAddress((void**)&mhc, g_mhc);
    cudaGetSymbolAddress((void**)&mhe, g_mhe);
    __half *Ke16, *Vte16, *Kc16, *Vtc16;
    cudaGetSymbolAddress((void**)&Ke16, g_Ke16);
    cudaGetSymbolAddress((void**)&Vte16, g_Vte16);
    cudaGetSymbolAddress((void**)&Kc16, g_Kc16);
    cudaGetSymbolAddress((void**)&Vtc16, g_Vtc16);

    cudaFuncSetAttribute(gemm_f16, cudaFuncAttributeMaxDynamicSharedMemorySize, G_SMEM);
    cudaFuncSetAttribute(attn_all, cudaFuncAttributeMaxDynamicSharedMemorySize, ASMEM);

    const int Mc = B * SC;   // 2048
    const int Me = B * SE;   // 8192

    // converts: weights (3072 blocks), x_c (1024), x_e (4096), masks (10)
    cvt_all<<<8192 + 10, 256>>>(W_cq, W_ck, W_cv, W_eq, W_ek, W_ev, x_c, x_e,
                                msk_c, msk_e, Wch, Weh, xch, xeh, mhc, mhe);

    gemm_f16<<<dim3(8, Me / 128, 6), 128, G_SMEM>>>(
        xeh, Weh, xch, Wch,
        b_eq, b_ek, b_ev, b_cq, b_ck, b_cv,
        QKVe, QKVc);

    float* Qc = QKVc;
    float* Kc = QKVc + (size_t)Mc * HS;
    float* Vc = QKVc + (size_t)2 * Mc * HS;
    float* Qe = QKVe;
    float* Ke = QKVe + (size_t)Me * HS;
    float* Ve = QKVe + (size_t)2 * Me * HS;

    prep_all<<<dim3(SC / 64 + SE / 64, NH, B), 256>>>(
        Kc, Vc, Kc16, Vtc16, Ke, Ve, Ke16, Vte16);

    attn_all<<<dim3(SC / 128 + SE / 128, NH, B), 128, ASMEM>>>(
        Qc, Ke16, Vte16, mhe, Ac,
        Qe, Kc16, Vtc16, mhc, Ae);

    add_ln_all<<<Mc + Me, 256>>>(x_c, Ac, x_e, Ae, ln_g, ln_b, out);
}

// round 13
// speedup vs baseline: 1.1702x; 1.0618x over previous
#include <cuda_runtime.h>
#include <cuda_fp16.h>
#include <cstdint>

#define HS 1024
#define NH 16
#define DH 64
#define B 4
#define SC 512
#define SE 2048

// -------------------- scratch (device globals; no allocation) --------------------
__device__ float g_QKVc[(size_t)3 * B * SC * HS];   // Qc | Kc | Vc
__device__ float g_QKVe[(size_t)3 * B * SE * HS];   // Qe | Ke | Ve
__device__ float g_Ac[(size_t)B * SC * HS];
__device__ float g_Ae[(size_t)B * SE * HS];
// fp16 preconverted GEMM operands (k-dim permuted within 16-groups)
__device__ __align__(256) __half g_xch[(size_t)B * SC * HS];
__device__ __align__(256) __half g_xeh[(size_t)B * SE * HS];
__device__ __align__(256) __half g_Wch[(size_t)3 * HS * HS];   // W_cq|W_ck|W_cv
__device__ __align__(256) __half g_Weh[(size_t)3 * HS * HS];   // W_eq|W_ek|W_ev
// fp16 K (d-permuted) / V-transposed (seq-permuted) per head
__device__ __align__(256) __half g_Ke16[(size_t)B * NH * SE * DH];
__device__ __align__(256) __half g_Vte16[(size_t)B * NH * SE * DH];
__device__ __align__(256) __half g_Kc16[(size_t)B * NH * SC * DH];
__device__ __align__(256) __half g_Vtc16[(size_t)B * NH * SC * DH];
// fp16 masks (0.0 / 1.0)
__device__ __align__(256) __half g_mhc[(size_t)B * SC];
__device__ __align__(256) __half g_mhe[(size_t)B * SE];

// ==================== helpers ====================
__device__ __forceinline__ void mma_f16(float* d, const uint32_t* a, const uint32_t* b) {
    asm volatile(
        "mma.sync.aligned.m16n8k16.row.col.f32.f16.f16.f32 "
        "{%0,%1,%2,%3}, {%4,%5,%6,%7}, {%8,%9}, {%0,%1,%2,%3};"
        : "+f"(d[0]), "+f"(d[1]), "+f"(d[2]), "+f"(d[3])
        : "r"(a[0]), "r"(a[1]), "r"(a[2]), "r"(a[3]), "r"(b[0]), "r"(b[1]));
}

// fp16-accumulator MMA: d/c are 2 packed regs (row g: {c0,c1}, row g+8: {c2,c3})
__device__ __forceinline__ void mma_f16acc(uint32_t* d, const uint32_t* a, const uint32_t* b) {
    asm volatile(
        "mma.sync.aligned.m16n8k16.row.col.f16.f16.f16.f16 "
        "{%0,%1}, {%2,%3,%4,%5}, {%6,%7}, {%0,%1};"
        : "+r"(d[0]), "+r"(d[1])
        : "r"(a[0]), "r"(a[1]), "r"(a[2]), "r"(a[3]), "r"(b[0]), "r"(b[1]));
}

__device__ __forceinline__ uint32_t packh2(float a, float b) {
    __half2 h = __floats2half2_rn(a, b);
    return *(uint32_t*)&h;
}

__device__ __forceinline__ uint32_t hmul2u(uint32_t a, uint32_t b) {
    __half2 r = __hmul2(*(__half2*)&a, *(__half2*)&b);
    return *(uint32_t*)&r;
}

__device__ __forceinline__ uint32_t smem_u32(const void* p) {
    uint32_t a;
    asm("{ .reg .u64 t; cvta.to.shared.u64 t, %1; cvt.u32.u64 %0, t; }" : "=r"(a) : "l"(p));
    return a;
}

__device__ __forceinline__ void cp16(uint32_t dst, const void* src) {
    asm volatile("cp.async.cg.shared.global [%0], [%1], 16;" :: "r"(dst), "l"(src));
}

// hardware exp2 (MUFU.EX2)
__device__ __forceinline__ float ex2(float x) {
    float r;
    asm("ex2.approx.f32 %0, %1;" : "=f"(r) : "f"(x));
    return r;
}

// k-dim pair permutation (within 16-element groups) used by prep_all (K,V paths)
__device__ __forceinline__ int kperm(int c) {
    return (c >> 4) * 16 + (((c & 7) >> 1) << 2) + (((c >> 3) & 1) << 1);
}

#define CSC 0.1803368801111694f   // log2(e)/8

// ==================== merged convert: weights + activations + masks ==============
__global__ __launch_bounds__(256) void cvt_all(
    const float* __restrict__ Wcq, const float* __restrict__ Wck,
    const float* __restrict__ Wcv, const float* __restrict__ Weq,
    const float* __restrict__ Wek, const float* __restrict__ Wev,
    const float* __restrict__ xc, const float* __restrict__ xe,
    const int* __restrict__ mc, const int* __restrict__ me,
    __half* __restrict__ dWc, __half* __restrict__ dWe,
    __half* __restrict__ dxc, __half* __restrict__ dxe,
    __half* __restrict__ dmc, __half* __restrict__ dme)
{
    int bid = blockIdx.x;
    if (bid >= 8192) {   // mask conversion: 10240 ints total, 4 per thread
        int idx = (bid - 8192) * 256 + threadIdx.x;
        int base = idx * 4;
        const int* src;
        __half* dst;
        if (base < B * SC) { src = mc + base; dst = dmc + base; }
        else { base -= B * SC; src = me + base; dst = dme + base; }
        int4 v = *(const int4*)src;
        uint2 o;
        o.x = packh2(v.x ? 1.f : 0.f, v.y ? 1.f : 0.f);
        o.y = packh2(v.z ? 1.f : 0.f, v.w ? 1.f : 0.f);
        *(uint2*)dst = o;
        return;
    }

    const float* s;
    __half* d;
    int i;
    if (bid < 3072) {
        int z = bid >> 9;
        const float* Ws[6] = {Wcq, Wck, Wcv, Weq, Wek, Wev};
        s = Ws[z];
        d = (z < 3) ? (dWc + ((size_t)z << 20)) : (dWe + ((size_t)(z - 3) << 20));
        i = (bid & 511) * 256 + threadIdx.x;
    } else if (bid < 4096) {
        s = xc; d = dxc;
        i = (bid - 3072) * 256 + threadIdx.x;
    } else {
        s = xe; d = dxe;
        i = (bid - 4096) * 256 + threadIdx.x;
    }
    int op = 4 * i;
    int grp = op >> 3;
    int j0 = op & 7;
    const float2* sp = (const float2*)s + (size_t)grp * 8;
    uint4 o;
    {
        int p0 = 4 * ((j0 + 0) & 1) + ((j0 + 0) >> 1);
        int p1 = 4 * ((j0 + 1) & 1) + ((j0 + 1) >> 1);
        int p2 = 4 * ((j0 + 2) & 1) + ((j0 + 2) >> 1);
        int p3 = 4 * ((j0 + 3) & 1) + ((j0 + 3) >> 1);
        float2 v0 = sp[p0], v1 = sp[p1], v2 = sp[p2], v3 = sp[p3];
        o.x = packh2(v0.x, v0.y);
        o.y = packh2(v1.x, v1.y);
        o.z = packh2(v2.x, v2.y);
        o.w = packh2(v3.x, v3.y);
    }
    ((uint4*)d)[i] = o;
}

// ==================== GEMM: fp16 accumulators, 3 CTA/SM, LDS.64 frags ============
#define G_RS    96
#define G_A     0
#define G_B     (128 * G_RS)          // 12288
#define G_STAGE (256 * G_RS)          // 24576
#define G_SMEM  (3 * G_STAGE)         // 73728

__global__ __launch_bounds__(128, 3) void gemm_f16(
    const __half* __restrict__ xeh, const __half* __restrict__ Weh,
    const __half* __restrict__ xch, const __half* __restrict__ Wch,
    const float* __restrict__ beq, const float* __restrict__ bek,
    const float* __restrict__ bev,
    const float* __restrict__ bcq, const float* __restrict__ bck,
    const float* __restrict__ bcv,
    float* __restrict__ Ce, float* __restrict__ Cc)
{
    const int z = blockIdx.z;
    const __half *Ah, *Wz;
    float* C;
    const float* bias;
    if (z < 3) {
        Ah = xeh;
        Wz = Weh + ((size_t)z << 20);
        C = Ce + (size_t)z * (B * SE) * HS;
        bias = (z == 0) ? beq : ((z == 1) ? bek : bev);
    } else {
        if (blockIdx.y >= (B * SC) / 128) return;
        int zz = z - 3;
        Ah = xch;
        Wz = Wch + ((size_t)zz << 20);
        C = Cc + (size_t)zz * (B * SC) * HS;
        bias = (zz == 0) ? bcq : ((zz == 1) ? bck : bcv);
    }

    extern __shared__ char smem[];
    const uint32_t sb = smem_u32(smem);
    const int tid = threadIdx.x;
    const int wid = tid >> 5;
    const int lane = tid & 31;
    const int g = lane >> 2;
    const int t = lane & 3;
    const int wm = wid >> 1;
    const int wn = wid & 1;
    const int bm = blockIdx.y * 128;
    const int bn = blockIdx.x * 128;

    const char* csrc[8];
    uint32_t cdst[8];
#pragma unroll
    for (int q = 0; q < 8; q++) {
        int f = q * 128 + tid;
        int tile = f >> 9;
        int idx = f & 511;
        int r = idx >> 2, c = idx & 3;
        cdst[q] = (uint32_t)(tile * G_B + r * G_RS + c * 16);
        if (tile == 0) csrc[q] = (const char*)(Ah + (size_t)(bm + r) * HS + c * 8);
        else           csrc[q] = (const char*)(Wz + (size_t)(bn + r) * HS + c * 8);
    }

    const int NC = HS / 32;

#pragma unroll
    for (int st = 0; st < 3; st++) {
        uint32_t db = sb + st * G_STAGE;
#pragma unroll
        for (int q = 0; q < 8; q++)
            cp16(db + cdst[q], csrc[q] + st * 64);
        asm volatile("cp.async.commit_group;");
    }

    // fp16 accumulators: acc[i][j] = {rowg_pack, rowg8_pack}
    uint32_t acc[4][8][2];
#pragma unroll
    for (int i = 0; i < 4; i++)
#pragma unroll
        for (int j = 0; j < 8; j++) {
            acc[i][j][0] = 0u;
            acc[i][j][1] = 0u;
        }

    for (int c = 0; c < NC; c++) {
        asm volatile("cp.async.wait_group 2;");
        __syncthreads();

        const char* buf = smem + (c % 3) * G_STAGE;
#pragma unroll
        for (int s = 0; s < 2; s++) {
            const int kb = s * 32 + t * 8;
            uint32_t ah[4][4];
#pragma unroll
            for (int i = 0; i < 4; i++) {
                const char* pa = buf + G_A + (wm * 64 + 16 * i + g) * G_RS + kb;
                uint2 alo = *(const uint2*)(pa);
                uint2 ahi = *(const uint2*)(pa + 8 * G_RS);
                ah[i][0] = alo.x;
                ah[i][1] = ahi.x;
                ah[i][2] = alo.y;
                ah[i][3] = ahi.y;
            }
#pragma unroll
            for (int j = 0; j < 8; j++) {
                uint2 bv = *(const uint2*)(buf + G_B + (wn * 64 + 8 * j + g) * G_RS + kb);
#pragma unroll
                for (int i = 0; i < 4; i++)
                    mma_f16acc(acc[i][j], ah[i], (const uint32_t*)&bv);
            }
        }
        __syncthreads();

        if (c + 3 < NC) {
            uint32_t db = sb + ((c + 3) % 3) * G_STAGE;
            int koff = (c + 3) * 64;
#pragma unroll
            for (int q = 0; q < 8; q++)
                cp16(db + cdst[q], csrc[q] + koff);
        }
        asm volatile("cp.async.commit_group;");
    }

    // epilogue: unpack fp16 acc -> fp32 + bias
#pragma unroll
    for (int i = 0; i < 4; i++) {
        int row0 = bm + wm * 64 + 16 * i + g;
#pragma unroll
        for (int j = 0; j < 8; j++) {
            int col = bn + wn * 64 + 8 * j + 2 * t;
            float2 bv2 = *(const float2*)(bias + col);
            float2 lo = __half22float2(*(__half2*)&acc[i][j][0]);
            float2 hi = __half22float2(*(__half2*)&acc[i][j][1]);
            *(float2*)(C + (size_t)row0 * HS + col) =
                make_float2(lo.x + bv2.x, lo.y + bv2.y);
            *(float2*)(C + (size_t)(row0 + 8) * HS + col) =
                make_float2(hi.x + bv2.x, hi.y + bv2.y);
        }
    }
}

// ==================== K/V prep: fp32 -> fp16, k-dim permuted ====================
__global__ __launch_bounds__(256) void prep_all(
    const float* __restrict__ Kc, const float* __restrict__ Vc,
    __half* __restrict__ Kc16, __half* __restrict__ Vtc16,
    const float* __restrict__ Ke, const float* __restrict__ Ve,
    __half* __restrict__ Ke16, __half* __restrict__ Vte16)
{
    __shared__ float vs[64][65];
    const int tid = threadIdx.x;
    const int b = blockIdx.z, h = blockIdx.y;
    const int bh = b * NH + h;

    const float *K, *V;
    __half *Kh, *Vth;
    int Sk, s0;
    if (blockIdx.x < SC / 64) {
        K = Kc; V = Vc; Kh = Kc16; Vth = Vtc16; Sk = SC;
        s0 = blockIdx.x * 64;
    } else {
        K = Ke; V = Ve; Kh = Ke16; Vth = Vte16; Sk = SE;
        s0 = (blockIdx.x - SC / 64) * 64;
    }

#pragma unroll
    for (int i = 0; i < 4; i++) {
        int f = tid + 256 * i;
        int r = f >> 4, c4 = f & 15;
        float4 v = *(const float4*)(K + (size_t)(b * Sk + s0 + r) * HS + h * DH + c4 * 4);
        int c = c4 * 4;
        int n0 = kperm(c);
        size_t o = ((size_t)(bh * Sk + s0 + r)) * DH;
        *(uint32_t*)(Kh + o + n0) = packh2(v.x, v.y);
        *(uint32_t*)(Kh + o + n0 + 4) = packh2(v.z, v.w);
    }
#pragma unroll
    for (int i = 0; i < 4; i++) {
        int f = tid + 256 * i;
        int r = f >> 4, c4 = f & 15;
        float4 v = *(const float4*)(V + (size_t)(b * Sk + s0 + r) * HS + h * DH + c4 * 4);
        vs[r][c4 * 4 + 0] = v.x;
        vs[r][c4 * 4 + 1] = v.y;
        vs[r][c4 * 4 + 2] = v.z;
        vs[r][c4 * 4 + 3] = v.w;
    }
    __syncthreads();
#pragma unroll
    for (int i = 0; i < 8; i++) {
        int f = tid + 256 * i;
        int d = f >> 5, sp = f & 31;
        float v0 = vs[2 * sp][d], v1 = vs[2 * sp + 1][d];
        int np = kperm(2 * sp);
        size_t o = ((size_t)(bh * DH + d)) * Sk + s0 + np;
        *(uint32_t*)(Vth + o) = packh2(v0, v1);
    }
}

// ==================== attention: ones-column l-sum + fp16 mask multiply ==========
#define AK    0
#define AV    10240               // 72 rows x 160 (rows 64..71 = ones/zero pad)
#define AMS   21760               // 64 fp16 mask values (128B)
#define ABUF  22016
#define ASMEM (2 * ABUF)          // 44032
#define ARS   160

__global__ __launch_bounds__(128, 2) void attn_all(
    const float* __restrict__ Qc, const __half* __restrict__ Ke,
    const __half* __restrict__ Vte, const __half* __restrict__ me,
    float* __restrict__ Ac,
    const float* __restrict__ Qe, const __half* __restrict__ Kc,
    const __half* __restrict__ Vtc, const __half* __restrict__ mc,
    float* __restrict__ Ae)
{
    extern __shared__ char sm[];
    const uint32_t sb = smem_u32(sm);
    const int tid = threadIdx.x;
    const int wid = tid >> 5;
    const int lane = tid & 31;
    const int g = lane >> 2;
    const int t = lane & 3;
    const int b = blockIdx.z, h = blockIdx.y;
    const int bx = blockIdx.x;
    const int bh = b * NH + h;

    const float* Q;
    const __half* K;
    const __half* Vt;
    const __half* mask;
    float* O;
    int Sq, Sk, q0;
    if (bx < SC / 128) {
        Q = Qc; K = Ke; Vt = Vte; mask = me; O = Ac;
        Sq = SC; Sk = SE; q0 = bx * 128;
    } else {
        Q = Qe; K = Kc; Vt = Vtc; mask = mc; O = Ae;
        Sq = SE; Sk = SC; q0 = (bx - SC / 128) * 128;
    }
    const int nt = Sk / 64;

    const char* csrc[8];
    uint32_t cdst[8];
#pragma unroll
    for (int q = 0; q < 8; q++) {
        int f = q * 128 + tid;
        int tile = f >> 9;
        int idx = f & 511;
        int r = idx >> 3, c = idx & 7;
        if (tile == 0) {
            csrc[q] = (const char*)(K + (size_t)(bh * (size_t)Sk + r) * DH + c * 8);
            cdst[q] = AK + (uint32_t)(r * ARS + c * 16);
        } else {
            csrc[q] = (const char*)(Vt + (size_t)(bh * DH + r) * (size_t)Sk + c * 8);
            cdst[q] = AV + (uint32_t)(r * ARS + c * 16);
        }
    }
    const char* msrc = (const char*)(mask + (size_t)b * Sk) + tid * 16;

    {
#pragma unroll
        for (int q = 0; q < 8; q++)
            cp16(sb + cdst[q], csrc[q]);
        if (tid < 8) cp16(sb + AMS + tid * 16, msrc);
        asm volatile("cp.async.commit_group;");
    }

    // init ones/zero pad rows 64..71 of both V buffers (128B per row used)
    {
        int row = 64 + (tid >> 4);
        int off = (tid & 15) * 8;
        uint2 val = (row == 64) ? make_uint2(0x3C003C00u, 0x3C003C00u)
                                : make_uint2(0u, 0u);
        *(uint2*)(sm + AV + row * ARS + off) = val;
        *(uint2*)(sm + ABUF + AV + row * ARS + off) = val;
    }

    if (nt > 1) {
#pragma unroll
        for (int q = 0; q < 8; q++)
            cp16(sb + ABUF + cdst[q], csrc[q] + ((q < 4) ? 8192 : 128));
        if (tid < 8) cp16(sb + ABUF + AMS + tid * 16, msrc + 128);
    }
    asm volatile("cp.async.commit_group;");

    // Q fragments (2 m16 tiles per warp), pre-scaled by CSC
    uint32_t qh[2][4][4];
#pragma unroll
    for (int i = 0; i < 2; i++) {
        const float* qp0 = Q + (size_t)(b * Sq + q0 + wid * 32 + 16 * i + g) * HS + h * DH;
        const float* qp8 = qp0 + 8 * HS;
#pragma unroll
        for (int kk = 0; kk < 4; kk++) {
            int c0 = 16 * kk + 2 * t;
            float2 x0 = *(const float2*)(qp0 + c0);
            float2 x1 = *(const float2*)(qp8 + c0);
            float2 x2 = *(const float2*)(qp0 + c0 + 8);
            float2 x3 = *(const float2*)(qp8 + c0 + 8);
            qh[i][kk][0] = packh2(x0.x * CSC, x0.y * CSC);
            qh[i][kk][1] = packh2(x1.x * CSC, x1.y * CSC);
            qh[i][kk][2] = packh2(x2.x * CSC, x2.y * CSC);
            qh[i][kk][3] = packh2(x3.x * CSC, x3.y * CSC);
        }
    }

    // oacc has 9 n-tiles: j=8 is the ones column (l accumulator)
    float oacc[2][9][4];
#pragma unroll
    for (int i = 0; i < 2; i++)
#pragma unroll
        for (int j = 0; j < 9; j++)
#pragma unroll
            for (int k = 0; k < 4; k++) oacc[i][j][k] = 0.f;

    for (int it = 0; it < nt; it++) {
        if (it + 1 < nt) { asm volatile("cp.async.wait_group 1;"); }
        else             { asm volatile("cp.async.wait_group 0;"); }
        __syncthreads();

        char* buf = sm + (it & 1) * ABUF;

        // ---- S = Q @ K^T ----
        float sacc[2][8][4];
#pragma unroll
        for (int i = 0; i < 2; i++)
#pragma unroll
            for (int j = 0; j < 8; j++)
#pragma unroll
                for (int k = 0; k < 4; k++) sacc[i][j][k] = 0.f;

#pragma unroll
        for (int kk = 0; kk < 4; kk++) {
#pragma unroll
            for (int j = 0; j < 8; j++) {
                uint2 kv = *(const uint2*)(buf + AK + (8 * j + g) * ARS + kk * 32 + t * 8);
                mma_f16(sacc[0][j], qh[0][kk], (const uint32_t*)&kv);
                mma_f16(sacc[1][j], qh[1][kk], (const uint32_t*)&kv);
            }
        }

        // ---- p = ex2(s) ----
#pragma unroll
        for (int i = 0; i < 2; i++)
#pragma unroll
            for (int j = 0; j < 8; j++) {
                sacc[i][j][0] = ex2(sacc[i][j][0]);
                sacc[i][j][1] = ex2(sacc[i][j][1]);
                sacc[i][j][2] = ex2(sacc[i][j][2]);
                sacc[i][j][3] = ex2(sacc[i][j][3]);
            }

        // ---- pack P, apply fp16 mask multiply ----
        uint32_t ph[2][4][4];
#pragma unroll
        for (int s = 0; s < 4; s++) {
            uint32_t m0 = *(const uint32_t*)(buf + AMS + s * 32 + t * 4);
            uint32_t m1 = *(const uint32_t*)(buf + AMS + s * 32 + t * 4 + 16);
#pragma unroll
            for (int i = 0; i < 2; i++) {
                const float* pa = sacc[i][2 * s];
                const float* pb = sacc[i][2 * s + 1];
                ph[i][s][0] = hmul2u(packh2(pa[0], pa[1]), m0);
                ph[i][s][1] = hmul2u(packh2(pa[2], pa[3]), m0);
                ph[i][s][2] = hmul2u(packh2(pb[0], pb[1]), m1);
                ph[i][s][3] = hmul2u(packh2(pb[2], pb[3]), m1);
            }
        }

        // ---- O += P @ V  (9th n-tile = ones column -> l) ----
#pragma unroll
        for (int s = 0; s < 4; s++) {
#pragma unroll
            for (int j = 0; j < 9; j++) {
                uint2 vv = *(const uint2*)(buf + AV + (8 * j + g) * ARS + s * 32 + t * 8);
                mma_f16(oacc[0][j], ph[0][s], (const uint32_t*)&vv);
                mma_f16(oacc[1][j], ph[1][s], (const uint32_t*)&vv);
            }
        }

        __syncthreads();
        if (it + 2 < nt) {
            size_t kaK = (size_t)(it + 2) * 8192;
            size_t kaV = (size_t)(it + 2) * 128;
            uint32_t db = sb + (it & 1) * ABUF;
#pragma unroll
            for (int q = 0; q < 8; q++)
                cp16(db + cdst[q], csrc[q] + ((q < 4) ? kaK : kaV));
            if (tid < 8) cp16(db + AMS + tid * 16, msrc + (size_t)(it + 2) * 128);
        }
        asm volatile("cp.async.commit_group;");
    }

    // l lives in oacc[i][8][0]/[2] of the t=0 lane of each quad; broadcast + write
#pragma unroll
    for (int i = 0; i < 2; i++) {
        float l0 = __shfl_sync(0xffffffffu, oacc[i][8][0], lane & ~3);
        float l1 = __shfl_sync(0xffffffffu, oacc[i][8][2], lane & ~3);
        float inv0 = 1.f / l0;
        float inv1 = 1.f / l1;
        int row0 = q0 + wid * 32 + 16 * i + g;
#pragma unroll
        for (int j = 0; j < 8; j++) {
            int col = h * DH + 8 * j + 2 * t;
            *(float2*)(O + (size_t)(b * Sq + row0) * HS + col) =
                make_float2(oacc[i][j][0] * inv0, oacc[i][j][1] * inv0);
            *(float2*)(O + (size_t)(b * Sq + row0 + 8) * HS + col) =
                make_float2(oacc[i][j][2] * inv1, oacc[i][j][3] * inv1);
        }
    }
}

// ==================== fused residual add + LayerNorm (merged) ====================
__global__ __launch_bounds__(256) void add_ln_all(
    const float* __restrict__ xc, const float* __restrict__ Ac,
    const float* __restrict__ xe, const float* __restrict__ Ae,
    const float* __restrict__ g, const float* __restrict__ bb,
    float* __restrict__ out)
{
    int row = blockIdx.x;
    const float *x, *att;
    if (row < B * SC) { x = xc + (size_t)row * HS; att = Ac + (size_t)row * HS; }
    else {
        int r = row - B * SC;
        x = xe + (size_t)r * HS; att = Ae + (size_t)r * HS;
    }
    int tid = threadIdx.x;
    float4 xv = ((const float4*)x)[tid];
    float4 av = ((const float4*)att)[tid];
    float v0 = xv.x + av.x, v1 = xv.y + av.y, v2 = xv.z + av.z, v3 = xv.w + av.w;

    float s = v0 + v1 + v2 + v3;
    float sq = v0 * v0 + v1 * v1 + v2 * v2 + v3 * v3;
#pragma unroll
    for (int off = 16; off > 0; off >>= 1) {
        s  += __shfl_xor_sync(0xffffffffu, s, off);
        sq += __shfl_xor_sync(0xffffffffu, sq, off);
    }
    __shared__ float ss[8], ssq[8];
    int wid = tid >> 5, lane = tid & 31;
    if (lane == 0) { ss[wid] = s; ssq[wid] = sq; }
    __syncthreads();
    s = 0.f; sq = 0.f;
#pragma unroll
    for (int w = 0; w < 8; w++) { s += ss[w]; sq += ssq[w]; }

    float mu = s * (1.f / HS);
    float var = sq * (1.f / HS) - mu * mu;
    float r = rsqrtf(var + 1e-5f);

    float4 gv = ((const float4*)g)[tid];
    float4 bv = ((const float4*)bb)[tid];
    float4 ov = make_float4((v0 - mu) * r * gv.x + bv.x,
                            (v1 - mu) * r * gv.y + bv.y,
                            (v2 - mu) * r * gv.z + bv.z,
                            (v3 - mu) * r * gv.w + bv.w);
    ((float4*)(out + (size_t)row * HS))[tid] = ov;
}

// ==================== launcher ====================
extern "C" void kernel_launch(void* const* d_in, const int* in_sizes, int n_in,
                              void* d_out, int out_size)
{
    (void)in_sizes; (void)n_in; (void)out_size;
    const float* x_c   = (const float*)d_in[0];
    const float* x_e   = (const float*)d_in[1];
    const int*   msk_c = (const int*)d_in[2];
    const int*   msk_e = (const int*)d_in[3];
    const float* W_cq = (const float*)d_in[4];  const float* b_cq = (const float*)d_in[5];
    const float* W_ek = (const float*)d_in[6];  const float* b_ek = (const float*)d_in[7];
    const float* W_ev = (const float*)d_in[8];  const float* b_ev = (const float*)d_in[9];
    const float* W_eq = (const float*)d_in[10]; const float* b_eq = (const float*)d_in[11];
    const float* W_ck = (const float*)d_in[12]; const float* b_ck = (const float*)d_in[13];
    const float* W_cv = (const float*)d_in[14]; const float* b_cv = (const float*)d_in[15];
    const float* ln_g = (const float*)d_in[16]; const float* ln_b = (const float*)d_in[17];
    float* out = (float*)d_out;

    float *QKVc, *QKVe, *Ac, *Ae;
    cudaGetSymbolAddress((void**)&QKVc, g_QKVc);
    cudaGetSymbolAddress((void**)&QKVe, g_QKVe);
    cudaGetSymbolAddress((void**)&Ac, g_Ac);
    cudaGetSymbolAddress((void**)&Ae, g_Ae);
    __half *xch, *xeh, *Wch, *Weh, *mhc, *mhe;
    cudaGetSymbolAddress((void**)&xch, g_xch);
    cudaGetSymbolAddress((void**)&xeh, g_xeh);
    cudaGetSymbolAddress((void**)&Wch, g_Wch);
    cudaGetSymbolAddress((void**)&Weh, g_Weh);
    cudaGetSymbolAddress((void**)&mhc, g_mhc);
    cudaGetSymbolAddress((void**)&mhe, g_mhe);
    __half *Ke16, *Vte16, *Kc16, *Vtc16;
    cudaGetSymbolAddress((void**)&Ke16, g_Ke16);
    cudaGetSymbolAddress((void**)&Vte16, g_Vte16);
    cudaGetSymbolAddress((void**)&Kc16, g_Kc16);
    cudaGetSymbolAddress((void**)&Vtc16, g_Vtc16);

    cudaFuncSetAttribute(gemm_f16, cudaFuncAttributeMaxDynamicSharedMemorySize, G_SMEM);
    cudaFuncSetAttribute(attn_all, cudaFuncAttributeMaxDynamicSharedMemorySize, ASMEM);

    const int Mc = B * SC;   // 2048
    const int Me = B * SE;   // 8192

    cvt_all<<<8192 + 10, 256>>>(W_cq, W_ck, W_cv, W_eq, W_ek, W_ev, x_c, x_e,
                                msk_c, msk_e, Wch, Weh, xch, xeh, mhc, mhe);

    gemm_f16<<<dim3(8, Me / 128, 6), 128, G_SMEM>>>(
        xeh, Weh, xch, Wch,
        b_eq, b_ek, b_ev, b_cq, b_ck, b_cv,
        QKVe, QKVc);

    float* Qc = QKVc;
    float* Kc = QKVc + (size_t)Mc * HS;
    float* Vc = QKVc + (size_t)2 * Mc * HS;
    float* Qe = QKVe;
    float* Ke = QKVe + (size_t)Me * HS;
    float* Ve = QKVe + (size_t)2 * Me * HS;

    prep_all<<<dim3(SC / 64 + SE / 64, NH, B), 256>>>(
        Kc, Vc, Kc16, Vtc16, Ke, Ve, Ke16, Vte16);

    attn_all<<<dim3(SC / 128 + SE / 128, NH, B), 128, ASMEM>>>(
        Qc, Ke16, Vte16, mhe, Ac,
        Qe, Kc16, Vtc16, mhc, Ae);

    add_ln_all<<<Mc + Me, 256>>>(x_c, Ac, x_e, Ae, ln_g, ln_b, out);
}

// round 14
// speedup vs baseline: 1.1711x; 1.0008x over previous
#include <cuda_runtime.h>
#include <cuda_fp16.h>
#include <cstdint>

#define HS 1024
#define NH 16
#define DH 64
#define B 4
#define SC 512
#define SE 2048

// -------------------- scratch (device globals; no allocation) --------------------
__device__ float g_QKVc[(size_t)3 * B * SC * HS];   // Qc | Kc | Vc
__device__ float g_QKVe[(size_t)3 * B * SE * HS];   // Qe | Ke | Ve
__device__ float g_Ac[(size_t)B * SC * HS];
__device__ float g_Ae[(size_t)B * SE * HS];
// fp16 preconverted GEMM operands (k-dim permuted within 16-groups)
__device__ __align__(256) __half g_xch[(size_t)B * SC * HS];
__device__ __align__(256) __half g_xeh[(size_t)B * SE * HS];
__device__ __align__(256) __half g_Wch[(size_t)3 * HS * HS];   // W_cq|W_ck|W_cv
__device__ __align__(256) __half g_Weh[(size_t)3 * HS * HS];   // W_eq|W_ek|W_ev
// fp16 K (d-permuted) / V-transposed (seq-permuted) per head
__device__ __align__(256) __half g_Ke16[(size_t)B * NH * SE * DH];
__device__ __align__(256) __half g_Vte16[(size_t)B * NH * SE * DH];
__device__ __align__(256) __half g_Kc16[(size_t)B * NH * SC * DH];
__device__ __align__(256) __half g_Vtc16[(size_t)B * NH * SC * DH];
// fp16 masks (0.0 / 1.0)
__device__ __align__(256) __half g_mhc[(size_t)B * SC];
__device__ __align__(256) __half g_mhe[(size_t)B * SE];

// ==================== helpers ====================
__device__ __forceinline__ void mma_f16(float* d, const uint32_t* a, const uint32_t* b) {
    asm volatile(
        "mma.sync.aligned.m16n8k16.row.col.f32.f16.f16.f32 "
        "{%0,%1,%2,%3}, {%4,%5,%6,%7}, {%8,%9}, {%0,%1,%2,%3};"
        : "+f"(d[0]), "+f"(d[1]), "+f"(d[2]), "+f"(d[3])
        : "r"(a[0]), "r"(a[1]), "r"(a[2]), "r"(a[3]), "r"(b[0]), "r"(b[1]));
}

// fp16-accumulator MMA: d packs {row g: c0,c1} in d[0], {row g+8: c0,c1} in d[1]
__device__ __forceinline__ void mma_f16acc(uint32_t* d, const uint32_t* a, const uint32_t* b) {
    asm volatile(
        "mma.sync.aligned.m16n8k16.row.col.f16.f16.f16.f16 "
        "{%0,%1}, {%2,%3,%4,%5}, {%6,%7}, {%0,%1};"
        : "+r"(d[0]), "+r"(d[1])
        : "r"(a[0]), "r"(a[1]), "r"(a[2]), "r"(a[3]), "r"(b[0]), "r"(b[1]));
}

__device__ __forceinline__ uint32_t packh2(float a, float b) {
    __half2 h = __floats2half2_rn(a, b);
    return *(uint32_t*)&h;
}

__device__ __forceinline__ uint32_t hmul2u(uint32_t a, uint32_t b) {
    __half2 r = __hmul2(*(__half2*)&a, *(__half2*)&b);
    return *(uint32_t*)&r;
}

__device__ __forceinline__ uint32_t smem_u32(const void* p) {
    uint32_t a;
    asm("{ .reg .u64 t; cvta.to.shared.u64 t, %1; cvt.u32.u64 %0, t; }" : "=r"(a) : "l"(p));
    return a;
}

__device__ __forceinline__ void cp16(uint32_t dst, const void* src) {
    asm volatile("cp.async.cg.shared.global [%0], [%1], 16;" :: "r"(dst), "l"(src));
}

// hardware exp2 (MUFU.EX2)
__device__ __forceinline__ float ex2(float x) {
    float r;
    asm("ex2.approx.f32 %0, %1;" : "=f"(r) : "f"(x));
    return r;
}

// k-dim pair permutation (within 16-element groups) used by prep_all (K,V paths)
__device__ __forceinline__ int kperm(int c) {
    return (c >> 4) * 16 + (((c & 7) >> 1) << 2) + (((c >> 3) & 1) << 1);
}

#define CSC 0.1803368801111694f   // log2(e)/8

// ==================== merged convert: weights + activations + masks ==============
__global__ __launch_bounds__(256) void cvt_all(
    const float* __restrict__ Wcq, const float* __restrict__ Wck,
    const float* __restrict__ Wcv, const float* __restrict__ Weq,
    const float* __restrict__ Wek, const float* __restrict__ Wev,
    const float* __restrict__ xc, const float* __restrict__ xe,
    const int* __restrict__ mc, const int* __restrict__ me,
    __half* __restrict__ dWc, __half* __restrict__ dWe,
    __half* __restrict__ dxc, __half* __restrict__ dxe,
    __half* __restrict__ dmc, __half* __restrict__ dme)
{
    int bid = blockIdx.x;
    if (bid >= 8192) {   // mask conversion: 10240 ints total, 4 per thread
        int idx = (bid - 8192) * 256 + threadIdx.x;
        int base = idx * 4;
        const int* src;
        __half* dst;
        if (base < B * SC) { src = mc + base; dst = dmc + base; }
        else { base -= B * SC; src = me + base; dst = dme + base; }
        int4 v = *(const int4*)src;
        uint2 o;
        o.x = packh2(v.x ? 1.f : 0.f, v.y ? 1.f : 0.f);
        o.y = packh2(v.z ? 1.f : 0.f, v.w ? 1.f : 0.f);
        *(uint2*)dst = o;
        return;
    }

    const float* s;
    __half* d;
    int i;
    if (bid < 3072) {
        int z = bid >> 9;
        const float* Ws[6] = {Wcq, Wck, Wcv, Weq, Wek, Wev};
        s = Ws[z];
        d = (z < 3) ? (dWc + ((size_t)z << 20)) : (dWe + ((size_t)(z - 3) << 20));
        i = (bid & 511) * 256 + threadIdx.x;
    } else if (bid < 4096) {
        s = xc; d = dxc;
        i = (bid - 3072) * 256 + threadIdx.x;
    } else {
        s = xe; d = dxe;
        i = (bid - 4096) * 256 + threadIdx.x;
    }
    int op = 4 * i;
    int grp = op >> 3;
    int j0 = op & 7;
    const float2* sp = (const float2*)s + (size_t)grp * 8;
    uint4 o;
    {
        int p0 = 4 * ((j0 + 0) & 1) + ((j0 + 0) >> 1);
        int p1 = 4 * ((j0 + 1) & 1) + ((j0 + 1) >> 1);
        int p2 = 4 * ((j0 + 2) & 1) + ((j0 + 2) >> 1);
        int p3 = 4 * ((j0 + 3) & 1) + ((j0 + 3) >> 1);
        float2 v0 = sp[p0], v1 = sp[p1], v2 = sp[p2], v3 = sp[p3];
        o.x = packh2(v0.x, v0.y);
        o.y = packh2(v1.x, v1.y);
        o.z = packh2(v2.x, v2.y);
        o.w = packh2(v3.x, v3.y);
    }
    ((uint4*)d)[i] = o;
}

// ==================== GEMM: fp16 accumulators, 3 CTA/SM, LDS.64 frags ============
#define G_RS    96
#define G_A     0
#define G_B     (128 * G_RS)          // 12288
#define G_STAGE (256 * G_RS)          // 24576
#define G_SMEM  (3 * G_STAGE)         // 73728

__global__ __launch_bounds__(128, 3) void gemm_f16(
    const __half* __restrict__ xeh, const __half* __restrict__ Weh,
    const __half* __restrict__ xch, const __half* __restrict__ Wch,
    const float* __restrict__ beq, const float* __restrict__ bek,
    const float* __restrict__ bev,
    const float* __restrict__ bcq, const float* __restrict__ bck,
    const float* __restrict__ bcv,
    float* __restrict__ Ce, float* __restrict__ Cc)
{
    const int z = blockIdx.z;
    const __half *Ah, *Wz;
    float* C;
    const float* bias;
    if (z < 3) {
        Ah = xeh;
        Wz = Weh + ((size_t)z << 20);
        C = Ce + (size_t)z * (B * SE) * HS;
        bias = (z == 0) ? beq : ((z == 1) ? bek : bev);
    } else {
        if (blockIdx.y >= (B * SC) / 128) return;
        int zz = z - 3;
        Ah = xch;
        Wz = Wch + ((size_t)zz << 20);
        C = Cc + (size_t)zz * (B * SC) * HS;
        bias = (zz == 0) ? bcq : ((zz == 1) ? bck : bcv);
    }

    extern __shared__ char smem[];
    const uint32_t sb = smem_u32(smem);
    const int tid = threadIdx.x;
    const int wid = tid >> 5;
    const int lane = tid & 31;
    const int g = lane >> 2;
    const int t = lane & 3;
    const int wm = wid >> 1;
    const int wn = wid & 1;
    const int bm = blockIdx.y * 128;
    const int bn = blockIdx.x * 128;

    const char* csrc[8];
    uint32_t cdst[8];
#pragma unroll
    for (int q = 0; q < 8; q++) {
        int f = q * 128 + tid;
        int tile = f >> 9;
        int idx = f & 511;
        int r = idx >> 2, c = idx & 3;
        cdst[q] = (uint32_t)(tile * G_B + r * G_RS + c * 16);
        if (tile == 0) csrc[q] = (const char*)(Ah + (size_t)(bm + r) * HS + c * 8);
        else           csrc[q] = (const char*)(Wz + (size_t)(bn + r) * HS + c * 8);
    }

    const int NC = HS / 32;

#pragma unroll
    for (int st = 0; st < 3; st++) {
        uint32_t db = sb + st * G_STAGE;
#pragma unroll
        for (int q = 0; q < 8; q++)
            cp16(db + cdst[q], csrc[q] + st * 64);
        asm volatile("cp.async.commit_group;");
    }

    uint32_t acc[4][8][2];
#pragma unroll
    for (int i = 0; i < 4; i++)
#pragma unroll
        for (int j = 0; j < 8; j++) {
            acc[i][j][0] = 0u;
            acc[i][j][1] = 0u;
        }

    for (int c = 0; c < NC; c++) {
        asm volatile("cp.async.wait_group 2;");
        __syncthreads();

        const char* buf = smem + (c % 3) * G_STAGE;
#pragma unroll
        for (int s = 0; s < 2; s++) {
            const int kb = s * 32 + t * 8;
            uint32_t ah[4][4];
#pragma unroll
            for (int i = 0; i < 4; i++) {
                const char* pa = buf + G_A + (wm * 64 + 16 * i + g) * G_RS + kb;
                uint2 alo = *(const uint2*)(pa);
                uint2 ahi = *(const uint2*)(pa + 8 * G_RS);
                ah[i][0] = alo.x;
                ah[i][1] = ahi.x;
                ah[i][2] = alo.y;
                ah[i][3] = ahi.y;
            }
#pragma unroll
            for (int j = 0; j < 8; j++) {
                uint2 bv = *(const uint2*)(buf + G_B + (wn * 64 + 8 * j + g) * G_RS + kb);
#pragma unroll
                for (int i = 0; i < 4; i++)
                    mma_f16acc(acc[i][j], ah[i], (const uint32_t*)&bv);
            }
        }
        __syncthreads();

        if (c + 3 < NC) {
            uint32_t db = sb + ((c + 3) % 3) * G_STAGE;
            int koff = (c + 3) * 64;
#pragma unroll
            for (int q = 0; q < 8; q++)
                cp16(db + cdst[q], csrc[q] + koff);
        }
        asm volatile("cp.async.commit_group;");
    }

#pragma unroll
    for (int i = 0; i < 4; i++) {
        int row0 = bm + wm * 64 + 16 * i + g;
#pragma unroll
        for (int j = 0; j < 8; j++) {
            int col = bn + wn * 64 + 8 * j + 2 * t;
            float2 bv2 = *(const float2*)(bias + col);
            float2 lo = __half22float2(*(__half2*)&acc[i][j][0]);
            float2 hi = __half22float2(*(__half2*)&acc[i][j][1]);
            *(float2*)(C + (size_t)row0 * HS + col) =
                make_float2(lo.x + bv2.x, lo.y + bv2.y);
            *(float2*)(C + (size_t)(row0 + 8) * HS + col) =
                make_float2(hi.x + bv2.x, hi.y + bv2.y);
        }
    }
}

// ==================== K/V prep: fp32 -> fp16, k-dim permuted ====================
__global__ __launch_bounds__(256) void prep_all(
    const float* __restrict__ Kc, const float* __restrict__ Vc,
    __half* __restrict__ Kc16, __half* __restrict__ Vtc16,
    const float* __restrict__ Ke, const float* __restrict__ Ve,
    __half* __restrict__ Ke16, __half* __restrict__ Vte16)
{
    __shared__ float vs[64][65];
    const int tid = threadIdx.x;
    const int b = blockIdx.z, h = blockIdx.y;
    const int bh = b * NH + h;

    const float *K, *V;
    __half *Kh, *Vth;
    int Sk, s0;
    if (blockIdx.x < SC / 64) {
        K = Kc; V = Vc; Kh = Kc16; Vth = Vtc16; Sk = SC;
        s0 = blockIdx.x * 64;
    } else {
        K = Ke; V = Ve; Kh = Ke16; Vth = Vte16; Sk = SE;
        s0 = (blockIdx.x - SC / 64) * 64;
    }

#pragma unroll
    for (int i = 0; i < 4; i++) {
        int f = tid + 256 * i;
        int r = f >> 4, c4 = f & 15;
        float4 v = *(const float4*)(K + (size_t)(b * Sk + s0 + r) * HS + h * DH + c4 * 4);
        int c = c4 * 4;
        int n0 = kperm(c);
        size_t o = ((size_t)(bh * Sk + s0 + r)) * DH;
        *(uint32_t*)(Kh + o + n0) = packh2(v.x, v.y);
        *(uint32_t*)(Kh + o + n0 + 4) = packh2(v.z, v.w);
    }
#pragma unroll
    for (int i = 0; i < 4; i++) {
        int f = tid + 256 * i;
        int r = f >> 4, c4 = f & 15;
        float4 v = *(const float4*)(V + (size_t)(b * Sk + s0 + r) * HS + h * DH + c4 * 4);
        vs[r][c4 * 4 + 0] = v.x;
        vs[r][c4 * 4 + 1] = v.y;
        vs[r][c4 * 4 + 2] = v.z;
        vs[r][c4 * 4 + 3] = v.w;
    }
    __syncthreads();
#pragma unroll
    for (int i = 0; i < 8; i++) {
        int f = tid + 256 * i;
        int d = f >> 5, sp = f & 31;
        float v0 = vs[2 * sp][d], v1 = vs[2 * sp + 1][d];
        int np = kperm(2 * sp);
        size_t o = ((size_t)(bh * DH + d)) * Sk + s0 + np;
        *(uint32_t*)(Vth + o) = packh2(v0, v1);
    }
}

// ==================== attention: fp16 P*V accumulators, 3 CTA/SM =================
#define AK    0
#define AV    10240               // 72 rows x 160 (rows 64..71 = ones/zero pad)
#define AMS   21760               // 64 fp16 mask values (128B)
#define ABUF  22016
#define ASMEM (2 * ABUF)          // 44032
#define ARS   160

__global__ __launch_bounds__(128, 3) void attn_all(
    const float* __restrict__ Qc, const __half* __restrict__ Ke,
    const __half* __restrict__ Vte, const __half* __restrict__ me,
    float* __restrict__ Ac,
    const float* __restrict__ Qe, const __half* __restrict__ Kc,
    const __half* __restrict__ Vtc, const __half* __restrict__ mc,
    float* __restrict__ Ae)
{
    extern __shared__ char sm[];
    const uint32_t sb = smem_u32(sm);
    const int tid = threadIdx.x;
    const int wid = tid >> 5;
    const int lane = tid & 31;
    const int g = lane >> 2;
    const int t = lane & 3;
    const int b = blockIdx.z, h = blockIdx.y;
    const int bx = blockIdx.x;
    const int bh = b * NH + h;

    const float* Q;
    const __half* K;
    const __half* Vt;
    const __half* mask;
    float* O;
    int Sq, Sk, q0;
    if (bx < SC / 128) {
        Q = Qc; K = Ke; Vt = Vte; mask = me; O = Ac;
        Sq = SC; Sk = SE; q0 = bx * 128;
    } else {
        Q = Qe; K = Kc; Vt = Vtc; mask = mc; O = Ae;
        Sq = SE; Sk = SC; q0 = (bx - SC / 128) * 128;
    }
    const int nt = Sk / 64;

    const char* csrc[8];
    uint32_t cdst[8];
#pragma unroll
    for (int q = 0; q < 8; q++) {
        int f = q * 128 + tid;
        int tile = f >> 9;
        int idx = f & 511;
        int r = idx >> 3, c = idx & 7;
        if (tile == 0) {
            csrc[q] = (const char*)(K + (size_t)(bh * (size_t)Sk + r) * DH + c * 8);
            cdst[q] = AK + (uint32_t)(r * ARS + c * 16);
        } else {
            csrc[q] = (const char*)(Vt + (size_t)(bh * DH + r) * (size_t)Sk + c * 8);
            cdst[q] = AV + (uint32_t)(r * ARS + c * 16);
        }
    }
    const char* msrc = (const char*)(mask + (size_t)b * Sk) + tid * 16;

    {
#pragma unroll
        for (int q = 0; q < 8; q++)
            cp16(sb + cdst[q], csrc[q]);
        if (tid < 8) cp16(sb + AMS + tid * 16, msrc);
        asm volatile("cp.async.commit_group;");
    }

    // init ones/zero pad rows 64..71 of both V buffers (128B per row used)
    {
        int row = 64 + (tid >> 4);
        int off = (tid & 15) * 8;
        uint2 val = (row == 64) ? make_uint2(0x3C003C00u, 0x3C003C00u)
                                : make_uint2(0u, 0u);
        *(uint2*)(sm + AV + row * ARS + off) = val;
        *(uint2*)(sm + ABUF + AV + row * ARS + off) = val;
    }

    if (nt > 1) {
#pragma unroll
        for (int q = 0; q < 8; q++)
            cp16(sb + ABUF + cdst[q], csrc[q] + ((q < 4) ? 8192 : 128));
        if (tid < 8) cp16(sb + ABUF + AMS + tid * 16, msrc + 128);
    }
    asm volatile("cp.async.commit_group;");

    // Q fragments (2 m16 tiles per warp), pre-scaled by CSC
    uint32_t qh[2][4][4];
#pragma unroll
    for (int i = 0; i < 2; i++) {
        const float* qp0 = Q + (size_t)(b * Sq + q0 + wid * 32 + 16 * i + g) * HS + h * DH;
        const float* qp8 = qp0 + 8 * HS;
#pragma unroll
        for (int kk = 0; kk < 4; kk++) {
            int c0 = 16 * kk + 2 * t;
            float2 x0 = *(const float2*)(qp0 + c0);
            float2 x1 = *(const float2*)(qp8 + c0);
            float2 x2 = *(const float2*)(qp0 + c0 + 8);
            float2 x3 = *(const float2*)(qp8 + c0 + 8);
            qh[i][kk][0] = packh2(x0.x * CSC, x0.y * CSC);
            qh[i][kk][1] = packh2(x1.x * CSC, x1.y * CSC);
            qh[i][kk][2] = packh2(x2.x * CSC, x2.y * CSC);
            qh[i][kk][3] = packh2(x3.x * CSC, x3.y * CSC);
        }
    }

    // fp16 packed accumulators: oacc[i][j] = {row g cols 2t..2t+1, row g+8 ...}
    // j=8 is the ones column (l accumulator)
    uint32_t oacc[2][9][2];
#pragma unroll
    for (int i = 0; i < 2; i++)
#pragma unroll
        for (int j = 0; j < 9; j++) {
            oacc[i][j][0] = 0u;
            oacc[i][j][1] = 0u;
        }

    for (int it = 0; it < nt; it++) {
        if (it + 1 < nt) { asm volatile("cp.async.wait_group 1;"); }
        else             { asm volatile("cp.async.wait_group 0;"); }
        __syncthreads();

        char* buf = sm + (it & 1) * ABUF;

        // ---- S = Q @ K^T (fp32 acc, feeds ex2) ----
        float sacc[2][8][4];
#pragma unroll
        for (int i = 0; i < 2; i++)
#pragma unroll
            for (int j = 0; j < 8; j++)
#pragma unroll
                for (int k = 0; k < 4; k++) sacc[i][j][k] = 0.f;

#pragma unroll
        for (int kk = 0; kk < 4; kk++) {
#pragma unroll
            for (int j = 0; j < 8; j++) {
                uint2 kv = *(const uint2*)(buf + AK + (8 * j + g) * ARS + kk * 32 + t * 8);
                mma_f16(sacc[0][j], qh[0][kk], (const uint32_t*)&kv);
                mma_f16(sacc[1][j], qh[1][kk], (const uint32_t*)&kv);
            }
        }

        // ---- p = ex2(s) ----
#pragma unroll
        for (int i = 0; i < 2; i++)
#pragma unroll
            for (int j = 0; j < 8; j++) {
                sacc[i][j][0] = ex2(sacc[i][j][0]);
                sacc[i][j][1] = ex2(sacc[i][j][1]);
                sacc[i][j][2] = ex2(sacc[i][j][2]);
                sacc[i][j][3] = ex2(sacc[i][j][3]);
            }

        // ---- pack P, apply fp16 mask multiply ----
        uint32_t ph[2][4][4];
#pragma unroll
        for (int s = 0; s < 4; s++) {
            uint32_t m0 = *(const uint32_t*)(buf + AMS + s * 32 + t * 4);
            uint32_t m1 = *(const uint32_t*)(buf + AMS + s * 32 + t * 4 + 16);
#pragma unroll
            for (int i = 0; i < 2; i++) {
                const float* pa = sacc[i][2 * s];
                const float* pb = sacc[i][2 * s + 1];
                ph[i][s][0] = hmul2u(packh2(pa[0], pa[1]), m0);
                ph[i][s][1] = hmul2u(packh2(pa[2], pa[3]), m0);
                ph[i][s][2] = hmul2u(packh2(pb[0], pb[1]), m1);
                ph[i][s][3] = hmul2u(packh2(pb[2], pb[3]), m1);
            }
        }

        // ---- O += P @ V  (fp16 acc; 9th n-tile = ones column -> l) ----
#pragma unroll
        for (int s = 0; s < 4; s++) {
#pragma unroll
            for (int j = 0; j < 9; j++) {
                uint2 vv = *(const uint2*)(buf + AV + (8 * j + g) * ARS + s * 32 + t * 8);
                mma_f16acc(oacc[0][j], ph[0][s], (const uint32_t*)&vv);
                mma_f16acc(oacc[1][j], ph[1][s], (const uint32_t*)&vv);
            }
        }

        __syncthreads();
        if (it + 2 < nt) {
            size_t kaK = (size_t)(it + 2) * 8192;
            size_t kaV = (size_t)(it + 2) * 128;
            uint32_t db = sb + (it & 1) * ABUF;
#pragma unroll
            for (int q = 0; q < 8; q++)
                cp16(db + cdst[q], csrc[q] + ((q < 4) ? kaK : kaV));
            if (tid < 8) cp16(db + AMS + tid * 16, msrc + (size_t)(it + 2) * 128);
        }
        asm volatile("cp.async.commit_group;");
    }

    // l = column 64 = low half of oacc[i][8][*] at the t=0 lane of each quad
#pragma unroll
    for (int i = 0; i < 2; i++) {
        uint32_t lw0 = __shfl_sync(0xffffffffu, oacc[i][8][0], lane & ~3);
        uint32_t lw1 = __shfl_sync(0xffffffffu, oacc[i][8][1], lane & ~3);
        float l0 = __half2float(((const __half2*)&lw0)->x);
        float l1 = __half2float(((const __half2*)&lw1)->x);
        float inv0 = 1.f / l0;
        float inv1 = 1.f / l1;
        int row0 = q0 + wid * 32 + 16 * i + g;
#pragma unroll
        for (int j = 0; j < 8; j++) {
            int col = h * DH + 8 * j + 2 * t;
            float2 lo = __half22float2(*(__half2*)&oacc[i][j][0]);
            float2 hi = __half22float2(*(__half2*)&oacc[i][j][1]);
            *(float2*)(O + (size_t)(b * Sq + row0) * HS + col) =
                make_float2(lo.x * inv0, lo.y * inv0);
            *(float2*)(O + (size_t)(b * Sq + row0 + 8) * HS + col) =
                make_float2(hi.x * inv1, hi.y * inv1);
        }
    }
}

// ==================== fused residual add + LayerNorm (merged) ====================
__global__ __launch_bounds__(256) void add_ln_all(
    const float* __restrict__ xc, const float* __restrict__ Ac,
    const float* __restrict__ xe, const float* __restrict__ Ae,
    const float* __restrict__ g, const float* __restrict__ bb,
    float* __restrict__ out)
{
    int row = blockIdx.x;
    const float *x, *att;
    if (row < B * SC) { x = xc + (size_t)row * HS; att = Ac + (size_t)row * HS; }
    else {
        int r = row - B * SC;
        x = xe + (size_t)r * HS; att = Ae + (size_t)r * HS;
    }
    int tid = threadIdx.x;
    float4 xv = ((const float4*)x)[tid];
    float4 av = ((const float4*)att)[tid];
    float v0 = xv.x + av.x, v1 = xv.y + av.y, v2 = xv.z + av.z, v3 = xv.w + av.w;

    float s = v0 + v1 + v2 + v3;
    float sq = v0 * v0 + v1 * v1 + v2 * v2 + v3 * v3;
#pragma unroll
    for (int off = 16; off > 0; off >>= 1) {
        s  += __shfl_xor_sync(0xffffffffu, s, off);
        sq += __shfl_xor_sync(0xffffffffu, sq, off);
    }
    __shared__ float ss[8], ssq[8];
    int wid = tid >> 5, lane = tid & 31;
    if (lane == 0) { ss[wid] = s; ssq[wid] = sq; }
    __syncthreads();
    s = 0.f; sq = 0.f;
#pragma unroll
    for (int w = 0; w < 8; w++) { s += ss[w]; sq += ssq[w]; }

    float mu = s * (1.f / HS);
    float var = sq * (1.f / HS) - mu * mu;
    float r = rsqrtf(var + 1e-5f);

    float4 gv = ((const float4*)g)[tid];
    float4 bv = ((const float4*)bb)[tid];
    float4 ov = make_float4((v0 - mu) * r * gv.x + bv.x,
                            (v1 - mu) * r * gv.y + bv.y,
                            (v2 - mu) * r * gv.z + bv.z,
                            (v3 - mu) * r * gv.w + bv.w);
    ((float4*)(out + (size_t)row * HS))[tid] = ov;
}

// ==================== launcher ====================
extern "C" void kernel_launch(void* const* d_in, const int* in_sizes, int n_in,
                              void* d_out, int out_size)
{
    (void)in_sizes; (void)n_in; (void)out_size;
    const float* x_c   = (const float*)d_in[0];
    const float* x_e   = (const float*)d_in[1];
    const int*   msk_c = (const int*)d_in[2];
    const int*   msk_e = (const int*)d_in[3];
    const float* W_cq = (const float*)d_in[4];  const float* b_cq = (const float*)d_in[5];
    const float* W_ek = (const float*)d_in[6];  const float* b_ek = (const float*)d_in[7];
    const float* W_ev = (const float*)d_in[8];  const float* b_ev = (const float*)d_in[9];
    const float* W_eq = (const float*)d_in[10]; const float* b_eq = (const float*)d_in[11];
    const float* W_ck = (const float*)d_in[12]; const float* b_ck = (const float*)d_in[13];
    const float* W_cv = (const float*)d_in[14]; const float* b_cv = (const float*)d_in[15];
    const float* ln_g = (const float*)d_in[16]; const float* ln_b = (const float*)d_in[17];
    float* out = (float*)d_out;

    float *QKVc, *QKVe, *Ac, *Ae;
    cudaGetSymbolAddress((void**)&QKVc, g_QKVc);
    cudaGetSymbolAddress((void**)&QKVe, g_QKVe);
    cudaGetSymbolAddress((void**)&Ac, g_Ac);
    cudaGetSymbolAddress((void**)&Ae, g_Ae);
    __half *xch, *xeh, *Wch, *Weh, *mhc, *mhe;
    cudaGetSymbolAddress((void**)&xch, g_xch);
    cudaGetSymbolAddress((void**)&xeh, g_xeh);
    cudaGetSymbolAddress((void**)&Wch, g_Wch);
    cudaGetSymbolAddress((void**)&Weh, g_Weh);
    cudaGetSymbolAddress((void**)&mhc, g_mhc);
    cudaGetSymbolAddress((void**)&mhe, g_mhe);
    __half *Ke16, *Vte16, *Kc16, *Vtc16;
    cudaGetSymbolAddress((void**)&Ke16, g_Ke16);
    cudaGetSymbolAddress((void**)&Vte16, g_Vte16);
    cudaGetSymbolAddress((void**)&Kc16, g_Kc16);
    cudaGetSymbolAddress((void**)&Vtc16, g_Vtc16);

    cudaFuncSetAttribute(gemm_f16, cudaFuncAttributeMaxDynamicSharedMemorySize, G_SMEM);
    cudaFuncSetAttribute(attn_all, cudaFuncAttributeMaxDynamicSharedMemorySize, ASMEM);

    const int Mc = B * SC;   // 2048
    const int Me = B * SE;   // 8192

    cvt_all<<<8192 + 10, 256>>>(W_cq, W_ck, W_cv, W_eq, W_ek, W_ev, x_c, x_e,
                                msk_c, msk_e, Wch, Weh, xch, xeh, mhc, mhe);

    gemm_f16<<<dim3(8, Me / 128, 6), 128, G_SMEM>>>(
        xeh, Weh, xch, Wch,
        b_eq, b_ek, b_ev, b_cq, b_ck, b_cv,
        QKVe, QKVc);

    float* Qc = QKVc;
    float* Kc = QKVc + (size_t)Mc * HS;
    float* Vc = QKVc + (size_t)2 * Mc * HS;
    float* Qe = QKVe;
    float* Ke = QKVe + (size_t)Me * HS;
    float* Ve = QKVe + (size_t)2 * Me * HS;

    prep_all<<<dim3(SC / 64 + SE / 64, NH, B), 256>>>(
        Kc, Vc, Kc16, Vtc16, Ke, Ve, Ke16, Vte16);

    attn_all<<<dim3(SC / 128 + SE / 128, NH, B), 128, ASMEM>>>(
        Qc, Ke16, Vte16, mhe, Ac,
        Qe, Kc16, Vtc16, mhc, Ae);

    add_ln_all<<<Mc + Me, 256>>>(x_c, Ac, x_e, Ae, ln_g, ln_b, out);
}

// round 15
// speedup vs baseline: 1.1867x; 1.0133x over previous
#include <cuda_runtime.h>
#include <cuda_fp16.h>
#include <cstdint>

#define HS 1024
#define NH 16
#define DH 64
#define B 4
#define SC 512
#define SE 2048

// -------------------- scratch (device globals; no allocation) --------------------
__device__ float g_Ac[(size_t)B * SC * HS];
__device__ float g_Ae[(size_t)B * SE * HS];
// fp16 preconverted GEMM operands (k-dim permuted within 16-groups)
__device__ __align__(256) __half g_xch[(size_t)B * SC * HS];
__device__ __align__(256) __half g_xeh[(size_t)B * SE * HS];
__device__ __align__(256) __half g_Wch[(size_t)3 * HS * HS];   // W_cq|W_ck|W_cv
__device__ __align__(256) __half g_Weh[(size_t)3 * HS * HS];   // W_eq|W_ek|W_ev
// fp16 GEMM outputs: Q (CSC-scaled, kperm cols), K (kperm cols), V (plain)
__device__ __align__(256) __half g_Q16c[(size_t)B * SC * HS];
__device__ __align__(256) __half g_K16c[(size_t)B * SC * HS];
__device__ __align__(256) __half g_V16c[(size_t)B * SC * HS];
__device__ __align__(256) __half g_Q16e[(size_t)B * SE * HS];
__device__ __align__(256) __half g_K16e[(size_t)B * SE * HS];
__device__ __align__(256) __half g_V16e[(size_t)B * SE * HS];
// fp16 V-transposed per head (seq-permuted)
__device__ __align__(256) __half g_Vtc16[(size_t)B * NH * SC * DH];
__device__ __align__(256) __half g_Vte16[(size_t)B * NH * SE * DH];
// fp16 masks (0.0 / 1.0)
__device__ __align__(256) __half g_mhc[(size_t)B * SC];
__device__ __align__(256) __half g_mhe[(size_t)B * SE];

// ==================== helpers ====================
__device__ __forceinline__ void mma_f16(float* d, const uint32_t* a, const uint32_t* b) {
    asm volatile(
        "mma.sync.aligned.m16n8k16.row.col.f32.f16.f16.f32 "
        "{%0,%1,%2,%3}, {%4,%5,%6,%7}, {%8,%9}, {%0,%1,%2,%3};"
        : "+f"(d[0]), "+f"(d[1]), "+f"(d[2]), "+f"(d[3])
        : "r"(a[0]), "r"(a[1]), "r"(a[2]), "r"(a[3]), "r"(b[0]), "r"(b[1]));
}

__device__ __forceinline__ void mma_f16acc(uint32_t* d, const uint32_t* a, const uint32_t* b) {
    asm volatile(
        "mma.sync.aligned.m16n8k16.row.col.f16.f16.f16.f16 "
        "{%0,%1}, {%2,%3,%4,%5}, {%6,%7}, {%0,%1};"
        : "+r"(d[0]), "+r"(d[1])
        : "r"(a[0]), "r"(a[1]), "r"(a[2]), "r"(a[3]), "r"(b[0]), "r"(b[1]));
}

__device__ __forceinline__ uint32_t packh2(float a, float b) {
    __half2 h = __floats2half2_rn(a, b);
    return *(uint32_t*)&h;
}

__device__ __forceinline__ uint32_t hmul2u(uint32_t a, uint32_t b) {
    __half2 r = __hmul2(*(__half2*)&a, *(__half2*)&b);
    return *(uint32_t*)&r;
}

__device__ __forceinline__ uint32_t smem_u32(const void* p) {
    uint32_t a;
    asm("{ .reg .u64 t; cvta.to.shared.u64 t, %1; cvt.u32.u64 %0, t; }" : "=r"(a) : "l"(p));
    return a;
}

__device__ __forceinline__ void cp16(uint32_t dst, const void* src) {
    asm volatile("cp.async.cg.shared.global [%0], [%1], 16;" :: "r"(dst), "l"(src));
}

__device__ __forceinline__ float ex2(float x) {
    float r;
    asm("ex2.approx.f32 %0, %1;" : "=f"(r) : "f"(x));
    return r;
}

// k-dim pair permutation (within 16-element groups); group boundaries align with
// heads and tiles, so applying it to a global column index is equivalent.
__device__ __forceinline__ int kperm(int c) {
    return (c >> 4) * 16 + (((c & 7) >> 1) << 2) + (((c >> 3) & 1) << 1);
}

#define CSC 0.1803368801111694f   // log2(e)/8

// ==================== merged convert: weights + activations + masks ==============
__global__ __launch_bounds__(256) void cvt_all(
    const float* __restrict__ Wcq, const float* __restrict__ Wck,
    const float* __restrict__ Wcv, const float* __restrict__ Weq,
    const float* __restrict__ Wek, const float* __restrict__ Wev,
    const float* __restrict__ xc, const float* __restrict__ xe,
    const int* __restrict__ mc, const int* __restrict__ me,
    __half* __restrict__ dWc, __half* __restrict__ dWe,
    __half* __restrict__ dxc, __half* __restrict__ dxe,
    __half* __restrict__ dmc, __half* __restrict__ dme)
{
    int bid = blockIdx.x;
    if (bid >= 8192) {   // mask conversion: 10240 ints total, 4 per thread
        int idx = (bid - 8192) * 256 + threadIdx.x;
        int base = idx * 4;
        const int* src;
        __half* dst;
        if (base < B * SC) { src = mc + base; dst = dmc + base; }
        else { base -= B * SC; src = me + base; dst = dme + base; }
        int4 v = *(const int4*)src;
        uint2 o;
        o.x = packh2(v.x ? 1.f : 0.f, v.y ? 1.f : 0.f);
        o.y = packh2(v.z ? 1.f : 0.f, v.w ? 1.f : 0.f);
        *(uint2*)dst = o;
        return;
    }

    const float* s;
    __half* d;
    int i;
    if (bid < 3072) {
        int z = bid >> 9;
        const float* Ws[6] = {Wcq, Wck, Wcv, Weq, Wek, Wev};
        s = Ws[z];
        d = (z < 3) ? (dWc + ((size_t)z << 20)) : (dWe + ((size_t)(z - 3) << 20));
        i = (bid & 511) * 256 + threadIdx.x;
    } else if (bid < 4096) {
        s = xc; d = dxc;
        i = (bid - 3072) * 256 + threadIdx.x;
    } else {
        s = xe; d = dxe;
        i = (bid - 4096) * 256 + threadIdx.x;
    }
    int op = 4 * i;
    int grp = op >> 3;
    int j0 = op & 7;
    const float2* sp = (const float2*)s + (size_t)grp * 8;
    uint4 o;
    {
        int p0 = 4 * ((j0 + 0) & 1) + ((j0 + 0) >> 1);
        int p1 = 4 * ((j0 + 1) & 1) + ((j0 + 1) >> 1);
        int p2 = 4 * ((j0 + 2) & 1) + ((j0 + 2) >> 1);
        int p3 = 4 * ((j0 + 3) & 1) + ((j0 + 3) >> 1);
        float2 v0 = sp[p0], v1 = sp[p1], v2 = sp[p2], v3 = sp[p3];
        o.x = packh2(v0.x, v0.y);
        o.y = packh2(v1.x, v1.y);
        o.z = packh2(v2.x, v2.y);
        o.w = packh2(v3.x, v3.y);
    }
    ((uint4*)d)[i] = o;
}

// ==================== GEMM: fp16 acc, fp16 consumer-layout outputs ===============
#define G_RS    96
#define G_A     0
#define G_B     (128 * G_RS)          // 12288
#define G_STAGE (256 * G_RS)          // 24576
#define G_SMEM  (3 * G_STAGE)         // 73728

__global__ __launch_bounds__(128, 3) void gemm_f16(
    const __half* __restrict__ xeh, const __half* __restrict__ Weh,
    const __half* __restrict__ xch, const __half* __restrict__ Wch,
    const float* __restrict__ beq, const float* __restrict__ bek,
    const float* __restrict__ bev,
    const float* __restrict__ bcq, const float* __restrict__ bck,
    const float* __restrict__ bcv,
    __half* __restrict__ Qe, __half* __restrict__ Ke, __half* __restrict__ Ve,
    __half* __restrict__ Qc, __half* __restrict__ Kc, __half* __restrict__ Vc)
{
    const int z = blockIdx.z;
    const __half *Ah, *Wz;
    __half* D;
    const float* bias;
    int zm;
    if (z < 3) {
        zm = z;
        Ah = xeh;
        Wz = Weh + ((size_t)z << 20);
        D = (z == 0) ? Qe : ((z == 1) ? Ke : Ve);
        bias = (z == 0) ? beq : ((z == 1) ? bek : bev);
    } else {
        if (blockIdx.y >= (B * SC) / 128) return;
        zm = z - 3;
        Ah = xch;
        Wz = Wch + ((size_t)zm << 20);
        D = (zm == 0) ? Qc : ((zm == 1) ? Kc : Vc);
        bias = (zm == 0) ? bcq : ((zm == 1) ? bck : bcv);
    }
    const float scale = (zm == 0) ? CSC : 1.f;
    const bool doperm = (zm != 2);

    extern __shared__ char smem[];
    const uint32_t sb = smem_u32(smem);
    const int tid = threadIdx.x;
    const int wid = tid >> 5;
    const int lane = tid & 31;
    const int g = lane >> 2;
    const int t = lane & 3;
    const int wm = wid >> 1;
    const int wn = wid & 1;
    const int bm = blockIdx.y * 128;
    const int bn = blockIdx.x * 128;

    const char* csrc[8];
    uint32_t cdst[8];
#pragma unroll
    for (int q = 0; q < 8; q++) {
        int f = q * 128 + tid;
        int tile = f >> 9;
        int idx = f & 511;
        int r = idx >> 2, c = idx & 3;
        cdst[q] = (uint32_t)(tile * G_B + r * G_RS + c * 16);
        if (tile == 0) csrc[q] = (const char*)(Ah + (size_t)(bm + r) * HS + c * 8);
        else           csrc[q] = (const char*)(Wz + (size_t)(bn + r) * HS + c * 8);
    }

    const int NC = HS / 32;

#pragma unroll
    for (int st = 0; st < 3; st++) {
        uint32_t db = sb + st * G_STAGE;
#pragma unroll
        for (int q = 0; q < 8; q++)
            cp16(db + cdst[q], csrc[q] + st * 64);
        asm volatile("cp.async.commit_group;");
    }

    uint32_t acc[4][8][2];
#pragma unroll
    for (int i = 0; i < 4; i++)
#pragma unroll
        for (int j = 0; j < 8; j++) {
            acc[i][j][0] = 0u;
            acc[i][j][1] = 0u;
        }

    for (int c = 0; c < NC; c++) {
        asm volatile("cp.async.wait_group 2;");
        __syncthreads();

        const char* buf = smem + (c % 3) * G_STAGE;
#pragma unroll
        for (int s = 0; s < 2; s++) {
            const int kb = s * 32 + t * 8;
            uint32_t ah[4][4];
#pragma unroll
            for (int i = 0; i < 4; i++) {
                const char* pa = buf + G_A + (wm * 64 + 16 * i + g) * G_RS + kb;
                uint2 alo = *(const uint2*)(pa);
                uint2 ahi = *(const uint2*)(pa + 8 * G_RS);
                ah[i][0] = alo.x;
                ah[i][1] = ahi.x;
                ah[i][2] = alo.y;
                ah[i][3] = ahi.y;
            }
#pragma unroll
            for (int j = 0; j < 8; j++) {
                uint2 bv = *(const uint2*)(buf + G_B + (wn * 64 + 8 * j + g) * G_RS + kb);
#pragma unroll
                for (int i = 0; i < 4; i++)
                    mma_f16acc(acc[i][j], ah[i], (const uint32_t*)&bv);
            }
        }
        __syncthreads();

        if (c + 3 < NC) {
            uint32_t db = sb + ((c + 3) % 3) * G_STAGE;
            int koff = (c + 3) * 64;
#pragma unroll
            for (int q = 0; q < 8; q++)
                cp16(db + cdst[q], csrc[q] + koff);
        }
        asm volatile("cp.async.commit_group;");
    }

    // epilogue: fp16 acc + bias (+scale), store fp16 at (optionally kperm'd) cols
#pragma unroll
    for (int i = 0; i < 4; i++) {
        int row0 = bm + wm * 64 + 16 * i + g;
#pragma unroll
        for (int j = 0; j < 8; j++) {
            int c = bn + wn * 64 + 8 * j + 2 * t;
            float2 bv2 = *(const float2*)(bias + c);
            float2 lo = __half22float2(*(__half2*)&acc[i][j][0]);
            float2 hi = __half22float2(*(__half2*)&acc[i][j][1]);
            uint32_t w0 = packh2((lo.x + bv2.x) * scale, (lo.y + bv2.y) * scale);
            uint32_t w1 = packh2((hi.x + bv2.x) * scale, (hi.y + bv2.y) * scale);
            int oc = doperm ? kperm(c) : c;
            *(uint32_t*)(D + (size_t)row0 * HS + oc) = w0;
            *(uint32_t*)(D + (size_t)(row0 + 8) * HS + oc) = w1;
        }
    }
}

// ==================== V prep: fp16 transpose, seq-dim kperm ====================
__global__ __launch_bounds__(256) void prep_v(
    const __half* __restrict__ Vc, __half* __restrict__ Vtc,
    const __half* __restrict__ Ve, __half* __restrict__ Vte)
{
    __shared__ __half vs[64][66];
    const int tid = threadIdx.x;
    const int b = blockIdx.z, h = blockIdx.y;
    const int bh = b * NH + h;

    const __half* V;
    __half* Vt;
    int Sk, s0;
    if (blockIdx.x < SC / 64) {
        V = Vc; Vt = Vtc; Sk = SC;
        s0 = blockIdx.x * 64;
    } else {
        V = Ve; Vt = Vte; Sk = SE;
        s0 = (blockIdx.x - SC / 64) * 64;
    }

#pragma unroll
    for (int i = 0; i < 4; i++) {
        int f = tid + 256 * i;
        int r = f >> 4, cu = f & 15;
        uint2 v = *(const uint2*)(V + (size_t)(b * Sk + s0 + r) * HS + h * DH + cu * 4);
        *(uint32_t*)&vs[r][cu * 4] = v.x;
        *(uint32_t*)&vs[r][cu * 4 + 2] = v.y;
    }
    __syncthreads();
#pragma unroll
    for (int i = 0; i < 8; i++) {
        int f = tid + 256 * i;
        int d = f >> 5, sp = f & 31;
        __half2 pr(vs[2 * sp][d], vs[2 * sp + 1][d]);
        size_t o = ((size_t)(bh * DH + d)) * Sk + s0 + kperm(2 * sp);
        *(uint32_t*)(Vt + o) = *(uint32_t*)&pr;
    }
}

// ==================== attention: fp32 oacc, ones-column l, fp16 Q/K/V ============
#define AK    0
#define AV    10240               // 72 rows x 160 (rows 64..71 = ones/zero pad)
#define AMS   21760               // 64 fp16 mask values (128B)
#define ABUF  22016
#define ASMEM (2 * ABUF)          // 44032
#define ARS   160

__global__ __launch_bounds__(128, 2) void attn_all(
    const __half* __restrict__ Q16c, const __half* __restrict__ K16e,
    const __half* __restrict__ Vte, const __half* __restrict__ me,
    float* __restrict__ Ac,
    const __half* __restrict__ Q16e, const __half* __restrict__ K16c,
    const __half* __restrict__ Vtc, const __half* __restrict__ mc,
    float* __restrict__ Ae)
{
    extern __shared__ char sm[];
    const uint32_t sb = smem_u32(sm);
    const int tid = threadIdx.x;
    const int wid = tid >> 5;
    const int lane = tid & 31;
    const int g = lane >> 2;
    const int t = lane & 3;
    const int b = blockIdx.z, h = blockIdx.y;
    const int bx = blockIdx.x;
    const int bh = b * NH + h;

    const __half* Q;
    const __half* K;
    const __half* Vt;
    const __half* mask;
    float* O;
    int Sq, Sk, q0;
    if (bx < SC / 128) {
        Q = Q16c; K = K16e; Vt = Vte; mask = me; O = Ac;
        Sq = SC; Sk = SE; q0 = bx * 128;
    } else {
        Q = Q16e; K = K16c; Vt = Vtc; mask = mc; O = Ae;
        Sq = SE; Sk = SC; q0 = (bx - SC / 128) * 128;
    }
    const int nt = Sk / 64;
    const size_t KADV = (size_t)64 * HS * 2;   // K bytes per 64-row tile

    const char* csrc[8];
    uint32_t cdst[8];
#pragma unroll
    for (int q = 0; q < 8; q++) {
        int f = q * 128 + tid;
        int tile = f >> 9;
        int idx = f & 511;
        int r = idx >> 3, c = idx & 7;
        if (tile == 0) {
            csrc[q] = (const char*)(K + ((size_t)(b * Sk) + r) * HS + h * DH + c * 8);
            cdst[q] = AK + (uint32_t)(r * ARS + c * 16);
        } else {
            csrc[q] = (const char*)(Vt + (size_t)(bh * DH + r) * (size_t)Sk + c * 8);
            cdst[q] = AV + (uint32_t)(r * ARS + c * 16);
        }
    }
    const char* msrc = (const char*)(mask + (size_t)b * Sk) + tid * 16;

    {
#pragma unroll
        for (int q = 0; q < 8; q++)
            cp16(sb + cdst[q], csrc[q]);
        if (tid < 8) cp16(sb + AMS + tid * 16, msrc);
        asm volatile("cp.async.commit_group;");
    }

    // init ones/zero pad rows 64..71 of both V buffers (128B per row used)
    {
        int row = 64 + (tid >> 4);
        int off = (tid & 15) * 8;
        uint2 val = (row == 64) ? make_uint2(0x3C003C00u, 0x3C003C00u)
                                : make_uint2(0u, 0u);
        *(uint2*)(sm + AV + row * ARS + off) = val;
        *(uint2*)(sm + ABUF + AV + row * ARS + off) = val;
    }

    if (nt > 1) {
#pragma unroll
        for (int q = 0; q < 8; q++)
            cp16(sb + ABUF + cdst[q], csrc[q] + ((q < 4) ? KADV : 128));
        if (tid < 8) cp16(sb + ABUF + AMS + tid * 16, msrc + 128);
    }
    asm volatile("cp.async.commit_group;");

    // Q fragments (2 m16 tiles per warp): fp16, CSC-prescaled, kperm'd cols
    // -> uint2 per (i,kk,row): {pair(2t), pair(2t+8)}
    uint32_t qh[2][4][4];
#pragma unroll
    for (int i = 0; i < 2; i++) {
        const __half* qp0 = Q + (size_t)(b * Sq + q0 + wid * 32 + 16 * i + g) * HS + h * DH;
        const __half* qp8 = qp0 + 8 * HS;
#pragma unroll
        for (int kk = 0; kk < 4; kk++) {
            uint2 u0 = *(const uint2*)(qp0 + 16 * kk + 4 * t);
            uint2 u8 = *(const uint2*)(qp8 + 16 * kk + 4 * t);
            qh[i][kk][0] = u0.x;
            qh[i][kk][1] = u8.x;
            qh[i][kk][2] = u0.y;
            qh[i][kk][3] = u8.y;
        }
    }

    // fp32 accumulators; j=8 is the ones column (l accumulator)
    float oacc[2][9][4];
#pragma unroll
    for (int i = 0; i < 2; i++)
#pragma unroll
        for (int j = 0; j < 9; j++)
#pragma unroll
            for (int k = 0; k < 4; k++) oacc[i][j][k] = 0.f;

    for (int it = 0; it < nt; it++) {
        if (it + 1 < nt) { asm volatile("cp.async.wait_group 1;"); }
        else             { asm volatile("cp.async.wait_group 0;"); }
        __syncthreads();

        char* buf = sm + (it & 1) * ABUF;

        // ---- S = Q @ K^T ----
        float sacc[2][8][4];
#pragma unroll
        for (int i = 0; i < 2; i++)
#pragma unroll
            for (int j = 0; j < 8; j++)
#pragma unroll
                for (int k = 0; k < 4; k++) sacc[i][j][k] = 0.f;

#pragma unroll
        for (int kk = 0; kk < 4; kk++) {
#pragma unroll
            for (int j = 0; j < 8; j++) {
                uint2 kv = *(const uint2*)(buf + AK + (8 * j + g) * ARS + kk * 32 + t * 8);
                mma_f16(sacc[0][j], qh[0][kk], (const uint32_t*)&kv);
                mma_f16(sacc[1][j], qh[1][kk], (const uint32_t*)&kv);
            }
        }

        // ---- p = ex2(s) ----
#pragma unroll
        for (int i = 0; i < 2; i++)
#pragma unroll
            for (int j = 0; j < 8; j++) {
                sacc[i][j][0] = ex2(sacc[i][j][0]);
                sacc[i][j][1] = ex2(sacc[i][j][1]);
                sacc[i][j][2] = ex2(sacc[i][j][2]);
                sacc[i][j][3] = ex2(sacc[i][j][3]);
            }

        // ---- pack P, apply fp16 mask multiply ----
        uint32_t ph[2][4][4];
#pragma unroll
        for (int s = 0; s < 4; s++) {
            uint32_t m0 = *(const uint32_t*)(buf + AMS + s * 32 + t * 4);
            uint32_t m1 = *(const uint32_t*)(buf + AMS + s * 32 + t * 4 + 16);
#pragma unroll
            for (int i = 0; i < 2; i++) {
                const float* pa = sacc[i][2 * s];
                const float* pb = sacc[i][2 * s + 1];
                ph[i][s][0] = hmul2u(packh2(pa[0], pa[1]), m0);
                ph[i][s][1] = hmul2u(packh2(pa[2], pa[3]), m0);
                ph[i][s][2] = hmul2u(packh2(pb[0], pb[1]), m1);
                ph[i][s][3] = hmul2u(packh2(pb[2], pb[3]), m1);
            }
        }

        // ---- O += P @ V  (9th n-tile = ones column -> l) ----
#pragma unroll
        for (int s = 0; s < 4; s++) {
#pragma unroll
            for (int j = 0; j < 9; j++) {
                uint2 vv = *(const uint2*)(buf + AV + (8 * j + g) * ARS + s * 32 + t * 8);
                mma_f16(oacc[0][j], ph[0][s], (const uint32_t*)&vv);
                mma_f16(oacc[1][j], ph[1][s], (const uint32_t*)&vv);
            }
        }

        __syncthreads();
        if (it + 2 < nt) {
            size_t kaK = (size_t)(it + 2) * KADV;
            size_t kaV = (size_t)(it + 2) * 128;
            uint32_t db = sb + (it & 1) * ABUF;
#pragma unroll
            for (int q = 0; q < 8; q++)
                cp16(db + cdst[q], csrc[q] + ((q < 4) ? kaK : kaV));
            if (tid < 8) cp16(db + AMS + tid * 16, msrc + (size_t)(it + 2) * 128);
        }
        asm volatile("cp.async.commit_group;");
    }

    // l lives in oacc[i][8][0]/[2] of the t=0 lane of each quad; broadcast + write
#pragma unroll
    for (int i = 0; i < 2; i++) {
        float l0 = __shfl_sync(0xffffffffu, oacc[i][8][0], lane & ~3);
        float l1 = __shfl_sync(0xffffffffu, oacc[i][8][2], lane & ~3);
        float inv0 = 1.f / l0;
        float inv1 = 1.f / l1;
        int row0 = q0 + wid * 32 + 16 * i + g;
#pragma unroll
        for (int j = 0; j < 8; j++) {
            int col = h * DH + 8 * j + 2 * t;
            *(float2*)(O + (size_t)(b * Sq + row0) * HS + col) =
                make_float2(oacc[i][j][0] * inv0, oacc[i][j][1] * inv0);
            *(float2*)(O + (size_t)(b * Sq + row0 + 8) * HS + col) =
                make_float2(oacc[i][j][2] * inv1, oacc[i][j][3] * inv1);
        }
    }
}

// ==================== fused residual add + LayerNorm (merged) ====================
__global__ __launch_bounds__(256) void add_ln_all(
    const float* __restrict__ xc, const float* __restrict__ Ac,
    const float* __restrict__ xe, const float* __restrict__ Ae,
    const float* __restrict__ g, const float* __restrict__ bb,
    float* __restrict__ out)
{
    int row = blockIdx.x;
    const float *x, *att;
    if (row < B * SC) { x = xc + (size_t)row * HS; att = Ac + (size_t)row * HS; }
    else {
        int r = row - B * SC;
        x = xe + (size_t)r * HS; att = Ae + (size_t)r * HS;
    }
    int tid = threadIdx.x;
    float4 xv = ((const float4*)x)[tid];
    float4 av = ((const float4*)att)[tid];
    float v0 = xv.x + av.x, v1 = xv.y + av.y, v2 = xv.z + av.z, v3 = xv.w + av.w;

    float s = v0 + v1 + v2 + v3;
    float sq = v0 * v0 + v1 * v1 + v2 * v2 + v3 * v3;
#pragma unroll
    for (int off = 16; off > 0; off >>= 1) {
        s  += __shfl_xor_sync(0xffffffffu, s, off);
        sq += __shfl_xor_sync(0xffffffffu, sq, off);
    }
    __shared__ float ss[8], ssq[8];
    int wid = tid >> 5, lane = tid & 31;
    if (lane == 0) { ss[wid] = s; ssq[wid] = sq; }
    __syncthreads();
    s = 0.f; sq = 0.f;
#pragma unroll
    for (int w = 0; w < 8; w++) { s += ss[w]; sq += ssq[w]; }

    float mu = s * (1.f / HS);
    float var = sq * (1.f / HS) - mu * mu;
    float r = rsqrtf(var + 1e-5f);

    float4 gv = ((const float4*)g)[tid];
    float4 bv = ((const float4*)bb)[tid];
    float4 ov = make_float4((v0 - mu) * r * gv.x + bv.x,
                            (v1 - mu) * r * gv.y + bv.y,
                            (v2 - mu) * r * gv.z + bv.z,
                            (v3 - mu) * r * gv.w + bv.w);
    ((float4*)(out + (size_t)row * HS))[tid] = ov;
}

// ==================== launcher ====================
extern "C" void kernel_launch(void* const* d_in, const int* in_sizes, int n_in,
                              void* d_out, int out_size)
{
    (void)in_sizes; (void)n_in; (void)out_size;
    const float* x_c   = (const float*)d_in[0];
    const float* x_e   = (const float*)d_in[1];
    const int*   msk_c = (const int*)d_in[2];
    const int*   msk_e = (const int*)d_in[3];
    const float* W_cq = (const float*)d_in[4];  const float* b_cq = (const float*)d_in[5];
    const float* W_ek = (const float*)d_in[6];  const float* b_ek = (const float*)d_in[7];
    const float* W_ev = (const float*)d_in[8];  const float* b_ev = (const float*)d_in[9];
    const float* W_eq = (const float*)d_in[10]; const float* b_eq = (const float*)d_in[11];
    const float* W_ck = (const float*)d_in[12]; const float* b_ck = (const float*)d_in[13];
    const float* W_cv = (const float*)d_in[14]; const float* b_cv = (const float*)d_in[15];
    const float* ln_g = (const float*)d_in[16]; const float* ln_b = (const float*)d_in[17];
    float* out = (float*)d_out;

    float *Ac, *Ae;
    cudaGetSymbolAddress((void**)&Ac, g_Ac);
    cudaGetSymbolAddress((void**)&Ae, g_Ae);
    __half *xch, *xeh, *Wch, *Weh, *mhc, *mhe;
    cudaGetSymbolAddress((void**)&xch, g_xch);
    cudaGetSymbolAddress((void**)&xeh, g_xeh);
    cudaGetSymbolAddress((void**)&Wch, g_Wch);
    cudaGetSymbolAddress((void**)&Weh, g_Weh);
    cudaGetSymbolAddress((void**)&mhc, g_mhc);
    cudaGetSymbolAddress((void**)&mhe, g_mhe);
    __half *Q16c, *K16c, *V16c, *Q16e, *K16e, *V16e, *Vtc16, *Vte16;
    cudaGetSymbolAddress((void**)&Q16c, g_Q16c);
    cudaGetSymbolAddress((void**)&K16c, g_K16c);
    cudaGetSymbolAddress((void**)&V16c, g_V16c);
    cudaGetSymbolAddress((void**)&Q16e, g_Q16e);
    cudaGetSymbolAddress((void**)&K16e, g_K16e);
    cudaGetSymbolAddress((void**)&V16e, g_V16e);
    cudaGetSymbolAddress((void**)&Vtc16, g_Vtc16);
    cudaGetSymbolAddress((void**)&Vte16, g_Vte16);

    cudaFuncSetAttribute(gemm_f16, cudaFuncAttributeMaxDynamicSharedMemorySize, G_SMEM);
    cudaFuncSetAttribute(attn_all, cudaFuncAttributeMaxDynamicSharedMemorySize, ASMEM);

    const int Mc = B * SC;   // 2048
    const int Me = B * SE;   // 8192

    cvt_all<<<8192 + 10, 256>>>(W_cq, W_ck, W_cv, W_eq, W_ek, W_ev, x_c, x_e,
                                msk_c, msk_e, Wch, Weh, xch, xeh, mhc, mhe);

    gemm_f16<<<dim3(8, Me / 128, 6), 128, G_SMEM>>>(
        xeh, Weh, xch, Wch,
        b_eq, b_ek, b_ev, b_cq, b_ck, b_cv,
        Q16e, K16e, V16e, Q16c, K16c, V16c);

    prep_v<<<dim3(SC / 64 + SE / 64, NH, B), 256>>>(V16c, Vtc16, V16e, Vte16);

    attn_all<<<dim3(SC / 128 + SE / 128, NH, B), 128, ASMEM>>>(
        Q16c, K16e, Vte16, mhe, Ac,
        Q16e, K16c, Vtc16, mhc, Ae);

    add_ln_all<<<Mc + Me, 256>>>(x_c, Ac, x_e, Ae, ln_g, ln_b, out);
}

// round 16
// speedup vs baseline: 1.2212x; 1.0291x over previous
#include <cuda_runtime.h>
#include <cuda_fp16.h>
#include <cstdint>

#define HS 1024
#define NH 16
#define DH 64
#define B 4
#define SC 512
#define SE 2048

// -------------------- scratch (device globals; no allocation) --------------------
__device__ float g_Ac[(size_t)B * SC * HS];
__device__ float g_Ae[(size_t)B * SE * HS];
// fp16 preconverted GEMM operands (k-dim permuted within 16-groups)
__device__ __align__(256) __half g_xch[(size_t)B * SC * HS];
__device__ __align__(256) __half g_xeh[(size_t)B * SE * HS];
__device__ __align__(256) __half g_Wch[(size_t)3 * HS * HS];   // W_cq|W_ck|W_cv
__device__ __align__(256) __half g_Weh[(size_t)3 * HS * HS];   // W_eq|W_ek|W_ev
// fp16 GEMM outputs: Q (CSC-scaled, kperm cols), K (kperm cols), V (plain)
__device__ __align__(256) __half g_Q16c[(size_t)B * SC * HS];
__device__ __align__(256) __half g_K16c[(size_t)B * SC * HS];
__device__ __align__(256) __half g_V16c[(size_t)B * SC * HS];
__device__ __align__(256) __half g_Q16e[(size_t)B * SE * HS];
__device__ __align__(256) __half g_K16e[(size_t)B * SE * HS];
__device__ __align__(256) __half g_V16e[(size_t)B * SE * HS];
// fp16 V-transposed per head (seq-permuted)
__device__ __align__(256) __half g_Vtc16[(size_t)B * NH * SC * DH];
__device__ __align__(256) __half g_Vte16[(size_t)B * NH * SE * DH];
// fp16 masks (0.0 / 1.0)
__device__ __align__(256) __half g_mhc[(size_t)B * SC];
__device__ __align__(256) __half g_mhe[(size_t)B * SE];

// ==================== helpers ====================
__device__ __forceinline__ void mma_f16(float* d, const uint32_t* a, const uint32_t* b) {
    asm volatile(
        "mma.sync.aligned.m16n8k16.row.col.f32.f16.f16.f32 "
        "{%0,%1,%2,%3}, {%4,%5,%6,%7}, {%8,%9}, {%0,%1,%2,%3};"
        : "+f"(d[0]), "+f"(d[1]), "+f"(d[2]), "+f"(d[3])
        : "r"(a[0]), "r"(a[1]), "r"(a[2]), "r"(a[3]), "r"(b[0]), "r"(b[1]));
}

// fp16-accumulator MMA: d[0] packs {row g: c0,c1}, d[1] packs {row g+8: c0,c1}
__device__ __forceinline__ void mma_f16acc(uint32_t* d, const uint32_t* a, const uint32_t* b) {
    asm volatile(
        "mma.sync.aligned.m16n8k16.row.col.f16.f16.f16.f16 "
        "{%0,%1}, {%2,%3,%4,%5}, {%6,%7}, {%0,%1};"
        : "+r"(d[0]), "+r"(d[1])
        : "r"(a[0]), "r"(a[1]), "r"(a[2]), "r"(a[3]), "r"(b[0]), "r"(b[1]));
}

__device__ __forceinline__ uint32_t packh2(float a, float b) {
    __half2 h = __floats2half2_rn(a, b);
    return *(uint32_t*)&h;
}

__device__ __forceinline__ uint32_t hmul2u(uint32_t a, uint32_t b) {
    __half2 r = __hmul2(*(__half2*)&a, *(__half2*)&b);
    return *(uint32_t*)&r;
}

__device__ __forceinline__ uint32_t smem_u32(const void* p) {
    uint32_t a;
    asm("{ .reg .u64 t; cvta.to.shared.u64 t, %1; cvt.u32.u64 %0, t; }" : "=r"(a) : "l"(p));
    return a;
}

__device__ __forceinline__ void cp16(uint32_t dst, const void* src) {
    asm volatile("cp.async.cg.shared.global [%0], [%1], 16;" :: "r"(dst), "l"(src));
}

// packed-fp16 hardware exp2: 2 values per lane per issue
__device__ __forceinline__ uint32_t ex2h2(uint32_t x) {
    uint32_t r;
    asm("ex2.approx.f16x2 %0, %1;" : "=r"(r) : "r"(x));
    return r;
}

// k-dim pair permutation (within 16-element groups)
__device__ __forceinline__ int kperm(int c) {
    return (c >> 4) * 16 + (((c & 7) >> 1) << 2) + (((c >> 3) & 1) << 1);
}

#define CSC 0.1803368801111694f   // log2(e)/8

// ==================== merged convert: weights + activations + masks ==============
__global__ __launch_bounds__(256) void cvt_all(
    const float* __restrict__ Wcq, const float* __restrict__ Wck,
    const float* __restrict__ Wcv, const float* __restrict__ Weq,
    const float* __restrict__ Wek, const float* __restrict__ Wev,
    const float* __restrict__ xc, const float* __restrict__ xe,
    const int* __restrict__ mc, const int* __restrict__ me,
    __half* __restrict__ dWc, __half* __restrict__ dWe,
    __half* __restrict__ dxc, __half* __restrict__ dxe,
    __half* __restrict__ dmc, __half* __restrict__ dme)
{
    int bid = blockIdx.x;
    if (bid >= 8192) {   // mask conversion: 10240 ints total, 4 per thread
        int idx = (bid - 8192) * 256 + threadIdx.x;
        int base = idx * 4;
        const int* src;
        __half* dst;
        if (base < B * SC) { src = mc + base; dst = dmc + base; }
        else { base -= B * SC; src = me + base; dst = dme + base; }
        int4 v = *(const int4*)src;
        uint2 o;
        o.x = packh2(v.x ? 1.f : 0.f, v.y ? 1.f : 0.f);
        o.y = packh2(v.z ? 1.f : 0.f, v.w ? 1.f : 0.f);
        *(uint2*)dst = o;
        return;
    }

    const float* s;
    __half* d;
    int i;
    if (bid < 3072) {
        int z = bid >> 9;
        const float* Ws[6] = {Wcq, Wck, Wcv, Weq, Wek, Wev};
        s = Ws[z];
        d = (z < 3) ? (dWc + ((size_t)z << 20)) : (dWe + ((size_t)(z - 3) << 20));
        i = (bid & 511) * 256 + threadIdx.x;
    } else if (bid < 4096) {
        s = xc; d = dxc;
        i = (bid - 3072) * 256 + threadIdx.x;
    } else {
        s = xe; d = dxe;
        i = (bid - 4096) * 256 + threadIdx.x;
    }
    int op = 4 * i;
    int grp = op >> 3;
    int j0 = op & 7;
    const float2* sp = (const float2*)s + (size_t)grp * 8;
    uint4 o;
    {
        int p0 = 4 * ((j0 + 0) & 1) + ((j0 + 0) >> 1);
        int p1 = 4 * ((j0 + 1) & 1) + ((j0 + 1) >> 1);
        int p2 = 4 * ((j0 + 2) & 1) + ((j0 + 2) >> 1);
        int p3 = 4 * ((j0 + 3) & 1) + ((j0 + 3) >> 1);
        float2 v0 = sp[p0], v1 = sp[p1], v2 = sp[p2], v3 = sp[p3];
        o.x = packh2(v0.x, v0.y);
        o.y = packh2(v1.x, v1.y);
        o.z = packh2(v2.x, v2.y);
        o.w = packh2(v3.x, v3.y);
    }
    ((uint4*)d)[i] = o;
}

// ==================== GEMM: fp16 acc, fp16 consumer-layout outputs ===============
#define G_RS    96
#define G_A     0
#define G_B     (128 * G_RS)          // 12288
#define G_STAGE (256 * G_RS)          // 24576
#define G_SMEM  (3 * G_STAGE)         // 73728

__global__ __launch_bounds__(128, 3) void gemm_f16(
    const __half* __restrict__ xeh, const __half* __restrict__ Weh,
    const __half* __restrict__ xch, const __half* __restrict__ Wch,
    const float* __restrict__ beq, const float* __restrict__ bek,
    const float* __restrict__ bev,
    const float* __restrict__ bcq, const float* __restrict__ bck,
    const float* __restrict__ bcv,
    __half* __restrict__ Qe, __half* __restrict__ Ke, __half* __restrict__ Ve,
    __half* __restrict__ Qc, __half* __restrict__ Kc, __half* __restrict__ Vc)
{
    const int z = blockIdx.z;
    const __half *Ah, *Wz;
    __half* D;
    const float* bias;
    int zm;
    if (z < 3) {
        zm = z;
        Ah = xeh;
        Wz = Weh + ((size_t)z << 20);
        D = (z == 0) ? Qe : ((z == 1) ? Ke : Ve);
        bias = (z == 0) ? beq : ((z == 1) ? bek : bev);
    } else {
        if (blockIdx.y >= (B * SC) / 128) return;
        zm = z - 3;
        Ah = xch;
        Wz = Wch + ((size_t)zm << 20);
        D = (zm == 0) ? Qc : ((zm == 1) ? Kc : Vc);
        bias = (zm == 0) ? bcq : ((zm == 1) ? bck : bcv);
    }
    const float scale = (zm == 0) ? CSC : 1.f;
    const bool doperm = (zm != 2);

    extern __shared__ char smem[];
    const uint32_t sb = smem_u32(smem);
    const int tid = threadIdx.x;
    const int wid = tid >> 5;
    const int lane = tid & 31;
    const int g = lane >> 2;
    const int t = lane & 3;
    const int wm = wid >> 1;
    const int wn = wid & 1;
    const int bm = blockIdx.y * 128;
    const int bn = blockIdx.x * 128;

    const char* csrc[8];
    uint32_t cdst[8];
#pragma unroll
    for (int q = 0; q < 8; q++) {
        int f = q * 128 + tid;
        int tile = f >> 9;
        int idx = f & 511;
        int r = idx >> 2, c = idx & 3;
        cdst[q] = (uint32_t)(tile * G_B + r * G_RS + c * 16);
        if (tile == 0) csrc[q] = (const char*)(Ah + (size_t)(bm + r) * HS + c * 8);
        else           csrc[q] = (const char*)(Wz + (size_t)(bn + r) * HS + c * 8);
    }

    const int NC = HS / 32;

#pragma unroll
    for (int st = 0; st < 3; st++) {
        uint32_t db = sb + st * G_STAGE;
#pragma unroll
        for (int q = 0; q < 8; q++)
            cp16(db + cdst[q], csrc[q] + st * 64);
        asm volatile("cp.async.commit_group;");
    }

    uint32_t acc[4][8][2];
#pragma unroll
    for (int i = 0; i < 4; i++)
#pragma unroll
        for (int j = 0; j < 8; j++) {
            acc[i][j][0] = 0u;
            acc[i][j][1] = 0u;
        }

    for (int c = 0; c < NC; c++) {
        asm volatile("cp.async.wait_group 2;");
        __syncthreads();

        const char* buf = smem + (c % 3) * G_STAGE;
#pragma unroll
        for (int s = 0; s < 2; s++) {
            const int kb = s * 32 + t * 8;
            uint32_t ah[4][4];
#pragma unroll
            for (int i = 0; i < 4; i++) {
                const char* pa = buf + G_A + (wm * 64 + 16 * i + g) * G_RS + kb;
                uint2 alo = *(const uint2*)(pa);
                uint2 ahi = *(const uint2*)(pa + 8 * G_RS);
                ah[i][0] = alo.x;
                ah[i][1] = ahi.x;
                ah[i][2] = alo.y;
                ah[i][3] = ahi.y;
            }
#pragma unroll
            for (int j = 0; j < 8; j++) {
                uint2 bv = *(const uint2*)(buf + G_B + (wn * 64 + 8 * j + g) * G_RS + kb);
#pragma unroll
                for (int i = 0; i < 4; i++)
                    mma_f16acc(acc[i][j], ah[i], (const uint32_t*)&bv);
            }
        }
        __syncthreads();

        if (c + 3 < NC) {
            uint32_t db = sb + ((c + 3) % 3) * G_STAGE;
            int koff = (c + 3) * 64;
#pragma unroll
            for (int q = 0; q < 8; q++)
                cp16(db + cdst[q], csrc[q] + koff);
        }
        asm volatile("cp.async.commit_group;");
    }

    // epilogue: fp16 acc + bias (+scale), store fp16 at (optionally kperm'd) cols
#pragma unroll
    for (int i = 0; i < 4; i++) {
        int row0 = bm + wm * 64 + 16 * i + g;
#pragma unroll
        for (int j = 0; j < 8; j++) {
            int c = bn + wn * 64 + 8 * j + 2 * t;
            float2 bv2 = *(const float2*)(bias + c);
            float2 lo = __half22float2(*(__half2*)&acc[i][j][0]);
            float2 hi = __half22float2(*(__half2*)&acc[i][j][1]);
            uint32_t w0 = packh2((lo.x + bv2.x) * scale, (lo.y + bv2.y) * scale);
            uint32_t w1 = packh2((hi.x + bv2.x) * scale, (hi.y + bv2.y) * scale);
            int oc = doperm ? kperm(c) : c;
            *(uint32_t*)(D + (size_t)row0 * HS + oc) = w0;
            *(uint32_t*)(D + (size_t)(row0 + 8) * HS + oc) = w1;
        }
    }
}

// ==================== V prep: fp16 transpose, seq-dim kperm ====================
__global__ __launch_bounds__(256) void prep_v(
    const __half* __restrict__ Vc, __half* __restrict__ Vtc,
    const __half* __restrict__ Ve, __half* __restrict__ Vte)
{
    __shared__ __half vs[64][66];
    const int tid = threadIdx.x;
    const int b = blockIdx.z, h = blockIdx.y;
    const int bh = b * NH + h;

    const __half* V;
    __half* Vt;
    int Sk, s0;
    if (blockIdx.x < SC / 64) {
        V = Vc; Vt = Vtc; Sk = SC;
        s0 = blockIdx.x * 64;
    } else {
        V = Ve; Vt = Vte; Sk = SE;
        s0 = (blockIdx.x - SC / 64) * 64;
    }

#pragma unroll
    for (int i = 0; i < 4; i++) {
        int f = tid + 256 * i;
        int r = f >> 4, cu = f & 15;
        uint2 v = *(const uint2*)(V + (size_t)(b * Sk + s0 + r) * HS + h * DH + cu * 4);
        *(uint32_t*)&vs[r][cu * 4] = v.x;
        *(uint32_t*)&vs[r][cu * 4 + 2] = v.y;
    }
    __syncthreads();
#pragma unroll
    for (int i = 0; i < 8; i++) {
        int f = tid + 256 * i;
        int d = f >> 5, sp = f & 31;
        __half2 pr(vs[2 * sp][d], vs[2 * sp + 1][d]);
        size_t o = ((size_t)(bh * DH + d)) * Sk + s0 + kperm(2 * sp);
        *(uint32_t*)(Vt + o) = *(uint32_t*)&pr;
    }
}

// ==================== attention: fp16 S acc + ex2.f16x2, fp32 oacc ===============
#define AK    0
#define AV    10240               // 72 rows x 160 (rows 64..71 = ones/zero pad)
#define AMS   21760               // 64 fp16 mask values (128B)
#define ABUF  22016
#define ASMEM (2 * ABUF)          // 44032
#define ARS   160

__global__ __launch_bounds__(128, 2) void attn_all(
    const __half* __restrict__ Q16c, const __half* __restrict__ K16e,
    const __half* __restrict__ Vte, const __half* __restrict__ me,
    float* __restrict__ Ac,
    const __half* __restrict__ Q16e, const __half* __restrict__ K16c,
    const __half* __restrict__ Vtc, const __half* __restrict__ mc,
    float* __restrict__ Ae)
{
    extern __shared__ char sm[];
    const uint32_t sb = smem_u32(sm);
    const int tid = threadIdx.x;
    const int wid = tid >> 5;
    const int lane = tid & 31;
    const int g = lane >> 2;
    const int t = lane & 3;
    const int b = blockIdx.z, h = blockIdx.y;
    const int bx = blockIdx.x;
    const int bh = b * NH + h;

    const __half* Q;
    const __half* K;
    const __half* Vt;
    const __half* mask;
    float* O;
    int Sq, Sk, q0;
    if (bx < SC / 128) {
        Q = Q16c; K = K16e; Vt = Vte; mask = me; O = Ac;
        Sq = SC; Sk = SE; q0 = bx * 128;
    } else {
        Q = Q16e; K = K16c; Vt = Vtc; mask = mc; O = Ae;
        Sq = SE; Sk = SC; q0 = (bx - SC / 128) * 128;
    }
    const int nt = Sk / 64;
    const size_t KADV = (size_t)64 * HS * 2;   // K bytes per 64-row tile

    const char* csrc[8];
    uint32_t cdst[8];
#pragma unroll
    for (int q = 0; q < 8; q++) {
        int f = q * 128 + tid;
        int tile = f >> 9;
        int idx = f & 511;
        int r = idx >> 3, c = idx & 7;
        if (tile == 0) {
            csrc[q] = (const char*)(K + ((size_t)(b * Sk) + r) * HS + h * DH + c * 8);
            cdst[q] = AK + (uint32_t)(r * ARS + c * 16);
        } else {
            csrc[q] = (const char*)(Vt + (size_t)(bh * DH + r) * (size_t)Sk + c * 8);
            cdst[q] = AV + (uint32_t)(r * ARS + c * 16);
        }
    }
    const char* msrc = (const char*)(mask + (size_t)b * Sk) + tid * 16;

    {
#pragma unroll
        for (int q = 0; q < 8; q++)
            cp16(sb + cdst[q], csrc[q]);
        if (tid < 8) cp16(sb + AMS + tid * 16, msrc);
        asm volatile("cp.async.commit_group;");
    }

    // init ones/zero pad rows 64..71 of both V buffers
    {
        int row = 64 + (tid >> 4);
        int off = (tid & 15) * 8;
        uint2 val = (row == 64) ? make_uint2(0x3C003C00u, 0x3C003C00u)
                                : make_uint2(0u, 0u);
        *(uint2*)(sm + AV + row * ARS + off) = val;
        *(uint2*)(sm + ABUF + AV + row * ARS + off) = val;
    }

    if (nt > 1) {
#pragma unroll
        for (int q = 0; q < 8; q++)
            cp16(sb + ABUF + cdst[q], csrc[q] + ((q < 4) ? KADV : 128));
        if (tid < 8) cp16(sb + ABUF + AMS + tid * 16, msrc + 128);
    }
    asm volatile("cp.async.commit_group;");

    // Q fragments (2 m16 tiles per warp): fp16, CSC-prescaled, kperm'd cols
    uint32_t qh[2][4][4];
#pragma unroll
    for (int i = 0; i < 2; i++) {
        const __half* qp0 = Q + (size_t)(b * Sq + q0 + wid * 32 + 16 * i + g) * HS + h * DH;
        const __half* qp8 = qp0 + 8 * HS;
#pragma unroll
        for (int kk = 0; kk < 4; kk++) {
            uint2 u0 = *(const uint2*)(qp0 + 16 * kk + 4 * t);
            uint2 u8 = *(const uint2*)(qp8 + 16 * kk + 4 * t);
            qh[i][kk][0] = u0.x;
            qh[i][kk][1] = u8.x;
            qh[i][kk][2] = u0.y;
            qh[i][kk][3] = u8.y;
        }
    }

    // fp32 accumulators; j=8 is the ones column (l accumulator)
    float oacc[2][9][4];
#pragma unroll
    for (int i = 0; i < 2; i++)
#pragma unroll
        for (int j = 0; j < 9; j++)
#pragma unroll
            for (int k = 0; k < 4; k++) oacc[i][j][k] = 0.f;

    for (int it = 0; it < nt; it++) {
        if (it + 1 < nt) { asm volatile("cp.async.wait_group 1;"); }
        else             { asm volatile("cp.async.wait_group 0;"); }
        __syncthreads();

        char* buf = sm + (it & 1) * ABUF;

        // ---- S = Q @ K^T (fp16 acc: values already packed as half2) ----
        uint32_t sacc[2][8][2];
#pragma unroll
        for (int i = 0; i < 2; i++)
#pragma unroll
            for (int j = 0; j < 8; j++) {
                sacc[i][j][0] = 0u;
                sacc[i][j][1] = 0u;
            }

#pragma unroll
        for (int kk = 0; kk < 4; kk++) {
#pragma unroll
            for (int j = 0; j < 8; j++) {
                uint2 kv = *(const uint2*)(buf + AK + (8 * j + g) * ARS + kk * 32 + t * 8);
                mma_f16acc(sacc[0][j], qh[0][kk], (const uint32_t*)&kv);
                mma_f16acc(sacc[1][j], qh[1][kk], (const uint32_t*)&kv);
            }
        }

        // ---- P = ex2(S) * mask : packed fp16 throughout ----
        // sacc[i][2s][0] = {row g, keys 16s+2t,+1}  -> ph[i][s][0]
        // sacc[i][2s][1] = {row g+8, same keys}     -> ph[i][s][1]
        // sacc[i][2s+1][0/1] = keys 16s+8+2t        -> ph[i][s][2/3]
        uint32_t ph[2][4][4];
#pragma unroll
        for (int s = 0; s < 4; s++) {
            uint32_t m0 = *(const uint32_t*)(buf + AMS + s * 32 + t * 4);
            uint32_t m1 = *(const uint32_t*)(buf + AMS + s * 32 + t * 4 + 16);
#pragma unroll
            for (int i = 0; i < 2; i++) {
                ph[i][s][0] = hmul2u(ex2h2(sacc[i][2 * s][0]), m0);
                ph[i][s][1] = hmul2u(ex2h2(sacc[i][2 * s][1]), m0);
                ph[i][s][2] = hmul2u(ex2h2(sacc[i][2 * s + 1][0]), m1);
                ph[i][s][3] = hmul2u(ex2h2(sacc[i][2 * s + 1][1]), m1);
            }
        }

        // ---- O += P @ V  (9th n-tile = ones column -> l) ----
#pragma unroll
        for (int s = 0; s < 4; s++) {
#pragma unroll
            for (int j = 0; j < 9; j++) {
                uint2 vv = *(const uint2*)(buf + AV + (8 * j + g) * ARS + s * 32 + t * 8);
                mma_f16(oacc[0][j], ph[0][s], (const uint32_t*)&vv);
                mma_f16(oacc[1][j], ph[1][s], (const uint32_t*)&vv);
            }
        }

        __syncthreads();
        if (it + 2 < nt) {
            size_t kaK = (size_t)(it + 2) * KADV;
            size_t kaV = (size_t)(it + 2) * 128;
            uint32_t db = sb + (it & 1) * ABUF;
#pragma unroll
            for (int q = 0; q < 8; q++)
                cp16(db + cdst[q], csrc[q] + ((q < 4) ? kaK : kaV));
            if (tid < 8) cp16(db + AMS + tid * 16, msrc + (size_t)(it + 2) * 128);
        }
        asm volatile("cp.async.commit_group;");
    }

    // l lives in oacc[i][8][0]/[2] of the t=0 lane of each quad; broadcast + write
#pragma unroll
    for (int i = 0; i < 2; i++) {
        float l0 = __shfl_sync(0xffffffffu, oacc[i][8][0], lane & ~3);
        float l1 = __shfl_sync(0xffffffffu, oacc[i][8][2], lane & ~3);
        float inv0 = 1.f / l0;
        float inv1 = 1.f / l1;
        int row0 = q0 + wid * 32 + 16 * i + g;
#pragma unroll
        for (int j = 0; j < 8; j++) {
            int col = h * DH + 8 * j + 2 * t;
            *(float2*)(O + (size_t)(b * Sq + row0) * HS + col) =
                make_float2(oacc[i][j][0] * inv0, oacc[i][j][1] * inv0);
            *(float2*)(O + (size_t)(b * Sq + row0 + 8) * HS + col) =
                make_float2(oacc[i][j][2] * inv1, oacc[i][j][3] * inv1);
        }
    }
}

// ==================== fused residual add + LayerNorm (merged) ====================
__global__ __launch_bounds__(256) void add_ln_all(
    const float* __restrict__ xc, const float* __restrict__ Ac,
    const float* __restrict__ xe, const float* __restrict__ Ae,
    const float* __restrict__ g, const float* __restrict__ bb,
    float* __restrict__ out)
{
    int row = blockIdx.x;
    const float *x, *att;
    if (row < B * SC) { x = xc + (size_t)row * HS; att = Ac + (size_t)row * HS; }
    else {
        int r = row - B * SC;
        x = xe + (size_t)r * HS; att = Ae + (size_t)r * HS;
    }
    int tid = threadIdx.x;
    float4 xv = ((const float4*)x)[tid];
    float4 av = ((const float4*)att)[tid];
    float v0 = xv.x + av.x, v1 = xv.y + av.y, v2 = xv.z + av.z, v3 = xv.w + av.w;

    float s = v0 + v1 + v2 + v3;
    float sq = v0 * v0 + v1 * v1 + v2 * v2 + v3 * v3;
#pragma unroll
    for (int off = 16; off > 0; off >>= 1) {
        s  += __shfl_xor_sync(0xffffffffu, s, off);
        sq += __shfl_xor_sync(0xffffffffu, sq, off);
    }
    __shared__ float ss[8], ssq[8];
    int wid = tid >> 5, lane = tid & 31;
    if (lane == 0) { ss[wid] = s; ssq[wid] = sq; }
    __syncthreads();
    s = 0.f; sq = 0.f;
#pragma unroll
    for (int w = 0; w < 8; w++) { s += ss[w]; sq += ssq[w]; }

    float mu = s * (1.f / HS);
    float var = sq * (1.f / HS) - mu * mu;
    float r = rsqrtf(var + 1e-5f);

    float4 gv = ((const float4*)g)[tid];
    float4 bv = ((const float4*)bb)[tid];
    float4 ov = make_float4((v0 - mu) * r * gv.x + bv.x,
                            (v1 - mu) * r * gv.y + bv.y,
                            (v2 - mu) * r * gv.z + bv.z,
                            (v3 - mu) * r * gv.w + bv.w);
    ((float4*)(out + (size_t)row * HS))[tid] = ov;
}

// ==================== launcher ====================
extern "C" void kernel_launch(void* const* d_in, const int* in_sizes, int n_in,
                              void* d_out, int out_size)
{
    (void)in_sizes; (void)n_in; (void)out_size;
    const float* x_c   = (const float*)d_in[0];
    const float* x_e   = (const float*)d_in[1];
    const int*   msk_c = (const int*)d_in[2];
    const int*   msk_e = (const int*)d_in[3];
    const float* W_cq = (const float*)d_in[4];  const float* b_cq = (const float*)d_in[5];
    const float* W_ek = (const float*)d_in[6];  const float* b_ek = (const float*)d_in[7];
    const float* W_ev = (const float*)d_in[8];  const float* b_ev = (const float*)d_in[9];
    const float* W_eq = (const float*)d_in[10]; const float* b_eq = (const float*)d_in[11];
    const float* W_ck = (const float*)d_in[12]; const float* b_ck = (const float*)d_in[13];
    const float* W_cv = (const float*)d_in[14]; const float* b_cv = (const float*)d_in[15];
    const float* ln_g = (const float*)d_in[16]; const float* ln_b = (const float*)d_in[17];
    float* out = (float*)d_out;

    float *Ac, *Ae;
    cudaGetSymbolAddress((void**)&Ac, g_Ac);
    cudaGetSymbolAddress((void**)&Ae, g_Ae);
    __half *xch, *xeh, *Wch, *Weh, *mhc, *mhe;
    cudaGetSymbolAddress((void**)&xch, g_xch);
    cudaGetSymbolAddress((void**)&xeh, g_xeh);
    cudaGetSymbolAddress((void**)&Wch, g_Wch);
    cudaGetSymbolAddress((void**)&Weh, g_Weh);
    cudaGetSymbolAddress((void**)&mhc, g_mhc);
    cudaGetSymbolAddress((void**)&mhe, g_mhe);
    __half *Q16c, *K16c, *V16c, *Q16e, *K16e, *V16e, *Vtc16, *Vte16;
    cudaGetSymbolAddress((void**)&Q16c, g_Q16c);
    cudaGetSymbolAddress((void**)&K16c, g_K16c);
    cudaGetSymbolAddress((void**)&V16c, g_V16c);
    cudaGetSymbolAddress((void**)&Q16e, g_Q16e);
    cudaGetSymbolAddress((void**)&K16e, g_K16e);
    cudaGetSymbolAddress((void**)&V16e, g_V16e);
    cudaGetSymbolAddress((void**)&Vtc16, g_Vtc16);
    cudaGetSymbolAddress((void**)&Vte16, g_Vte16);

    cudaFuncSetAttribute(gemm_f16, cudaFuncAttributeMaxDynamicSharedMemorySize, G_SMEM);
    cudaFuncSetAttribute(attn_all, cudaFuncAttributeMaxDynamicSharedMemorySize, ASMEM);

    const int Mc = B * SC;   // 2048
    const int Me = B * SE;   // 8192

    cvt_all<<<8192 + 10, 256>>>(W_cq, W_ck, W_cv, W_eq, W_ek, W_ev, x_c, x_e,
                                msk_c, msk_e, Wch, Weh, xch, xeh, mhc, mhe);

    gemm_f16<<<dim3(8, Me / 128, 6), 128, G_SMEM>>>(
        xeh, Weh, xch, Wch,
        b_eq, b_ek, b_ev, b_cq, b_ck, b_cv,
        Q16e, K16e, V16e, Q16c, K16c, V16c);

    prep_v<<<dim3(SC / 64 + SE / 64, NH, B), 256>>>(V16c, Vtc16, V16e, Vte16);

    attn_all<<<dim3(SC / 128 + SE / 128, NH, B), 128, ASMEM>>>(
        Q16c, K16e, Vte16, mhe, Ac,
        Q16e, K16c, Vtc16, mhc, Ae);

    add_ln_all<<<Mc + Me, 256>>>(x_c, Ac, x_e, Ae, ln_g, ln_b, out);
}

// round 17
// speedup vs baseline: 1.2262x; 1.0041x over previous
#include <cuda_runtime.h>
#include <cuda_fp16.h>
#include <cstdint>

#define HS 1024
#define NH 16
#define DH 64
#define B 4
#define SC 512
#define SE 2048

// -------------------- scratch (device globals; no allocation) --------------------
__device__ float g_Ac[(size_t)B * SC * HS];
__device__ float g_Ae[(size_t)B * SE * HS];
// fp16 preconverted GEMM operands (k-dim permuted within 16-groups)
__device__ __align__(256) __half g_xch[(size_t)B * SC * HS];
__device__ __align__(256) __half g_xeh[(size_t)B * SE * HS];
__device__ __align__(256) __half g_Wch[(size_t)3 * HS * HS];   // W_cq|W_ck|W_cv
__device__ __align__(256) __half g_Weh[(size_t)3 * HS * HS];   // W_eq|W_ek|W_ev
// fp16 GEMM outputs: Q (CSC-scaled, kperm cols), K (kperm cols), V (plain)
__device__ __align__(256) __half g_Q16c[(size_t)B * SC * HS];
__device__ __align__(256) __half g_K16c[(size_t)B * SC * HS];
__device__ __align__(256) __half g_V16c[(size_t)B * SC * HS];
__device__ __align__(256) __half g_Q16e[(size_t)B * SE * HS];
__device__ __align__(256) __half g_K16e[(size_t)B * SE * HS];
__device__ __align__(256) __half g_V16e[(size_t)B * SE * HS];
// fp16 V-transposed per head (seq-permuted)
__device__ __align__(256) __half g_Vtc16[(size_t)B * NH * SC * DH];
__device__ __align__(256) __half g_Vte16[(size_t)B * NH * SE * DH];
// fp16 masks (0.0 / 1.0)
__device__ __align__(256) __half g_mhc[(size_t)B * SC];
__device__ __align__(256) __half g_mhe[(size_t)B * SE];

// ==================== helpers ====================
__device__ __forceinline__ void mma_f16(float* d, const uint32_t* a, const uint32_t* b) {
    asm volatile(
        "mma.sync.aligned.m16n8k16.row.col.f32.f16.f16.f32 "
        "{%0,%1,%2,%3}, {%4,%5,%6,%7}, {%8,%9}, {%0,%1,%2,%3};"
        : "+f"(d[0]), "+f"(d[1]), "+f"(d[2]), "+f"(d[3])
        : "r"(a[0]), "r"(a[1]), "r"(a[2]), "r"(a[3]), "r"(b[0]), "r"(b[1]));
}

// fp16-accumulator MMA: d[0] packs {row g: c0,c1}, d[1] packs {row g+8: c0,c1}
__device__ __forceinline__ void mma_f16acc(uint32_t* d, const uint32_t* a, const uint32_t* b) {
    asm volatile(
        "mma.sync.aligned.m16n8k16.row.col.f16.f16.f16.f16 "
        "{%0,%1}, {%2,%3,%4,%5}, {%6,%7}, {%0,%1};"
        : "+r"(d[0]), "+r"(d[1])
        : "r"(a[0]), "r"(a[1]), "r"(a[2]), "r"(a[3]), "r"(b[0]), "r"(b[1]));
}

__device__ __forceinline__ uint32_t packh2(float a, float b) {
    __half2 h = __floats2half2_rn(a, b);
    return *(uint32_t*)&h;
}

__device__ __forceinline__ uint32_t hmul2u(uint32_t a, uint32_t b) {
    __half2 r = __hmul2(*(__half2*)&a, *(__half2*)&b);
    return *(uint32_t*)&r;
}

__device__ __forceinline__ uint32_t smem_u32(const void* p) {
    uint32_t a;
    asm("{ .reg .u64 t; cvta.to.shared.u64 t, %1; cvt.u32.u64 %0, t; }" : "=r"(a) : "l"(p));
    return a;
}

__device__ __forceinline__ void cp16(uint32_t dst, const void* src) {
    asm volatile("cp.async.cg.shared.global [%0], [%1], 16;" :: "r"(dst), "l"(src));
}

// packed-fp16 hardware exp2: 2 values per lane per issue
__device__ __forceinline__ uint32_t ex2h2(uint32_t x) {
    uint32_t r;
    asm("ex2.approx.f16x2 %0, %1;" : "=r"(r) : "r"(x));
    return r;
}

// k-dim pair permutation (within 16-element groups)
__device__ __forceinline__ int kperm(int c) {
    return (c >> 4) * 16 + (((c & 7) >> 1) << 2) + (((c >> 3) & 1) << 1);
}

#define CSC 0.1803368801111694f   // log2(e)/8

// ==================== merged convert: weights + activations + masks ==============
__global__ __launch_bounds__(256) void cvt_all(
    const float* __restrict__ Wcq, const float* __restrict__ Wck,
    const float* __restrict__ Wcv, const float* __restrict__ Weq,
    const float* __restrict__ Wek, const float* __restrict__ Wev,
    const float* __restrict__ xc, const float* __restrict__ xe,
    const int* __restrict__ mc, const int* __restrict__ me,
    __half* __restrict__ dWc, __half* __restrict__ dWe,
    __half* __restrict__ dxc, __half* __restrict__ dxe,
    __half* __restrict__ dmc, __half* __restrict__ dme)
{
    int bid = blockIdx.x;
    if (bid >= 8192) {   // mask conversion: 10240 ints total, 4 per thread
        int idx = (bid - 8192) * 256 + threadIdx.x;
        int base = idx * 4;
        const int* src;
        __half* dst;
        if (base < B * SC) { src = mc + base; dst = dmc + base; }
        else { base -= B * SC; src = me + base; dst = dme + base; }
        int4 v = *(const int4*)src;
        uint2 o;
        o.x = packh2(v.x ? 1.f : 0.f, v.y ? 1.f : 0.f);
        o.y = packh2(v.z ? 1.f : 0.f, v.w ? 1.f : 0.f);
        *(uint2*)dst = o;
        return;
    }

    const float* s;
    __half* d;
    int i;
    if (bid < 3072) {
        int z = bid >> 9;
        const float* Ws[6] = {Wcq, Wck, Wcv, Weq, Wek, Wev};
        s = Ws[z];
        d = (z < 3) ? (dWc + ((size_t)z << 20)) : (dWe + ((size_t)(z - 3) << 20));
        i = (bid & 511) * 256 + threadIdx.x;
    } else if (bid < 4096) {
        s = xc; d = dxc;
        i = (bid - 3072) * 256 + threadIdx.x;
    } else {
        s = xe; d = dxe;
        i = (bid - 4096) * 256 + threadIdx.x;
    }
    int op = 4 * i;
    int grp = op >> 3;
    int j0 = op & 7;
    const float2* sp = (const float2*)s + (size_t)grp * 8;
    uint4 o;
    {
        int p0 = 4 * ((j0 + 0) & 1) + ((j0 + 0) >> 1);
        int p1 = 4 * ((j0 + 1) & 1) + ((j0 + 1) >> 1);
        int p2 = 4 * ((j0 + 2) & 1) + ((j0 + 2) >> 1);
        int p3 = 4 * ((j0 + 3) & 1) + ((j0 + 3) >> 1);
        float2 v0 = sp[p0], v1 = sp[p1], v2 = sp[p2], v3 = sp[p3];
        o.x = packh2(v0.x, v0.y);
        o.y = packh2(v1.x, v1.y);
        o.z = packh2(v2.x, v2.y);
        o.w = packh2(v3.x, v3.y);
    }
    ((uint4*)d)[i] = o;
}

// ==================== GEMM: fp16 acc, single-sync 3-stage pipeline ===============
#define G_RS    96
#define G_A     0
#define G_B     (128 * G_RS)          // 12288
#define G_STAGE (256 * G_RS)          // 24576
#define G_SMEM  (3 * G_STAGE)         // 73728

__global__ __launch_bounds__(128, 3) void gemm_f16(
    const __half* __restrict__ xeh, const __half* __restrict__ Weh,
    const __half* __restrict__ xch, const __half* __restrict__ Wch,
    const float* __restrict__ beq, const float* __restrict__ bek,
    const float* __restrict__ bev,
    const float* __restrict__ bcq, const float* __restrict__ bck,
    const float* __restrict__ bcv,
    __half* __restrict__ Qe, __half* __restrict__ Ke, __half* __restrict__ Ve,
    __half* __restrict__ Qc, __half* __restrict__ Kc, __half* __restrict__ Vc)
{
    const int z = blockIdx.z;
    const __half *Ah, *Wz;
    __half* D;
    const float* bias;
    int zm;
    if (z < 3) {
        zm = z;
        Ah = xeh;
        Wz = Weh + ((size_t)z << 20);
        D = (z == 0) ? Qe : ((z == 1) ? Ke : Ve);
        bias = (z == 0) ? beq : ((z == 1) ? bek : bev);
    } else {
        if (blockIdx.y >= (B * SC) / 128) return;
        zm = z - 3;
        Ah = xch;
        Wz = Wch + ((size_t)zm << 20);
        D = (zm == 0) ? Qc : ((zm == 1) ? Kc : Vc);
        bias = (zm == 0) ? bcq : ((zm == 1) ? bck : bcv);
    }
    const float scale = (zm == 0) ? CSC : 1.f;
    const bool doperm = (zm != 2);

    extern __shared__ char smem[];
    const uint32_t sb = smem_u32(smem);
    const int tid = threadIdx.x;
    const int wid = tid >> 5;
    const int lane = tid & 31;
    const int g = lane >> 2;
    const int t = lane & 3;
    const int wm = wid >> 1;
    const int wn = wid & 1;
    const int bm = blockIdx.y * 128;
    const int bn = blockIdx.x * 128;

    const char* csrc[8];
    uint32_t cdst[8];
#pragma unroll
    for (int q = 0; q < 8; q++) {
        int f = q * 128 + tid;
        int tile = f >> 9;
        int idx = f & 511;
        int r = idx >> 2, c = idx & 3;
        cdst[q] = (uint32_t)(tile * G_B + r * G_RS + c * 16);
        if (tile == 0) csrc[q] = (const char*)(Ah + (size_t)(bm + r) * HS + c * 8);
        else           csrc[q] = (const char*)(Wz + (size_t)(bn + r) * HS + c * 8);
    }

    const int NC = HS / 32;

    // prologue: stages 0,1 only
#pragma unroll
    for (int st = 0; st < 2; st++) {
        uint32_t db = sb + st * G_STAGE;
#pragma unroll
        for (int q = 0; q < 8; q++)
            cp16(db + cdst[q], csrc[q] + st * 64);
        asm volatile("cp.async.commit_group;");
    }

    uint32_t acc[4][8][2];
#pragma unroll
    for (int i = 0; i < 4; i++)
#pragma unroll
        for (int j = 0; j < 8; j++) {
            acc[i][j][0] = 0u;
            acc[i][j][1] = 0u;
        }

    for (int c = 0; c < NC; c++) {
        asm volatile("cp.async.wait_group 1;");
        __syncthreads();

        // prefetch chunk c+2 into stage (c+2)%3 (freed at iter c-1, guarded by sync)
        if (c + 2 < NC) {
            uint32_t db = sb + ((c + 2) % 3) * G_STAGE;
            int koff = (c + 2) * 64;
#pragma unroll
            for (int q = 0; q < 8; q++)
                cp16(db + cdst[q], csrc[q] + koff);
        }
        asm volatile("cp.async.commit_group;");

        const char* buf = smem + (c % 3) * G_STAGE;
#pragma unroll
        for (int s = 0; s < 2; s++) {
            const int kb = s * 32 + t * 8;
            uint32_t ah[4][4];
#pragma unroll
            for (int i = 0; i < 4; i++) {
                const char* pa = buf + G_A + (wm * 64 + 16 * i + g) * G_RS + kb;
                uint2 alo = *(const uint2*)(pa);
                uint2 ahi = *(const uint2*)(pa + 8 * G_RS);
                ah[i][0] = alo.x;
                ah[i][1] = ahi.x;
                ah[i][2] = alo.y;
                ah[i][3] = ahi.y;
            }
#pragma unroll
            for (int j = 0; j < 8; j++) {
                uint2 bv = *(const uint2*)(buf + G_B + (wn * 64 + 8 * j + g) * G_RS + kb);
#pragma unroll
                for (int i = 0; i < 4; i++)
                    mma_f16acc(acc[i][j], ah[i], (const uint32_t*)&bv);
            }
        }
    }

    // epilogue: fp16 acc + bias (+scale), store fp16 at (optionally kperm'd) cols
#pragma unroll
    for (int i = 0; i < 4; i++) {
        int row0 = bm + wm * 64 + 16 * i + g;
#pragma unroll
        for (int j = 0; j < 8; j++) {
            int c = bn + wn * 64 + 8 * j + 2 * t;
            float2 bv2 = *(const float2*)(bias + c);
            float2 lo = __half22float2(*(__half2*)&acc[i][j][0]);
            float2 hi = __half22float2(*(__half2*)&acc[i][j][1]);
            uint32_t w0 = packh2((lo.x + bv2.x) * scale, (lo.y + bv2.y) * scale);
            uint32_t w1 = packh2((hi.x + bv2.x) * scale, (hi.y + bv2.y) * scale);
            int oc = doperm ? kperm(c) : c;
            *(uint32_t*)(D + (size_t)row0 * HS + oc) = w0;
            *(uint32_t*)(D + (size_t)(row0 + 8) * HS + oc) = w1;
        }
    }
}

// ==================== V prep: fp16 transpose, seq-dim kperm ====================
__global__ __launch_bounds__(256) void prep_v(
    const __half* __restrict__ Vc, __half* __restrict__ Vtc,
    const __half* __restrict__ Ve, __half* __restrict__ Vte)
{
    __shared__ __half vs[64][66];
    const int tid = threadIdx.x;
    const int b = blockIdx.z, h = blockIdx.y;
    const int bh = b * NH + h;

    const __half* V;
    __half* Vt;
    int Sk, s0;
    if (blockIdx.x < SC / 64) {
        V = Vc; Vt = Vtc; Sk = SC;
        s0 = blockIdx.x * 64;
    } else {
        V = Ve; Vt = Vte; Sk = SE;
        s0 = (blockIdx.x - SC / 64) * 64;
    }

#pragma unroll
    for (int i = 0; i < 4; i++) {
        int f = tid + 256 * i;
        int r = f >> 4, cu = f & 15;
        uint2 v = *(const uint2*)(V + (size_t)(b * Sk + s0 + r) * HS + h * DH + cu * 4);
        *(uint32_t*)&vs[r][cu * 4] = v.x;
        *(uint32_t*)&vs[r][cu * 4 + 2] = v.y;
    }
    __syncthreads();
#pragma unroll
    for (int i = 0; i < 8; i++) {
        int f = tid + 256 * i;
        int d = f >> 5, sp = f & 31;
        __half2 pr(vs[2 * sp][d], vs[2 * sp + 1][d]);
        size_t o = ((size_t)(bh * DH + d)) * Sk + s0 + kperm(2 * sp);
        *(uint32_t*)(Vt + o) = *(uint32_t*)&pr;
    }
}

// ==================== attention: single-sync 3-stage pipeline ====================
#define AK    0
#define AV    10240               // 72 rows x 160 (rows 64..71 = ones/zero pad)
#define AMS   21760               // 64 fp16 mask values (128B)
#define ABUF  22016
#define ASMEM (3 * ABUF)          // 66048
#define ARS   160

__global__ __launch_bounds__(128, 2) void attn_all(
    const __half* __restrict__ Q16c, const __half* __restrict__ K16e,
    const __half* __restrict__ Vte, const __half* __restrict__ me,
    float* __restrict__ Ac,
    const __half* __restrict__ Q16e, const __half* __restrict__ K16c,
    const __half* __restrict__ Vtc, const __half* __restrict__ mc,
    float* __restrict__ Ae)
{
    extern __shared__ char sm[];
    const uint32_t sb = smem_u32(sm);
    const int tid = threadIdx.x;
    const int wid = tid >> 5;
    const int lane = tid & 31;
    const int g = lane >> 2;
    const int t = lane & 3;
    const int b = blockIdx.z, h = blockIdx.y;
    const int bx = blockIdx.x;
    const int bh = b * NH + h;

    const __half* Q;
    const __half* K;
    const __half* Vt;
    const __half* mask;
    float* O;
    int Sq, Sk, q0;
    if (bx < SC / 128) {
        Q = Q16c; K = K16e; Vt = Vte; mask = me; O = Ac;
        Sq = SC; Sk = SE; q0 = bx * 128;
    } else {
        Q = Q16e; K = K16c; Vt = Vtc; mask = mc; O = Ae;
        Sq = SE; Sk = SC; q0 = (bx - SC / 128) * 128;
    }
    const int nt = Sk / 64;
    const size_t KADV = (size_t)64 * HS * 2;   // K bytes per 64-row tile

    const char* csrc[8];
    uint32_t cdst[8];
#pragma unroll
    for (int q = 0; q < 8; q++) {
        int f = q * 128 + tid;
        int tile = f >> 9;
        int idx = f & 511;
        int r = idx >> 3, c = idx & 7;
        if (tile == 0) {
            csrc[q] = (const char*)(K + ((size_t)(b * Sk) + r) * HS + h * DH + c * 8);
            cdst[q] = AK + (uint32_t)(r * ARS + c * 16);
        } else {
            csrc[q] = (const char*)(Vt + (size_t)(bh * DH + r) * (size_t)Sk + c * 8);
            cdst[q] = AV + (uint32_t)(r * ARS + c * 16);
        }
    }
    const char* msrc = (const char*)(mask + (size_t)b * Sk) + tid * 16;

    // prologue: tiles 0,1 into stages 0,1
#pragma unroll
    for (int st = 0; st < 2; st++) {
        if (st < 1 || nt > 1) {
            uint32_t db = sb + st * ABUF;
#pragma unroll
            for (int q = 0; q < 8; q++)
                cp16(db + cdst[q], csrc[q] + ((q < 4) ? st * KADV : st * 128));
            if (tid < 8) cp16(db + AMS + tid * 16, msrc + st * 128);
        }
        asm volatile("cp.async.commit_group;");
    }

    // init ones/zero pad rows 64..71 of all 3 V buffers (disjoint from cp.async)
    {
        int row = 64 + (tid >> 4);
        int off = (tid & 15) * 8;
        uint2 val = (row == 64) ? make_uint2(0x3C003C00u, 0x3C003C00u)
                                : make_uint2(0u, 0u);
        *(uint2*)(sm + AV + row * ARS + off) = val;
        *(uint2*)(sm + ABUF + AV + row * ARS + off) = val;
        *(uint2*)(sm + 2 * ABUF + AV + row * ARS + off) = val;
    }

    // Q fragments (2 m16 tiles per warp): fp16, CSC-prescaled, kperm'd cols
    uint32_t qh[2][4][4];
#pragma unroll
    for (int i = 0; i < 2; i++) {
        const __half* qp0 = Q + (size_t)(b * Sq + q0 + wid * 32 + 16 * i + g) * HS + h * DH;
        const __half* qp8 = qp0 + 8 * HS;
#pragma unroll
        for (int kk = 0; kk < 4; kk++) {
            uint2 u0 = *(const uint2*)(qp0 + 16 * kk + 4 * t);
            uint2 u8 = *(const uint2*)(qp8 + 16 * kk + 4 * t);
            qh[i][kk][0] = u0.x;
            qh[i][kk][1] = u8.x;
            qh[i][kk][2] = u0.y;
            qh[i][kk][3] = u8.y;
        }
    }

    // fp32 accumulators; j=8 is the ones column (l accumulator)
    float oacc[2][9][4];
#pragma unroll
    for (int i = 0; i < 2; i++)
#pragma unroll
        for (int j = 0; j < 9; j++)
#pragma unroll
            for (int k = 0; k < 4; k++) oacc[i][j][k] = 0.f;

    for (int it = 0; it < nt; it++) {
        asm volatile("cp.async.wait_group 1;");
        __syncthreads();

        // prefetch tile it+2 into stage (it+2)%3 (freed at iter it-1)
        if (it + 2 < nt) {
            size_t kaK = (size_t)(it + 2) * KADV;
            size_t kaV = (size_t)(it + 2) * 128;
            uint32_t db = sb + ((it + 2) % 3) * ABUF;
#pragma unroll
            for (int q = 0; q < 8; q++)
                cp16(db + cdst[q], csrc[q] + ((q < 4) ? kaK : kaV));
            if (tid < 8) cp16(db + AMS + tid * 16, msrc + (size_t)(it + 2) * 128);
        }
        asm volatile("cp.async.commit_group;");

        char* buf = sm + (it % 3) * ABUF;

        // ---- S = Q @ K^T (fp16 acc: values already packed as half2) ----
        uint32_t sacc[2][8][2];
#pragma unroll
        for (int i = 0; i < 2; i++)
#pragma unroll
            for (int j = 0; j < 8; j++) {
                sacc[i][j][0] = 0u;
                sacc[i][j][1] = 0u;
            }

#pragma unroll
        for (int kk = 0; kk < 4; kk++) {
#pragma unroll
            for (int j = 0; j < 8; j++) {
                uint2 kv = *(const uint2*)(buf + AK + (8 * j + g) * ARS + kk * 32 + t * 8);
                mma_f16acc(sacc[0][j], qh[0][kk], (const uint32_t*)&kv);
                mma_f16acc(sacc[1][j], qh[1][kk], (const uint32_t*)&kv);
            }
        }

        // ---- P = ex2(S) * mask : packed fp16 throughout ----
        uint32_t ph[2][4][4];
#pragma unroll
        for (int s = 0; s < 4; s++) {
            uint32_t m0 = *(const uint32_t*)(buf + AMS + s * 32 + t * 4);
            uint32_t m1 = *(const uint32_t*)(buf + AMS + s * 32 + t * 4 + 16);
#pragma unroll
            for (int i = 0; i < 2; i++) {
                ph[i][s][0] = hmul2u(ex2h2(sacc[i][2 * s][0]), m0);
                ph[i][s][1] = hmul2u(ex2h2(sacc[i][2 * s][1]), m0);
                ph[i][s][2] = hmul2u(ex2h2(sacc[i][2 * s + 1][0]), m1);
                ph[i][s][3] = hmul2u(ex2h2(sacc[i][2 * s + 1][1]), m1);
            }
        }

        // ---- O += P @ V  (9th n-tile = ones column -> l) ----
#pragma unroll
        for (int s = 0; s < 4; s++) {
#pragma unroll
            for (int j = 0; j < 9; j++) {
                uint2 vv = *(const uint2*)(buf + AV + (8 * j + g) * ARS + s * 32 + t * 8);
                mma_f16(oacc[0][j], ph[0][s], (const uint32_t*)&vv);
                mma_f16(oacc[1][j], ph[1][s], (const uint32_t*)&vv);
            }
        }
    }

    // l lives in oacc[i][8][0]/[2] of the t=0 lane of each quad; broadcast + write
#pragma unroll
    for (int i = 0; i < 2; i++) {
        float l0 = __shfl_sync(0xffffffffu, oacc[i][8][0], lane & ~3);
        float l1 = __shfl_sync(0xffffffffu, oacc[i][8][2], lane & ~3);
        float inv0 = 1.f / l0;
        float inv1 = 1.f / l1;
        int row0 = q0 + wid * 32 + 16 * i + g;
#pragma unroll
        for (int j = 0; j < 8; j++) {
            int col = h * DH + 8 * j + 2 * t;
            *(float2*)(O + (size_t)(b * Sq + row0) * HS + col) =
                make_float2(oacc[i][j][0] * inv0, oacc[i][j][1] * inv0);
            *(float2*)(O + (size_t)(b * Sq + row0 + 8) * HS + col) =
                make_float2(oacc[i][j][2] * inv1, oacc[i][j][3] * inv1);
        }
    }
}

// ==================== fused residual add + LayerNorm (merged) ====================
__global__ __launch_bounds__(256) void add_ln_all(
    const float* __restrict__ xc, const float* __restrict__ Ac,
    const float* __restrict__ xe, const float* __restrict__ Ae,
    const float* __restrict__ g, const float* __restrict__ bb,
    float* __restrict__ out)
{
    int row = blockIdx.x;
    const float *x, *att;
    if (row < B * SC) { x = xc + (size_t)row * HS; att = Ac + (size_t)row * HS; }
    else {
        int r = row - B * SC;
        x = xe + (size_t)r * HS; att = Ae + (size_t)r * HS;
    }
    int tid = threadIdx.x;
    float4 xv = ((const float4*)x)[tid];
    float4 av = ((const float4*)att)[tid];
    float v0 = xv.x + av.x, v1 = xv.y + av.y, v2 = xv.z + av.z, v3 = xv.w + av.w;

    float s = v0 + v1 + v2 + v3;
    float sq = v0 * v0 + v1 * v1 + v2 * v2 + v3 * v3;
#pragma unroll
    for (int off = 16; off > 0; off >>= 1) {
        s  += __shfl_xor_sync(0xffffffffu, s, off);
        sq += __shfl_xor_sync(0xffffffffu, sq, off);
    }
    __shared__ float ss[8], ssq[8];
    int wid = tid >> 5, lane = tid & 31;
    if (lane == 0) { ss[wid] = s; ssq[wid] = sq; }
    __syncthreads();
    s = 0.f; sq = 0.f;
#pragma unroll
    for (int w = 0; w < 8; w++) { s += ss[w]; sq += ssq[w]; }

    float mu = s * (1.f / HS);
    float var = sq * (1.f / HS) - mu * mu;
    float r = rsqrtf(var + 1e-5f);

    float4 gv = ((const float4*)g)[tid];
    float4 bv = ((const float4*)bb)[tid];
    float4 ov = make_float4((v0 - mu) * r * gv.x + bv.x,
                            (v1 - mu) * r * gv.y + bv.y,
                            (v2 - mu) * r * gv.z + bv.z,
                            (v3 - mu) * r * gv.w + bv.w);
    ((float4*)(out + (size_t)row * HS))[tid] = ov;
}

// ==================== launcher ====================
extern "C" void kernel_launch(void* const* d_in, const int* in_sizes, int n_in,
                              void* d_out, int out_size)
{
    (void)in_sizes; (void)n_in; (void)out_size;
    const float* x_c   = (const float*)d_in[0];
    const float* x_e   = (const float*)d_in[1];
    const int*   msk_c = (const int*)d_in[2];
    const int*   msk_e = (const int*)d_in[3];
    const float* W_cq = (const float*)d_in[4];  const float* b_cq = (const float*)d_in[5];
    const float* W_ek = (const float*)d_in[6];  const float* b_ek = (const float*)d_in[7];
    const float* W_ev = (const float*)d_in[8];  const float* b_ev = (const float*)d_in[9];
    const float* W_eq = (const float*)d_in[10]; const float* b_eq = (const float*)d_in[11];
    const float* W_ck = (const float*)d_in[12]; const float* b_ck = (const float*)d_in[13];
    const float* W_cv = (const float*)d_in[14]; const float* b_cv = (const float*)d_in[15];
    const float* ln_g = (const float*)d_in[16]; const float* ln_b = (const float*)d_in[17];
    float* out = (float*)d_out;

    float *Ac, *Ae;
    cudaGetSymbolAddress((void**)&Ac, g_Ac);
    cudaGetSymbolAddress((void**)&Ae, g_Ae);
    __half *xch, *xeh, *Wch, *Weh, *mhc, *mhe;
    cudaGetSymbolAddress((void**)&xch, g_xch);
    cudaGetSymbolAddress((void**)&xeh, g_xeh);
    cudaGetSymbolAddress((void**)&Wch, g_Wch);
    cudaGetSymbolAddress((void**)&Weh, g_Weh);
    cudaGetSymbolAddress((void**)&mhc, g_mhc);
    cudaGetSymbolAddress((void**)&mhe, g_mhe);
    __half *Q16c, *K16c, *V16c, *Q16e, *K16e, *V16e, *Vtc16, *Vte16;
    cudaGetSymbolAddress((void**)&Q16c, g_Q16c);
    cudaGetSymbolAddress((void**)&K16c, g_K16c);
    cudaGetSymbolAddress((void**)&V16c, g_V16c);
    cudaGetSymbolAddress((void**)&Q16e, g_Q16e);
    cudaGetSymbolAddress((void**)&K16e, g_K16e);
    cudaGetSymbolAddress((void**)&V16e, g_V16e);
    cudaGetSymbolAddress((void**)&Vtc16, g_Vtc16);
    cudaGetSymbolAddress((void**)&Vte16, g_Vte16);

    cudaFuncSetAttribute(gemm_f16, cudaFuncAttributeMaxDynamicSharedMemorySize, G_SMEM);
    cudaFuncSetAttribute(attn_all, cudaFuncAttributeMaxDynamicSharedMemorySize, ASMEM);

    const int Mc = B * SC;   // 2048
    const int Me = B * SE;   // 8192

    cvt_all<<<8192 + 10, 256>>>(W_cq, W_ck, W_cv, W_eq, W_ek, W_ev, x_c, x_e,
                                msk_c, msk_e, Wch, Weh, xch, xeh, mhc, mhe);

    gemm_f16<<<dim3(8, Me / 128, 6), 128, G_SMEM>>>(
        xeh, Weh, xch, Wch,
        b_eq, b_ek, b_ev, b_cq, b_ck, b_cv,
        Q16e, K16e, V16e, Q16c, K16c, V16c);

    prep_v<<<dim3(SC / 64 + SE / 64, NH, B), 256>>>(V16c, Vtc16, V16e, Vte16);

    attn_all<<<dim3(SC / 128 + SE / 128, NH, B), 128, ASMEM>>>(
        Q16c, K16e, Vte16, mhe, Ac,
        Q16e, K16c, Vtc16, mhc, Ae);

    add_ln_all<<<Mc + Me, 256>>>(x_c, Ac, x_e, Ae, ln_g, ln_b, out);
}